// round 1
// baseline (speedup 1.0000x reference)
#include <cuda_runtime.h>
#include <math.h>

#define NN 2048
#define BB 64
#define DD 64
#define ISZ 130
#define NM 7
#define XW (ISZ*BB)          // 8320
#define NDD (NN*DD)          // 131072
#define OUT1 (BB*NDD)        // 8388608 (first output tensor)
#define HXPART ((size_t)BB*4*NDD)
#define FULL_OUT ((size_t)OUT1 + HXPART)   // 41943040

// ---------------- scratch (static __device__, no allocation) ----------------
static __device__ float g_S1[(size_t)NN*NN];
static __device__ float g_S2[(size_t)NN*NN];
static __device__ float g_Ad[(size_t)NN*NN];
static __device__ float g_dinv1[NN];
static __device__ float g_dinv2[NN];
static __device__ float g_cspart[8*NN];
static __device__ float g_X0[(size_t)NN*XW];
static __device__ float g_X1[(size_t)NN*XW];
static __device__ float g_X2[(size_t)NN*XW];
static __device__ float g_gc[(size_t)BB*NN*DD];
static __device__ float g_logits[BB*4];
static __device__ float g_wt[BB*4];

__device__ __forceinline__ float* buf(int s) {
    switch (s) {
        case 0: return g_X0;
        case 1: return g_X1;
        case 2: return g_X2;
        case 3: return g_S1;
        case 4: return g_S2;
        default: return g_Ad;
    }
}

// ---------------- support construction ----------------
__global__ void rowsum_dinv_kernel(const float* __restrict__ g) {
    int row = blockIdx.x;
    int tid = threadIdx.x;
    float s = 0.f;
    for (int j = tid; j < NN; j += 256) s += g[(size_t)row*NN + j];
    for (int o = 16; o; o >>= 1) s += __shfl_down_sync(0xffffffffu, s, o);
    __shared__ float red[8];
    if ((tid & 31) == 0) red[tid >> 5] = s;
    __syncthreads();
    if (tid == 0) {
        float t = 0.f;
        #pragma unroll
        for (int w = 0; w < 8; w++) t += red[w];
        g_dinv1[row] = 1.f / (1.f + t);
    }
}

__global__ void colsum_part_kernel(const float* __restrict__ g) {
    int col = blockIdx.x * 256 + threadIdx.x;
    int r0 = blockIdx.y * 256;
    float s = 0.f;
    #pragma unroll 8
    for (int r = 0; r < 256; r++) s += g[(size_t)(r0 + r)*NN + col];
    g_cspart[blockIdx.y*NN + col] = s;
}

__global__ void colsum_fin_kernel() {
    int col = blockIdx.x * 256 + threadIdx.x;
    float s = 0.f;
    #pragma unroll
    for (int y = 0; y < 8; y++) s += g_cspart[y*NN + col];
    g_dinv2[col] = 1.f / (1.f + s);
}

// S1[i,j] = (graph[j,i] + d_ij) * dinv1[j]   (transpose with smem tile)
__global__ void build_S1_kernel(const float* __restrict__ g) {
    __shared__ float t[32][33];
    int bi = blockIdx.x * 32;   // i tile
    int bj = blockIdx.y * 32;   // j tile
    for (int r = threadIdx.y; r < 32; r += 8)
        t[r][threadIdx.x] = g[(size_t)(bj + r)*NN + bi + threadIdx.x];
    __syncthreads();
    for (int r = threadIdx.y; r < 32; r += 8) {
        int i = bi + r, j = bj + threadIdx.x;
        float dv = g_dinv1[j];
        float v = t[threadIdx.x][r] * dv;
        if (i == j) v += dv;
        g_S1[(size_t)i*NN + j] = v;
    }
}

// S2[i,j] = (graph[i,j] + d_ij) * dinv2[j]
__global__ void build_S2_kernel(const float* __restrict__ g) {
    int idx = blockIdx.x * 256 + threadIdx.x;
    int i = idx >> 11, j = idx & 2047;
    float v = g[idx] + (i == j ? 1.f : 0.f);
    g_S2[idx] = v * g_dinv2[j];
}

// adp = softmax(relu(nv1 @ nv2), axis=1) ; one block per row
__global__ void adp_kernel(const float* __restrict__ nv1, const float* __restrict__ nv2) {
    int i = blockIdx.x;
    int tid = threadIdx.x;
    __shared__ float v1[10];
    __shared__ float red[40];
    if (tid < 10) v1[tid] = nv1[i*10 + tid];
    __syncthreads();
    float p[8];
    float mx = 0.f;
    #pragma unroll
    for (int c = 0; c < 8; c++) {
        int j = tid + c*256;
        float s = 0.f;
        #pragma unroll
        for (int t = 0; t < 10; t++) s += v1[t] * nv2[t*NN + j];
        s = s > 0.f ? s : 0.f;
        p[c] = s;
        mx = fmaxf(mx, s);
    }
    for (int o = 16; o; o >>= 1) mx = fmaxf(mx, __shfl_xor_sync(0xffffffffu, mx, o));
    if ((tid & 31) == 0) red[tid >> 5] = mx;
    __syncthreads();
    if (tid == 0) {
        float m = red[0];
        #pragma unroll
        for (int w = 1; w < 8; w++) m = fmaxf(m, red[w]);
        red[32] = m;
    }
    __syncthreads();
    mx = red[32];
    float sum = 0.f;
    #pragma unroll
    for (int c = 0; c < 8; c++) { float e = expf(p[c] - mx); p[c] = e; sum += e; }
    for (int o = 16; o; o >>= 1) sum += __shfl_xor_sync(0xffffffffu, sum, o);
    if ((tid & 31) == 0) red[16 + (tid >> 5)] = sum;
    __syncthreads();
    if (tid == 0) {
        float t = 0.f;
        #pragma unroll
        for (int w = 0; w < 8; w++) t += red[16 + w];
        red[33] = 1.f / t;
    }
    __syncthreads();
    float inv = red[33];
    #pragma unroll
    for (int c = 0; c < 8; c++) g_Ad[(size_t)i*NN + tid + c*256] = p[c] * inv;
}

// ---------------- x0 build: x0[n, i*64+b] ----------------
__global__ void build_x0_kernel(const float* __restrict__ inputs, const float* __restrict__ hx) {
    size_t total = (size_t)NN * XW;
    for (size_t idx = (size_t)blockIdx.x*256 + threadIdx.x; idx < total; idx += (size_t)gridDim.x*256) {
        int n = (int)(idx / XW);
        int c = (int)(idx - (size_t)n*XW);
        int i = c >> 6, b = c & 63;
        float v;
        if (i < 2) {
            v = inputs[(size_t)b*(NN*2) + n*2 + i];
        } else {
            int q = i - 2;
            int kk = (q < 64) ? 3 : 2;
            int d = q & 63;
            v = hx[(size_t)((b << 2) + kk)*NDD + (size_t)n*64 + d];
        }
        g_X0[idx] = v;
    }
}

__global__ void gc_init_kernel(const float* __restrict__ gb) {
    int idx = blockIdx.x * 256 + threadIdx.x;
    g_gc[idx] = gb[idx & 63];
}

// gc[b*NN+n, d] += sum_i X[n, i*64+b] * gw[(i*7+m)*64 + d]
__global__ void __launch_bounds__(256) proj_kernel(int selX, int m, const float* __restrict__ gw) {
    const float* X = buf(selX);
    int n = blockIdx.x;
    int tid = threadIdx.x;
    __shared__ float sx[32*64];
    int b = tid >> 2;
    int d0 = (tid & 3) * 16;
    float acc[16];
    #pragma unroll
    for (int dd = 0; dd < 16; dd++) acc[dd] = 0.f;
    for (int ib = 0; ib < ISZ; ib += 32) {
        int cnt = min(32, ISZ - ib);
        __syncthreads();
        for (int t = tid; t < cnt*64; t += 256) sx[t] = X[(size_t)n*XW + (size_t)ib*64 + t];
        __syncthreads();
        for (int ii = 0; ii < cnt; ii++) {
            float a = sx[ii*64 + b];
            const float* wp = gw + ((size_t)(ib + ii)*7 + m)*64 + d0;
            #pragma unroll
            for (int dd = 0; dd < 16; dd++) acc[dd] += a * __ldg(&wp[dd]);
        }
    }
    float* out = g_gc + ((size_t)b*NN + n)*64 + d0;
    #pragma unroll
    for (int dd = 0; dd < 16; dd++) out[dd] += acc[dd];
}

// ---------------- SGEMM: C = alpha * A(2048x2048) @ B(2048x8320) + beta * Cin ----------------
__global__ void __launch_bounds__(256) sgemm_kernel(int selA, int selB, int selCin, int selC,
                                                    float alpha, float beta) {
    const float* __restrict__ A = buf(selA);
    const float* __restrict__ B = buf(selB);
    const float* __restrict__ Ci = buf(selCin);
    float* __restrict__ C = buf(selC);
    const int K = NN, N = XW;

    __shared__ float As[2][16][128];
    __shared__ float Bs[2][16][128];

    int tid = threadIdx.x;
    int nBase = blockIdx.x * 128;
    int mBase = blockIdx.y * 128;
    int tx = tid & 15, ty = tid >> 4;

    int ar = tid >> 2;           // 0..63
    int ac = (tid & 3) << 2;     // 0,4,8,12
    int br = tid >> 5;           // 0..7
    int bc = (tid & 31) << 2;    // 0..124

    const float* Aptr = A + (size_t)mBase * K;
    const float* Bptr = B + nBase;

    float4 ra0, ra1, rb0, rb1;
    ra0 = *(const float4*)&Aptr[(size_t)ar*K + ac];
    ra1 = *(const float4*)&Aptr[(size_t)(ar + 64)*K + ac];
    rb0 = *(const float4*)&Bptr[(size_t)br*N + bc];
    rb1 = *(const float4*)&Bptr[(size_t)(br + 8)*N + bc];

    As[0][ac + 0][ar] = ra0.x; As[0][ac + 1][ar] = ra0.y;
    As[0][ac + 2][ar] = ra0.z; As[0][ac + 3][ar] = ra0.w;
    As[0][ac + 0][ar + 64] = ra1.x; As[0][ac + 1][ar + 64] = ra1.y;
    As[0][ac + 2][ar + 64] = ra1.z; As[0][ac + 3][ar + 64] = ra1.w;
    *(float4*)&Bs[0][br][bc] = rb0;
    *(float4*)&Bs[0][br + 8][bc] = rb1;
    __syncthreads();

    float acc[8][8];
    #pragma unroll
    for (int i = 0; i < 8; i++)
        #pragma unroll
        for (int j = 0; j < 8; j++) acc[i][j] = 0.f;

    const int KT = K / 16;
    int s = 0;
    for (int kt = 0; kt < KT; kt++) {
        bool more = (kt + 1 < KT);
        if (more) {
            int k0n = (kt + 1) * 16;
            ra0 = *(const float4*)&Aptr[(size_t)ar*K + k0n + ac];
            ra1 = *(const float4*)&Aptr[(size_t)(ar + 64)*K + k0n + ac];
            rb0 = *(const float4*)&Bptr[(size_t)(k0n + br)*N + bc];
            rb1 = *(const float4*)&Bptr[(size_t)(k0n + br + 8)*N + bc];
        }
        #pragma unroll
        for (int k = 0; k < 16; k++) {
            float av[8], bv[8];
            *(float4*)&av[0] = *(const float4*)&As[s][k][ty*8];
            *(float4*)&av[4] = *(const float4*)&As[s][k][ty*8 + 4];
            *(float4*)&bv[0] = *(const float4*)&Bs[s][k][tx*8];
            *(float4*)&bv[4] = *(const float4*)&Bs[s][k][tx*8 + 4];
            #pragma unroll
            for (int i = 0; i < 8; i++)
                #pragma unroll
                for (int j = 0; j < 8; j++) acc[i][j] += av[i] * bv[j];
        }
        if (more) {
            int ns = s ^ 1;
            As[ns][ac + 0][ar] = ra0.x; As[ns][ac + 1][ar] = ra0.y;
            As[ns][ac + 2][ar] = ra0.z; As[ns][ac + 3][ar] = ra0.w;
            As[ns][ac + 0][ar + 64] = ra1.x; As[ns][ac + 1][ar + 64] = ra1.y;
            As[ns][ac + 2][ar + 64] = ra1.z; As[ns][ac + 3][ar + 64] = ra1.w;
            *(float4*)&Bs[ns][br][bc] = rb0;
            *(float4*)&Bs[ns][br + 8][bc] = rb1;
            __syncthreads();
            s = ns;
        }
    }

    #pragma unroll
    for (int i = 0; i < 8; i++) {
        size_t row = (size_t)(mBase + ty*8 + i);
        float* cp = C + row*N + nBase + tx*8;
        if (beta != 0.f) {
            const float* cip = Ci + row*N + nBase + tx*8;
            #pragma unroll
            for (int j = 0; j < 8; j++) cp[j] = alpha * acc[i][j] + beta * cip[j];
        } else {
            #pragma unroll
            for (int j = 0; j < 8; j++) cp[j] = alpha * acc[i][j];
        }
    }
}

// ---------------- attention ----------------
__global__ void logits_kernel(const float* __restrict__ hx, const float* __restrict__ R,
                              const float* __restrict__ aw, const float* __restrict__ ab) {
    int bk = blockIdx.x;       // b*4+k
    int k = bk & 3;
    int tid = threadIdx.x;
    const float* hp = hx + (size_t)bk * NDD;
    const float* rp = R + (size_t)k * NDD;
    float s = 0.f;
    for (int t = tid; t < NDD; t += 256) s += (hp[t] + rp[t]) * aw[t];
    for (int o = 16; o; o >>= 1) s += __shfl_down_sync(0xffffffffu, s, o);
    __shared__ float red[8];
    if ((tid & 31) == 0) red[tid >> 5] = s;
    __syncthreads();
    if (tid == 0) {
        float t = 0.f;
        #pragma unroll
        for (int w = 0; w < 8; w++) t += red[w];
        g_logits[bk] = t + ab[0];
    }
}

__global__ void weight_kernel() {
    int b = threadIdx.x;
    if (b < BB) {
        float l0 = g_logits[b*4+0], l1 = g_logits[b*4+1], l2 = g_logits[b*4+2], l3 = g_logits[b*4+3];
        float m = fmaxf(fmaxf(l0, l1), fmaxf(l2, l3));
        float e0 = expf(l0 - m), e1 = expf(l1 - m), e2 = expf(l2 - m), e3 = expf(l3 - m);
        float inv = 1.f / (e0 + e1 + e2 + e3);
        g_wt[b*4+0] = e0 * inv; g_wt[b*4+1] = e1 * inv;
        g_wt[b*4+2] = e2 * inv; g_wt[b*4+3] = e3 * inv;
    }
}

// ---------------- output: out = leaky(gc) @ W + b + att ----------------
__global__ void __launch_bounds__(256) final_kernel(const float* __restrict__ W,
                                                    const float* __restrict__ bbias,
                                                    const float* __restrict__ hx,
                                                    const float* __restrict__ R,
                                                    float* __restrict__ out, int write_hx) {
    __shared__ float sW[64*64];
    __shared__ float sg[4*64];
    int tid = threadIdx.x;
    int r0 = blockIdx.x * 4;
    for (int t = tid; t < 4096; t += 256) sW[t] = W[t];
    {
        float v = g_gc[(size_t)r0*64 + tid];
        sg[tid] = v > 0.f ? v : 0.01f * v;
    }
    __syncthreads();
    int rl = tid >> 6;
    int d = tid & 63;
    int r = r0 + rl;
    int b = r >> 11;
    int n = r & 2047;
    float acc = 0.f;
    #pragma unroll
    for (int e = 0; e < 64; e++) acc += sg[rl*64 + e] * sW[e*64 + d];
    float att = 0.f;
    #pragma unroll
    for (int k = 0; k < 4; k++) {
        float xv = hx[(size_t)((b << 2) + k)*NDD + (size_t)n*64 + d] + R[(size_t)k*NDD + (size_t)n*64 + d];
        att += xv * g_wt[b*4 + k];
    }
    float o = acc + bbias[(size_t)n*64 + d] + att;
    out[(size_t)b*NDD + (size_t)n*64 + d] = o;
    if (write_hx)
        out[(size_t)OUT1 + (size_t)((b << 2) + 3)*NDD + (size_t)n*64 + d] = o;
}

__global__ void hxcopy_kernel(const float* __restrict__ hx, float* __restrict__ out) {
    size_t idx = (size_t)blockIdx.x * 256 + threadIdx.x;
    // total = BB*3*NDD
    int b = (int)(idx / (3*(size_t)NDD));
    size_t rem = idx - (size_t)b * (3*(size_t)NDD);
    int kk = (int)(rem / NDD);
    size_t j = rem - (size_t)kk * NDD;
    out[(size_t)OUT1 + (size_t)(b*4 + kk)*NDD + j] = hx[(size_t)(b*4 + kk + 1)*NDD + j];
}

// ---------------- launch ----------------
extern "C" void kernel_launch(void* const* d_in, const int* in_sizes, int n_in,
                              void* d_out, int out_size) {
    const float* inputs = (const float*)d_in[0];
    const float* hx     = (const float*)d_in[1];
    const float* graph  = (const float*)d_in[2];
    const float* nv1    = (const float*)d_in[3];
    const float* nv2    = (const float*)d_in[4];
    const float* W      = (const float*)d_in[5];
    const float* bbias  = (const float*)d_in[6];
    const float* R      = (const float*)d_in[7];
    const float* gw     = (const float*)d_in[8];
    const float* gb     = (const float*)d_in[9];
    const float* aw     = (const float*)d_in[10];
    const float* ab     = (const float*)d_in[11];
    float* out = (float*)d_out;

    int write_hx = ((size_t)out_size >= FULL_OUT) ? 1 : 0;

    // supports + adaptive adjacency
    rowsum_dinv_kernel<<<NN, 256>>>(graph);
    colsum_part_kernel<<<dim3(NN/256, 8), 256>>>(graph);
    colsum_fin_kernel<<<NN/256, 256>>>();
    build_S1_kernel<<<dim3(64, 64), dim3(32, 8)>>>(graph);
    build_S2_kernel<<<(NN*NN)/256, 256>>>(graph);
    adp_kernel<<<NN, 256>>>(nv1, nv2);

    // x0 + gc init
    build_x0_kernel<<<66560, 256>>>(inputs, hx);
    gc_init_kernel<<<OUT1/256, 256>>>(gb);

    dim3 ggrid(XW/128, NN/128);   // 65 x 16

    // m0 = x0
    proj_kernel<<<NN, 256>>>(0, 0, gw);
    // m1 = S1 @ x0 -> X1
    sgemm_kernel<<<ggrid, 256>>>(3, 0, 0, 1, 1.f, 0.f);
    proj_kernel<<<NN, 256>>>(1, 1, gw);
    // m2 = 2*S1 @ m1 - x0 -> X2
    sgemm_kernel<<<ggrid, 256>>>(3, 1, 0, 2, 2.f, -1.f);
    proj_kernel<<<NN, 256>>>(2, 2, gw);
    // m3 = S2 @ m1 -> X0
    sgemm_kernel<<<ggrid, 256>>>(4, 1, 0, 0, 1.f, 0.f);
    proj_kernel<<<NN, 256>>>(0, 3, gw);
    // m4 = 2*S2 @ m3 - m1 -> X2
    sgemm_kernel<<<ggrid, 256>>>(4, 0, 1, 2, 2.f, -1.f);
    proj_kernel<<<NN, 256>>>(2, 4, gw);
    // m5 = A @ m3 -> X1
    sgemm_kernel<<<ggrid, 256>>>(5, 0, 0, 1, 1.f, 0.f);
    proj_kernel<<<NN, 256>>>(1, 5, gw);
    // m6 = A @ m5 - m3 -> X2
    sgemm_kernel<<<ggrid, 256>>>(5, 1, 0, 2, 1.f, -1.f);
    proj_kernel<<<NN, 256>>>(2, 6, gw);

    // attention
    logits_kernel<<<BB*4, 256>>>(hx, R, aw, ab);
    weight_kernel<<<1, 64>>>();

    // output + new hidden state
    final_kernel<<<(BB*NN)/4, 256>>>(W, bbias, hx, R, out, write_hx);
    if (write_hx)
        hxcopy_kernel<<<(unsigned)((size_t)BB*3*NDD/256), 256>>>(hx, out);
}

// round 3
// speedup vs baseline: 1.6510x; 1.6510x over previous
#include <cuda_runtime.h>
#include <cuda_bf16.h>
#include <math.h>
#include <stdint.h>

#define NN 2048
#define BB 64
#define DD 64
#define ISZ 130
#define XW (ISZ*BB)          // 8320
#define NDD (NN*DD)          // 131072
#define OUT1 (BB*NDD)        // 8388608
#define HXPART ((size_t)BB*4*NDD)
#define FULL_OUT ((size_t)OUT1 + HXPART)

// ---------------- scratch ----------------
static __device__ float g_S1[(size_t)NN*NN];
static __device__ float g_S2[(size_t)NN*NN];
static __device__ float g_Ad[(size_t)NN*NN];
static __device__ __nv_bfloat16 g_S1h[(size_t)NN*NN];
static __device__ __nv_bfloat16 g_S1l[(size_t)NN*NN];
static __device__ __nv_bfloat16 g_S2h[(size_t)NN*NN];
static __device__ __nv_bfloat16 g_S2l[(size_t)NN*NN];
static __device__ __nv_bfloat16 g_Adh[(size_t)NN*NN];
static __device__ __nv_bfloat16 g_Adl[(size_t)NN*NN];
static __device__ float g_dinv1[NN];
static __device__ float g_dinv2[NN];
static __device__ float g_cspart[8*NN];
static __device__ float g_X0[(size_t)NN*XW];
static __device__ float g_X1[(size_t)NN*XW];
static __device__ float g_X2[(size_t)NN*XW];
static __device__ __nv_bfloat16 g_XTh[(size_t)XW*NN];
static __device__ __nv_bfloat16 g_XTl[(size_t)XW*NN];
static __device__ float g_gc[(size_t)BB*NN*DD];
static __device__ float g_logits[BB*4];
static __device__ float g_wt[BB*4];

__device__ __forceinline__ float* bufF(int s) {
    switch (s) { case 0: return g_X0; case 1: return g_X1; default: return g_X2; }
}

// ---------------- PTX helpers ----------------
__device__ __forceinline__ uint32_t smem_u32(const void* p) {
    uint32_t a;
    asm("{ .reg .u64 t; cvta.to.shared.u64 t, %1; cvt.u32.u64 %0, t; }" : "=r"(a) : "l"(p));
    return a;
}
__device__ __forceinline__ void cp16(uint32_t dst, const void* src) {
    asm volatile("cp.async.cg.shared.global [%0], [%1], 16;" :: "r"(dst), "l"(src) : "memory");
}
__device__ __forceinline__ void cp_commit() { asm volatile("cp.async.commit_group;" ::: "memory"); }
__device__ __forceinline__ void cp_wait1() { asm volatile("cp.async.wait_group 1;" ::: "memory"); }
__device__ __forceinline__ void cp_wait0() { asm volatile("cp.async.wait_group 0;" ::: "memory"); }

__device__ __forceinline__ void ldm_x4(uint32_t* r, uint32_t addr) {
    asm volatile("ldmatrix.sync.aligned.m8n8.x4.shared.b16 {%0,%1,%2,%3}, [%4];"
                 : "=r"(r[0]), "=r"(r[1]), "=r"(r[2]), "=r"(r[3]) : "r"(addr));
}
__device__ __forceinline__ void mma16816(float* c, const uint32_t* a, uint32_t b0, uint32_t b1) {
    asm volatile(
        "mma.sync.aligned.m16n8k16.row.col.f32.bf16.bf16.f32 "
        "{%0,%1,%2,%3}, {%4,%5,%6,%7}, {%8,%9}, {%0,%1,%2,%3};"
        : "+f"(c[0]), "+f"(c[1]), "+f"(c[2]), "+f"(c[3])
        : "r"(a[0]), "r"(a[1]), "r"(a[2]), "r"(a[3]), "r"(b0), "r"(b1));
}

// ---------------- support construction ----------------
__global__ void rowsum_dinv_kernel(const float* __restrict__ g) {
    int row = blockIdx.x;
    int tid = threadIdx.x;
    float s = 0.f;
    for (int j = tid; j < NN; j += 256) s += g[(size_t)row*NN + j];
    for (int o = 16; o; o >>= 1) s += __shfl_down_sync(0xffffffffu, s, o);
    __shared__ float red[8];
    if ((tid & 31) == 0) red[tid >> 5] = s;
    __syncthreads();
    if (tid == 0) {
        float t = 0.f;
        #pragma unroll
        for (int w = 0; w < 8; w++) t += red[w];
        g_dinv1[row] = 1.f / (1.f + t);
    }
}

__global__ void colsum_part_kernel(const float* __restrict__ g) {
    int col = blockIdx.x * 256 + threadIdx.x;
    int r0 = blockIdx.y * 256;
    float s = 0.f;
    #pragma unroll 8
    for (int r = 0; r < 256; r++) s += g[(size_t)(r0 + r)*NN + col];
    g_cspart[blockIdx.y*NN + col] = s;
}

__global__ void colsum_fin_kernel() {
    int col = blockIdx.x * 256 + threadIdx.x;
    float s = 0.f;
    #pragma unroll
    for (int y = 0; y < 8; y++) s += g_cspart[y*NN + col];
    g_dinv2[col] = 1.f / (1.f + s);
}

__global__ void build_S1_kernel(const float* __restrict__ g) {
    __shared__ float t[32][33];
    int bi = blockIdx.x * 32;
    int bj = blockIdx.y * 32;
    for (int r = threadIdx.y; r < 32; r += 8)
        t[r][threadIdx.x] = g[(size_t)(bj + r)*NN + bi + threadIdx.x];
    __syncthreads();
    for (int r = threadIdx.y; r < 32; r += 8) {
        int i = bi + r, j = bj + threadIdx.x;
        float dv = g_dinv1[j];
        float v = t[threadIdx.x][r] * dv;
        if (i == j) v += dv;
        g_S1[(size_t)i*NN + j] = v;
    }
}

__global__ void build_S2_kernel(const float* __restrict__ g) {
    int idx = blockIdx.x * 256 + threadIdx.x;
    int i = idx >> 11, j = idx & 2047;
    float v = g[idx] + (i == j ? 1.f : 0.f);
    g_S2[idx] = v * g_dinv2[j];
}

__global__ void adp_kernel(const float* __restrict__ nv1, const float* __restrict__ nv2) {
    int i = blockIdx.x;
    int tid = threadIdx.x;
    __shared__ float v1[10];
    __shared__ float red[40];
    if (tid < 10) v1[tid] = nv1[i*10 + tid];
    __syncthreads();
    float p[8];
    float mx = 0.f;
    #pragma unroll
    for (int c = 0; c < 8; c++) {
        int j = tid + c*256;
        float s = 0.f;
        #pragma unroll
        for (int t = 0; t < 10; t++) s += v1[t] * nv2[t*NN + j];
        s = s > 0.f ? s : 0.f;
        p[c] = s;
        mx = fmaxf(mx, s);
    }
    for (int o = 16; o; o >>= 1) mx = fmaxf(mx, __shfl_xor_sync(0xffffffffu, mx, o));
    if ((tid & 31) == 0) red[tid >> 5] = mx;
    __syncthreads();
    if (tid == 0) {
        float m = red[0];
        #pragma unroll
        for (int w = 1; w < 8; w++) m = fmaxf(m, red[w]);
        red[32] = m;
    }
    __syncthreads();
    mx = red[32];
    float sum = 0.f;
    #pragma unroll
    for (int c = 0; c < 8; c++) { float e = expf(p[c] - mx); p[c] = e; sum += e; }
    for (int o = 16; o; o >>= 1) sum += __shfl_xor_sync(0xffffffffu, sum, o);
    if ((tid & 31) == 0) red[16 + (tid >> 5)] = sum;
    __syncthreads();
    if (tid == 0) {
        float t = 0.f;
        #pragma unroll
        for (int w = 0; w < 8; w++) t += red[16 + w];
        red[33] = 1.f / t;
    }
    __syncthreads();
    float inv = red[33];
    #pragma unroll
    for (int c = 0; c < 8; c++) g_Ad[(size_t)i*NN + tid + c*256] = p[c] * inv;
}

// split S matrices fp32 -> bf16 hi/lo
__global__ void splitS_kernel(int sel) {
    const float* s = sel == 0 ? g_S1 : (sel == 1 ? g_S2 : g_Ad);
    __nv_bfloat16* h = sel == 0 ? g_S1h : (sel == 1 ? g_S2h : g_Adh);
    __nv_bfloat16* l = sel == 0 ? g_S1l : (sel == 1 ? g_S2l : g_Adl);
    size_t idx = (size_t)blockIdx.x * 256 + threadIdx.x;
    float v = s[idx];
    __nv_bfloat16 hh = __float2bfloat16(v);
    h[idx] = hh;
    l[idx] = __float2bfloat16(v - __bfloat162float(hh));
}

// transpose + split X (fp32 [2048 x 8320]) -> XT hi/lo (bf16 [8320 x 2048])
__global__ void xt_convert_kernel(int selX) {
    const float* X = bufF(selX);
    __shared__ float t[32][33];
    int c0 = blockIdx.x * 32;
    int j0 = blockIdx.y * 32;
    int tx = threadIdx.x;
    for (int r = threadIdx.y; r < 32; r += 8)
        t[r][tx] = X[(size_t)(j0 + r)*XW + c0 + tx];
    __syncthreads();
    for (int r = threadIdx.y; r < 32; r += 8) {
        int c = c0 + r;
        int j = j0 + tx;
        float v = t[tx][r];
        __nv_bfloat16 hh = __float2bfloat16(v);
        g_XTh[(size_t)c*NN + j] = hh;
        g_XTl[(size_t)c*NN + j] = __float2bfloat16(v - __bfloat162float(hh));
    }
}

// ---------------- x0 build ----------------
__global__ void build_x0_kernel(const float* __restrict__ inputs, const float* __restrict__ hx) {
    size_t total = (size_t)NN * XW;
    for (size_t idx = (size_t)blockIdx.x*256 + threadIdx.x; idx < total; idx += (size_t)gridDim.x*256) {
        int n = (int)(idx / XW);
        int c = (int)(idx - (size_t)n*XW);
        int i = c >> 6, b = c & 63;
        float v;
        if (i < 2) {
            v = inputs[(size_t)b*(NN*2) + n*2 + i];
        } else {
            int q = i - 2;
            int kk = (q < 64) ? 3 : 2;
            int d = q & 63;
            v = hx[(size_t)((b << 2) + kk)*NDD + (size_t)n*64 + d];
        }
        g_X0[idx] = v;
    }
}

__global__ void gc_init_kernel(const float* __restrict__ gb) {
    int idx = blockIdx.x * 256 + threadIdx.x;
    g_gc[idx] = gb[idx & 63];
}

// gc[b*NN+n, d] += sum_i X[n, i*64+b] * gw[(i*7+m)*64 + d]
__global__ void __launch_bounds__(256) proj_kernel(int selX, int m, const float* __restrict__ gw) {
    const float* X = bufF(selX);
    int n = blockIdx.x;
    int tid = threadIdx.x;
    __shared__ float sx[32*64];
    int b = tid >> 2;
    int d0 = (tid & 3) * 16;
    float acc[16];
    #pragma unroll
    for (int dd = 0; dd < 16; dd++) acc[dd] = 0.f;
    for (int ib = 0; ib < ISZ; ib += 32) {
        int cnt = min(32, ISZ - ib);
        __syncthreads();
        for (int t = tid; t < cnt*64; t += 256) sx[t] = X[(size_t)n*XW + (size_t)ib*64 + t];
        __syncthreads();
        for (int ii = 0; ii < cnt; ii++) {
            float a = sx[ii*64 + b];
            const float* wp = gw + ((size_t)(ib + ii)*7 + m)*64 + d0;
            #pragma unroll
            for (int dd = 0; dd < 16; dd++) acc[dd] += a * __ldg(&wp[dd]);
        }
    }
    float* out = g_gc + ((size_t)b*NN + n)*64 + d0;
    #pragma unroll
    for (int dd = 0; dd < 16; dd++) out[dd] += acc[dd];
}

// ---------------- bf16 split GEMM via mma.sync ----------------
// C[m,n] = alpha * sum_k A[m,k]*X[k,n] + beta*Ci[m,n]
// A: bf16 hi/lo K-major rows (NN stride); B: g_XTh/g_XTl rows n, K-major.
// Tile 128x128, KC=32. SMEM: 4 tiles (Ah,Al,Bh,Bl), 128 rows x 80B pitch.
#define KC 32
#define TROW 80
#define TILEB (128*TROW)        // 10240
#define STAGEB (4*TILEB)        // 40960
#define GEMM_SMEM (2*STAGEB)    // 81920
#define NSTG 64

__global__ void __launch_bounds__(256, 1)
gemm_kernel(int selA, int selCi, int selC, float alpha, float beta) {
    extern __shared__ char smem[];
    uint32_t sb = smem_u32(smem);
    int tid = threadIdx.x;
    int wid = tid >> 5;
    int lane = tid & 31;

    const __nv_bfloat16* Ah = selA == 0 ? g_S1h : (selA == 1 ? g_S2h : g_Adh);
    const __nv_bfloat16* Al = selA == 0 ? g_S1l : (selA == 1 ? g_S2l : g_Adl);
    const float* Ci = bufF(selCi);
    float* C = bufF(selC);

    int mBase = blockIdx.x * 128;   // m fastest => B tiles reused in L2
    int nBase = blockIdx.y * 128;

    // per-thread load slots: 8 x 16B chunks per stage
    const __nv_bfloat16* src[8];
    uint32_t dst[8];
    #pragma unroll
    for (int i = 0; i < 8; i++) {
        int c = tid + i*256;
        int tile = c >> 9;          // 0=Ah 1=Al 2=Bh 3=Bl
        int q = c & 511;
        int row = q >> 2, col = q & 3;
        dst[i] = (uint32_t)(tile*TILEB + row*TROW + col*16);
        const __nv_bfloat16* base;
        if (tile == 0)      base = Ah   + (size_t)(mBase + row) * NN;
        else if (tile == 1) base = Al   + (size_t)(mBase + row) * NN;
        else if (tile == 2) base = g_XTh + (size_t)(nBase + row) * NN;
        else                base = g_XTl + (size_t)(nBase + row) * NN;
        src[i] = base + col*8;
    }

    // prologue: stages 0,1
    #pragma unroll
    for (int s = 0; s < 2; s++) {
        uint32_t so = sb + (uint32_t)(s * STAGEB);
        #pragma unroll
        for (int i = 0; i < 8; i++) cp16(so + dst[i], src[i] + s*KC);
        cp_commit();
    }

    float acc[4][4][4];
    #pragma unroll
    for (int mf = 0; mf < 4; mf++)
        #pragma unroll
        for (int nf = 0; nf < 4; nf++)
            #pragma unroll
            for (int e = 0; e < 4; e++) acc[mf][nf][e] = 0.f;

    int mw = wid & 1;      // 2 warp rows (64 each)
    int nw = wid >> 1;     // 4 warp cols (32 each)

    // ldmatrix address components
    int a_row = lane & 15;
    int a_colb = (lane >> 4) * 16;                      // byte offset within kstep
    int b_row = ((lane >> 4) & 1) * 8 + (lane & 7);
    int b_colb = ((lane >> 3) & 1) * 16;

    for (int s = 0; s < NSTG; s++) {
        if (s >= NSTG - 2) cp_wait0(); else cp_wait1();
        __syncthreads();
        uint32_t so = sb + (uint32_t)((s & 1) * STAGEB);

        // 3 passes: (Ah,Bh), (Ah,Bl), (Al,Bh)
        #pragma unroll
        for (int pass = 0; pass < 3; pass++) {
            int at = (pass == 2) ? 1 : 0;
            int bt = (pass == 1) ? 3 : 2;
            uint32_t aBase = so + (uint32_t)(at*TILEB) + (uint32_t)((mw*64 + a_row) * TROW) + (uint32_t)a_colb;
            uint32_t bBase = so + (uint32_t)(bt*TILEB) + (uint32_t)((nw*32 + b_row) * TROW) + (uint32_t)b_colb;
            #pragma unroll
            for (int ks = 0; ks < 2; ks++) {
                uint32_t ar[4][4];
                #pragma unroll
                for (int mf = 0; mf < 4; mf++)
                    ldm_x4(ar[mf], aBase + (uint32_t)(mf*16*TROW) + (uint32_t)(ks*32));
                uint32_t br[2][4];
                #pragma unroll
                for (int bg = 0; bg < 2; bg++)
                    ldm_x4(br[bg], bBase + (uint32_t)(bg*16*TROW) + (uint32_t)(ks*32));
                #pragma unroll
                for (int mf = 0; mf < 4; mf++) {
                    #pragma unroll
                    for (int bg = 0; bg < 2; bg++) {
                        mma16816(acc[mf][bg*2+0], ar[mf], br[bg][0], br[bg][1]);
                        mma16816(acc[mf][bg*2+1], ar[mf], br[bg][2], br[bg][3]);
                    }
                }
            }
        }

        __syncthreads();
        int sn = s + 2;
        if (sn < NSTG) {
            uint32_t so2 = sb + (uint32_t)((sn & 1) * STAGEB);
            #pragma unroll
            for (int i = 0; i < 8; i++) cp16(so2 + dst[i], src[i] + sn*KC);
            cp_commit();
        }
    }

    // epilogue
    int gid = lane >> 2, tg = lane & 3;
    #pragma unroll
    for (int mf = 0; mf < 4; mf++) {
        int row0 = mBase + mw*64 + mf*16 + gid;
        #pragma unroll
        for (int nf = 0; nf < 4; nf++) {
            int col = nBase + nw*32 + nf*8 + tg*2;
            size_t i0 = (size_t)row0 * XW + col;
            size_t i1 = i0 + (size_t)8 * XW;
            float2 v0, v1;
            v0.x = alpha * acc[mf][nf][0];
            v0.y = alpha * acc[mf][nf][1];
            v1.x = alpha * acc[mf][nf][2];
            v1.y = alpha * acc[mf][nf][3];
            if (beta != 0.f) {
                float2 c0 = *(const float2*)&Ci[i0];
                float2 c1 = *(const float2*)&Ci[i1];
                v0.x += beta * c0.x; v0.y += beta * c0.y;
                v1.x += beta * c1.x; v1.y += beta * c1.y;
            }
            *(float2*)&C[i0] = v0;
            *(float2*)&C[i1] = v1;
        }
    }
}

// ---------------- attention ----------------
__global__ void logits_kernel(const float* __restrict__ hx, const float* __restrict__ R,
                              const float* __restrict__ aw, const float* __restrict__ ab) {
    int bk = blockIdx.x;
    int k = bk & 3;
    int tid = threadIdx.x;
    const float* hp = hx + (size_t)bk * NDD;
    const float* rp = R + (size_t)k * NDD;
    float s = 0.f;
    for (int t = tid; t < NDD; t += 256) s += (hp[t] + rp[t]) * aw[t];
    for (int o = 16; o; o >>= 1) s += __shfl_down_sync(0xffffffffu, s, o);
    __shared__ float red[8];
    if ((tid & 31) == 0) red[tid >> 5] = s;
    __syncthreads();
    if (tid == 0) {
        float t = 0.f;
        #pragma unroll
        for (int w = 0; w < 8; w++) t += red[w];
        g_logits[bk] = t + ab[0];
    }
}

__global__ void weight_kernel() {
    int b = threadIdx.x;
    if (b < BB) {
        float l0 = g_logits[b*4+0], l1 = g_logits[b*4+1], l2 = g_logits[b*4+2], l3 = g_logits[b*4+3];
        float m = fmaxf(fmaxf(l0, l1), fmaxf(l2, l3));
        float e0 = expf(l0 - m), e1 = expf(l1 - m), e2 = expf(l2 - m), e3 = expf(l3 - m);
        float inv = 1.f / (e0 + e1 + e2 + e3);
        g_wt[b*4+0] = e0 * inv; g_wt[b*4+1] = e1 * inv;
        g_wt[b*4+2] = e2 * inv; g_wt[b*4+3] = e3 * inv;
    }
}

// ---------------- output ----------------
__global__ void __launch_bounds__(256) final_kernel(const float* __restrict__ W,
                                                    const float* __restrict__ bbias,
                                                    const float* __restrict__ hx,
                                                    const float* __restrict__ R,
                                                    float* __restrict__ out, int write_hx) {
    __shared__ float sW[64*64];
    __shared__ float sg[4*64];
    int tid = threadIdx.x;
    int r0 = blockIdx.x * 4;
    for (int t = tid; t < 4096; t += 256) sW[t] = W[t];
    {
        float v = g_gc[(size_t)r0*64 + tid];
        sg[tid] = v > 0.f ? v : 0.01f * v;
    }
    __syncthreads();
    int rl = tid >> 6;
    int d = tid & 63;
    int r = r0 + rl;
    int b = r >> 11;
    int n = r & 2047;
    float acc = 0.f;
    #pragma unroll
    for (int e = 0; e < 64; e++) acc += sg[rl*64 + e] * sW[e*64 + d];
    float att = 0.f;
    #pragma unroll
    for (int k = 0; k < 4; k++) {
        float xv = hx[(size_t)((b << 2) + k)*NDD + (size_t)n*64 + d] + R[(size_t)k*NDD + (size_t)n*64 + d];
        att += xv * g_wt[b*4 + k];
    }
    float o = acc + bbias[(size_t)n*64 + d] + att;
    out[(size_t)b*NDD + (size_t)n*64 + d] = o;
    if (write_hx)
        out[(size_t)OUT1 + (size_t)((b << 2) + 3)*NDD + (size_t)n*64 + d] = o;
}

__global__ void hxcopy_kernel(const float* __restrict__ hx, float* __restrict__ out) {
    size_t idx = (size_t)blockIdx.x * 256 + threadIdx.x;
    int b = (int)(idx / (3*(size_t)NDD));
    size_t rem = idx - (size_t)b * (3*(size_t)NDD);
    int kk = (int)(rem / NDD);
    size_t j = rem - (size_t)kk * NDD;
    out[(size_t)OUT1 + (size_t)(b*4 + kk)*NDD + j] = hx[(size_t)(b*4 + kk + 1)*NDD + j];
}

// ---------------- launch ----------------
extern "C" void kernel_launch(void* const* d_in, const int* in_sizes, int n_in,
                              void* d_out, int out_size) {
    const float* inputs = (const float*)d_in[0];
    const float* hx     = (const float*)d_in[1];
    const float* graph  = (const float*)d_in[2];
    const float* nv1    = (const float*)d_in[3];
    const float* nv2    = (const float*)d_in[4];
    const float* W      = (const float*)d_in[5];
    const float* bbias  = (const float*)d_in[6];
    const float* R      = (const float*)d_in[7];
    const float* gw     = (const float*)d_in[8];
    const float* gb     = (const float*)d_in[9];
    const float* aw     = (const float*)d_in[10];
    const float* ab     = (const float*)d_in[11];
    float* out = (float*)d_out;

    int write_hx = ((size_t)out_size >= FULL_OUT) ? 1 : 0;

    cudaFuncSetAttribute(gemm_kernel, cudaFuncAttributeMaxDynamicSharedMemorySize, GEMM_SMEM);

    // supports + adaptive adjacency
    rowsum_dinv_kernel<<<NN, 256>>>(graph);
    colsum_part_kernel<<<dim3(NN/256, 8), 256>>>(graph);
    colsum_fin_kernel<<<NN/256, 256>>>();
    build_S1_kernel<<<dim3(64, 64), dim3(32, 8)>>>(graph);
    build_S2_kernel<<<(NN*NN)/256, 256>>>(graph);
    adp_kernel<<<NN, 256>>>(nv1, nv2);
    splitS_kernel<<<(NN*NN)/256, 256>>>(0);
    splitS_kernel<<<(NN*NN)/256, 256>>>(1);
    splitS_kernel<<<(NN*NN)/256, 256>>>(2);

    // x0 + gc init
    build_x0_kernel<<<66560, 256>>>(inputs, hx);
    gc_init_kernel<<<OUT1/256, 256>>>(gb);

    dim3 ggrid(NN/128, XW/128);           // (16 m-tiles, 65 n-tiles)
    dim3 xgrid(XW/32, NN/32);
    dim3 xblk(32, 8);

    // m0 = x0
    proj_kernel<<<NN, 256>>>(0, 0, gw);
    xt_convert_kernel<<<xgrid, xblk>>>(0);                 // B = x0
    // m1 = S1 @ x0 -> X1
    gemm_kernel<<<ggrid, 256, GEMM_SMEM>>>(0, 0, 1, 1.f, 0.f);
    proj_kernel<<<NN, 256>>>(1, 1, gw);
    xt_convert_kernel<<<xgrid, xblk>>>(1);                 // B = m1
    // m2 = 2*S1 @ m1 - x0 -> X2
    gemm_kernel<<<ggrid, 256, GEMM_SMEM>>>(0, 0, 2, 2.f, -1.f);
    proj_kernel<<<NN, 256>>>(2, 2, gw);
    // m3 = S2 @ m1 -> X0   (B still m1)
    gemm_kernel<<<ggrid, 256, GEMM_SMEM>>>(1, 0, 0, 1.f, 0.f);
    proj_kernel<<<NN, 256>>>(0, 3, gw);
    xt_convert_kernel<<<xgrid, xblk>>>(0);                 // B = m3
    // m4 = 2*S2 @ m3 - m1 -> X2
    gemm_kernel<<<ggrid, 256, GEMM_SMEM>>>(1, 1, 2, 2.f, -1.f);
    proj_kernel<<<NN, 256>>>(2, 4, gw);
    // m5 = A @ m3 -> X1
    gemm_kernel<<<ggrid, 256, GEMM_SMEM>>>(2, 0, 1, 1.f, 0.f);
    proj_kernel<<<NN, 256>>>(1, 5, gw);
    xt_convert_kernel<<<xgrid, xblk>>>(1);                 // B = m5
    // m6 = A @ m5 - m3 -> X2
    gemm_kernel<<<ggrid, 256, GEMM_SMEM>>>(2, 0, 2, 1.f, -1.f);
    proj_kernel<<<NN, 256>>>(2, 6, gw);

    // attention
    logits_kernel<<<BB*4, 256>>>(hx, R, aw, ab);
    weight_kernel<<<1, 64>>>();

    // output + new hidden state
    final_kernel<<<(BB*NN)/4, 256>>>(W, bbias, hx, R, out, write_hx);
    if (write_hx)
        hxcopy_kernel<<<(unsigned)((size_t)BB*3*NDD/256), 256>>>(hx, out);
}

// round 4
// speedup vs baseline: 1.8125x; 1.0978x over previous
#include <cuda_runtime.h>
#include <cuda_bf16.h>
#include <math.h>
#include <stdint.h>

#define NN 2048
#define BB 64
#define DD 64
#define ISZ 130
#define XW (ISZ*BB)          // 8320
#define NDD (NN*DD)          // 131072
#define OUT1 (BB*NDD)        // 8388608
#define HXPART ((size_t)BB*4*NDD)
#define FULL_OUT ((size_t)OUT1 + HXPART)

// ---------------- scratch ----------------
static __device__ __nv_bfloat16 g_S1h[(size_t)NN*NN];
static __device__ __nv_bfloat16 g_S1l[(size_t)NN*NN];
static __device__ __nv_bfloat16 g_S2h[(size_t)NN*NN];
static __device__ __nv_bfloat16 g_S2l[(size_t)NN*NN];
static __device__ __nv_bfloat16 g_Adh[(size_t)NN*NN];
static __device__ __nv_bfloat16 g_Adl[(size_t)NN*NN];
static __device__ float g_dinv1[NN];
static __device__ float g_dinv2[NN];
static __device__ float g_cspart[8*NN];
static __device__ float g_X0[(size_t)NN*XW];
static __device__ float g_X1[(size_t)NN*XW];
static __device__ float g_X2[(size_t)NN*XW];
static __device__ __nv_bfloat16 g_XTh[(size_t)XW*NN];
static __device__ __nv_bfloat16 g_XTl[(size_t)XW*NN];
static __device__ float g_gc[(size_t)BB*NN*DD];
static __device__ float g_logits[BB*4];
static __device__ float g_wt[BB*4];

__device__ __forceinline__ float* bufF(int s) {
    switch (s) { case 0: return g_X0; case 1: return g_X1; default: return g_X2; }
}

// ---------------- PTX helpers ----------------
__device__ __forceinline__ uint32_t smem_u32(const void* p) {
    uint32_t a;
    asm("{ .reg .u64 t; cvta.to.shared.u64 t, %1; cvt.u32.u64 %0, t; }" : "=r"(a) : "l"(p));
    return a;
}
__device__ __forceinline__ void cp16(uint32_t dst, const void* src) {
    asm volatile("cp.async.cg.shared.global [%0], [%1], 16;" :: "r"(dst), "l"(src) : "memory");
}
__device__ __forceinline__ void cp_commit() { asm volatile("cp.async.commit_group;" ::: "memory"); }
__device__ __forceinline__ void cp_wait2() { asm volatile("cp.async.wait_group 2;" ::: "memory"); }

__device__ __forceinline__ void ldm_x4(uint32_t* r, uint32_t addr) {
    asm volatile("ldmatrix.sync.aligned.m8n8.x4.shared.b16 {%0,%1,%2,%3}, [%4];"
                 : "=r"(r[0]), "=r"(r[1]), "=r"(r[2]), "=r"(r[3]) : "r"(addr));
}
__device__ __forceinline__ void mma16816(float* c, const uint32_t* a, uint32_t b0, uint32_t b1) {
    asm volatile(
        "mma.sync.aligned.m16n8k16.row.col.f32.bf16.bf16.f32 "
        "{%0,%1,%2,%3}, {%4,%5,%6,%7}, {%8,%9}, {%0,%1,%2,%3};"
        : "+f"(c[0]), "+f"(c[1]), "+f"(c[2]), "+f"(c[3])
        : "r"(a[0]), "r"(a[1]), "r"(a[2]), "r"(a[3]), "r"(b0), "r"(b1));
}

// ---------------- support construction ----------------
__global__ void rowsum_dinv_kernel(const float* __restrict__ g) {
    int row = blockIdx.x;
    int tid = threadIdx.x;
    float s = 0.f;
    for (int j = tid; j < NN; j += 256) s += g[(size_t)row*NN + j];
    for (int o = 16; o; o >>= 1) s += __shfl_down_sync(0xffffffffu, s, o);
    __shared__ float red[8];
    if ((tid & 31) == 0) red[tid >> 5] = s;
    __syncthreads();
    if (tid == 0) {
        float t = 0.f;
        #pragma unroll
        for (int w = 0; w < 8; w++) t += red[w];
        g_dinv1[row] = 1.f / (1.f + t);
    }
}

__global__ void colsum_part_kernel(const float* __restrict__ g) {
    int col = blockIdx.x * 256 + threadIdx.x;
    int r0 = blockIdx.y * 256;
    float s = 0.f;
    #pragma unroll 8
    for (int r = 0; r < 256; r++) s += g[(size_t)(r0 + r)*NN + col];
    g_cspart[blockIdx.y*NN + col] = s;
}

__global__ void colsum_fin_kernel() {
    int col = blockIdx.x * 256 + threadIdx.x;
    float s = 0.f;
    #pragma unroll
    for (int y = 0; y < 8; y++) s += g_cspart[y*NN + col];
    g_dinv2[col] = 1.f / (1.f + s);
}

// S1[i,j] = (graph[j,i] + d_ij) * dinv1[j]  -> bf16 hi/lo directly
__global__ void build_S1_kernel(const float* __restrict__ g) {
    __shared__ float t[32][33];
    int bi = blockIdx.x * 32;
    int bj = blockIdx.y * 32;
    for (int r = threadIdx.y; r < 32; r += 8)
        t[r][threadIdx.x] = g[(size_t)(bj + r)*NN + bi + threadIdx.x];
    __syncthreads();
    for (int r = threadIdx.y; r < 32; r += 8) {
        int i = bi + r, j = bj + threadIdx.x;
        float dv = g_dinv1[j];
        float v = t[threadIdx.x][r] * dv;
        if (i == j) v += dv;
        __nv_bfloat16 hh = __float2bfloat16(v);
        g_S1h[(size_t)i*NN + j] = hh;
        g_S1l[(size_t)i*NN + j] = __float2bfloat16(v - __bfloat162float(hh));
    }
}

__global__ void build_S2_kernel(const float* __restrict__ g) {
    int idx = blockIdx.x * 256 + threadIdx.x;
    int i = idx >> 11, j = idx & 2047;
    float v = (g[idx] + (i == j ? 1.f : 0.f)) * g_dinv2[j];
    __nv_bfloat16 hh = __float2bfloat16(v);
    g_S2h[idx] = hh;
    g_S2l[idx] = __float2bfloat16(v - __bfloat162float(hh));
}

__global__ void adp_kernel(const float* __restrict__ nv1, const float* __restrict__ nv2) {
    int i = blockIdx.x;
    int tid = threadIdx.x;
    __shared__ float v1[10];
    __shared__ float red[40];
    if (tid < 10) v1[tid] = nv1[i*10 + tid];
    __syncthreads();
    float p[8];
    float mx = 0.f;
    #pragma unroll
    for (int c = 0; c < 8; c++) {
        int j = tid + c*256;
        float s = 0.f;
        #pragma unroll
        for (int t = 0; t < 10; t++) s += v1[t] * nv2[t*NN + j];
        s = s > 0.f ? s : 0.f;
        p[c] = s;
        mx = fmaxf(mx, s);
    }
    for (int o = 16; o; o >>= 1) mx = fmaxf(mx, __shfl_xor_sync(0xffffffffu, mx, o));
    if ((tid & 31) == 0) red[tid >> 5] = mx;
    __syncthreads();
    if (tid == 0) {
        float m = red[0];
        #pragma unroll
        for (int w = 1; w < 8; w++) m = fmaxf(m, red[w]);
        red[32] = m;
    }
    __syncthreads();
    mx = red[32];
    float sum = 0.f;
    #pragma unroll
    for (int c = 0; c < 8; c++) { float e = expf(p[c] - mx); p[c] = e; sum += e; }
    for (int o = 16; o; o >>= 1) sum += __shfl_xor_sync(0xffffffffu, sum, o);
    if ((tid & 31) == 0) red[16 + (tid >> 5)] = sum;
    __syncthreads();
    if (tid == 0) {
        float t = 0.f;
        #pragma unroll
        for (int w = 0; w < 8; w++) t += red[16 + w];
        red[33] = 1.f / t;
    }
    __syncthreads();
    float inv = red[33];
    #pragma unroll
    for (int c = 0; c < 8; c++) {
        float v = p[c] * inv;
        __nv_bfloat16 hh = __float2bfloat16(v);
        size_t idx = (size_t)i*NN + tid + c*256;
        g_Adh[idx] = hh;
        g_Adl[idx] = __float2bfloat16(v - __bfloat162float(hh));
    }
}

// transpose + split X (fp32 [2048 x 8320]) -> XT hi/lo (bf16 [8320 x 2048])
__global__ void xt_convert_kernel(int selX) {
    const float* X = bufF(selX);
    __shared__ float t[32][33];
    int c0 = blockIdx.x * 32;
    int j0 = blockIdx.y * 32;
    int tx = threadIdx.x;
    for (int r = threadIdx.y; r < 32; r += 8)
        t[r][tx] = X[(size_t)(j0 + r)*XW + c0 + tx];
    __syncthreads();
    for (int r = threadIdx.y; r < 32; r += 8) {
        int c = c0 + r;
        int j = j0 + tx;
        float v = t[tx][r];
        __nv_bfloat16 hh = __float2bfloat16(v);
        g_XTh[(size_t)c*NN + j] = hh;
        g_XTl[(size_t)c*NN + j] = __float2bfloat16(v - __bfloat162float(hh));
    }
}

// ---------------- x0 build ----------------
__global__ void build_x0_kernel(const float* __restrict__ inputs, const float* __restrict__ hx) {
    size_t total = (size_t)NN * XW;
    for (size_t idx = (size_t)blockIdx.x*256 + threadIdx.x; idx < total; idx += (size_t)gridDim.x*256) {
        int n = (int)(idx / XW);
        int c = (int)(idx - (size_t)n*XW);
        int i = c >> 6, b = c & 63;
        float v;
        if (i < 2) {
            v = inputs[(size_t)b*(NN*2) + n*2 + i];
        } else {
            int q = i - 2;
            int kk = (q < 64) ? 3 : 2;
            int d = q & 63;
            v = hx[(size_t)((b << 2) + kk)*NDD + (size_t)n*64 + d];
        }
        g_X0[idx] = v;
    }
}

__global__ void gc_init_kernel(const float* __restrict__ gb) {
    int idx = blockIdx.x * 256 + threadIdx.x;
    g_gc[idx] = gb[idx & 63];
}

// gc[b*NN+n, d] += sum_i X[n, i*64+b] * gw[(i*7+m)*64 + d]
__global__ void __launch_bounds__(256) proj_kernel(int selX, int m, const float* __restrict__ gw) {
    const float* X = bufF(selX);
    int n = blockIdx.x;
    int tid = threadIdx.x;
    __shared__ float sx[32*64];
    int b = tid >> 2;
    int d0 = (tid & 3) * 16;
    float acc[16];
    #pragma unroll
    for (int dd = 0; dd < 16; dd++) acc[dd] = 0.f;
    for (int ib = 0; ib < ISZ; ib += 32) {
        int cnt = min(32, ISZ - ib);
        __syncthreads();
        for (int t = tid; t < cnt*64; t += 256) sx[t] = X[(size_t)n*XW + (size_t)ib*64 + t];
        __syncthreads();
        for (int ii = 0; ii < cnt; ii++) {
            float a = sx[ii*64 + b];
            const float* wp = gw + ((size_t)(ib + ii)*7 + m)*64 + d0;
            #pragma unroll
            for (int dd = 0; dd < 16; dd++) acc[dd] += a * __ldg(&wp[dd]);
        }
    }
    float* out = g_gc + ((size_t)b*NN + n)*64 + d0;
    #pragma unroll
    for (int dd = 0; dd < 16; dd++) out[dd] += acc[dd];
}

// ---------------- bf16 split GEMM via mma.sync ----------------
// C[m,n] = alpha * sum_k A[m,k]*X[k,n] + beta*Ci[m,n]
// Tile 128x128, KC=32, 4-stage cp.async pipeline, 1 sync per stage,
// fragments cached across the 3 split products.
#define KC 32
#define TROW 80
#define TILEB (128*TROW)        // 10240
#define STAGEB (4*TILEB)        // 40960
#define GEMM_SMEM (4*STAGEB)    // 163840
#define NSTG 64

__global__ void __launch_bounds__(256, 1)
gemm_kernel(int selA, int selCi, int selC, float alpha, float beta) {
    extern __shared__ char smem[];
    uint32_t sb = smem_u32(smem);
    int tid = threadIdx.x;
    int wid = tid >> 5;
    int lane = tid & 31;

    const __nv_bfloat16* Ah = selA == 0 ? g_S1h : (selA == 1 ? g_S2h : g_Adh);
    const __nv_bfloat16* Al = selA == 0 ? g_S1l : (selA == 1 ? g_S2l : g_Adl);
    const float* Ci = bufF(selCi);
    float* C = bufF(selC);

    int mBase = blockIdx.x * 128;
    int nBase = blockIdx.y * 128;

    // per-thread load slots: 8 x 16B chunks per stage
    const __nv_bfloat16* src[8];
    uint32_t dst[8];
    #pragma unroll
    for (int i = 0; i < 8; i++) {
        int c = tid + i*256;
        int tile = c >> 9;          // 0=Ah 1=Al 2=Bh 3=Bl
        int q = c & 511;
        int row = q >> 2, col = q & 3;
        dst[i] = (uint32_t)(tile*TILEB + row*TROW + col*16);
        const __nv_bfloat16* base;
        if (tile == 0)      base = Ah    + (size_t)(mBase + row) * NN;
        else if (tile == 1) base = Al    + (size_t)(mBase + row) * NN;
        else if (tile == 2) base = g_XTh + (size_t)(nBase + row) * NN;
        else                base = g_XTl + (size_t)(nBase + row) * NN;
        src[i] = base + col*8;
    }

    // prologue: stages 0..2
    #pragma unroll
    for (int s = 0; s < 3; s++) {
        uint32_t so = sb + (uint32_t)(s * STAGEB);
        #pragma unroll
        for (int i = 0; i < 8; i++) cp16(so + dst[i], src[i] + s*KC);
        cp_commit();
    }

    float acc[4][4][4];
    #pragma unroll
    for (int mf = 0; mf < 4; mf++)
        #pragma unroll
        for (int nf = 0; nf < 4; nf++)
            #pragma unroll
            for (int e = 0; e < 4; e++) acc[mf][nf][e] = 0.f;

    int mw = wid & 1;      // 2 warp rows (64 each)
    int nw = wid >> 1;     // 4 warp cols (32 each)

    int a_row = lane & 15;
    int a_colb = (lane >> 4) * 16;
    int b_row = ((lane >> 4) & 1) * 8 + (lane & 7);
    int b_colb = ((lane >> 3) & 1) * 16;

    uint32_t aOffH = (uint32_t)(0*TILEB) + (uint32_t)((mw*64 + a_row) * TROW) + (uint32_t)a_colb;
    uint32_t aOffL = aOffH + (uint32_t)TILEB;
    uint32_t bOffH = (uint32_t)(2*TILEB) + (uint32_t)((nw*32 + b_row) * TROW) + (uint32_t)b_colb;
    uint32_t bOffL = bOffH + (uint32_t)TILEB;

    for (int s = 0; s < NSTG; s++) {
        cp_wait2();
        __syncthreads();
        // prefetch stage s+3 into buffer (s+3)&3 (safe: it held stage s-1, done)
        int sn = s + 3;
        if (sn < NSTG) {
            uint32_t so2 = sb + (uint32_t)((sn & 3) * STAGEB);
            #pragma unroll
            for (int i = 0; i < 8; i++) cp16(so2 + dst[i], src[i] + sn*KC);
        }
        cp_commit();   // exactly one group per iteration keeps wait_group 2 exact

        uint32_t so = sb + (uint32_t)((s & 3) * STAGEB);
        #pragma unroll
        for (int ks = 0; ks < 2; ks++) {
            uint32_t kb = (uint32_t)(ks*32);
            uint32_t arh[4][4], arl[4][4], brh[2][4], brl[2][4];
            #pragma unroll
            for (int mf = 0; mf < 4; mf++) {
                ldm_x4(arh[mf], so + aOffH + (uint32_t)(mf*16*TROW) + kb);
                ldm_x4(arl[mf], so + aOffL + (uint32_t)(mf*16*TROW) + kb);
            }
            #pragma unroll
            for (int bg = 0; bg < 2; bg++) {
                ldm_x4(brh[bg], so + bOffH + (uint32_t)(bg*16*TROW) + kb);
                ldm_x4(brl[bg], so + bOffL + (uint32_t)(bg*16*TROW) + kb);
            }
            #pragma unroll
            for (int mf = 0; mf < 4; mf++) {
                #pragma unroll
                for (int bg = 0; bg < 2; bg++) {
                    float* a0 = acc[mf][bg*2+0];
                    float* a1 = acc[mf][bg*2+1];
                    mma16816(a0, arh[mf], brh[bg][0], brh[bg][1]);
                    mma16816(a1, arh[mf], brh[bg][2], brh[bg][3]);
                    mma16816(a0, arh[mf], brl[bg][0], brl[bg][1]);
                    mma16816(a1, arh[mf], brl[bg][2], brl[bg][3]);
                    mma16816(a0, arl[mf], brh[bg][0], brh[bg][1]);
                    mma16816(a1, arl[mf], brh[bg][2], brh[bg][3]);
                }
            }
        }
    }

    // epilogue
    int gid = lane >> 2, tg = lane & 3;
    #pragma unroll
    for (int mf = 0; mf < 4; mf++) {
        int row0 = mBase + mw*64 + mf*16 + gid;
        #pragma unroll
        for (int nf = 0; nf < 4; nf++) {
            int col = nBase + nw*32 + nf*8 + tg*2;
            size_t i0 = (size_t)row0 * XW + col;
            size_t i1 = i0 + (size_t)8 * XW;
            float2 v0, v1;
            v0.x = alpha * acc[mf][nf][0];
            v0.y = alpha * acc[mf][nf][1];
            v1.x = alpha * acc[mf][nf][2];
            v1.y = alpha * acc[mf][nf][3];
            if (beta != 0.f) {
                float2 c0 = *(const float2*)&Ci[i0];
                float2 c1 = *(const float2*)&Ci[i1];
                v0.x += beta * c0.x; v0.y += beta * c0.y;
                v1.x += beta * c1.x; v1.y += beta * c1.y;
            }
            *(float2*)&C[i0] = v0;
            *(float2*)&C[i1] = v1;
        }
    }
}

// ---------------- attention ----------------
__global__ void logits_kernel(const float* __restrict__ hx, const float* __restrict__ R,
                              const float* __restrict__ aw, const float* __restrict__ ab) {
    int bk = blockIdx.x;
    int k = bk & 3;
    int tid = threadIdx.x;
    const float* hp = hx + (size_t)bk * NDD;
    const float* rp = R + (size_t)k * NDD;
    float s = 0.f;
    for (int t = tid; t < NDD; t += 256) s += (hp[t] + rp[t]) * aw[t];
    for (int o = 16; o; o >>= 1) s += __shfl_down_sync(0xffffffffu, s, o);
    __shared__ float red[8];
    if ((tid & 31) == 0) red[tid >> 5] = s;
    __syncthreads();
    if (tid == 0) {
        float t = 0.f;
        #pragma unroll
        for (int w = 0; w < 8; w++) t += red[w];
        g_logits[bk] = t + ab[0];
    }
}

__global__ void weight_kernel() {
    int b = threadIdx.x;
    if (b < BB) {
        float l0 = g_logits[b*4+0], l1 = g_logits[b*4+1], l2 = g_logits[b*4+2], l3 = g_logits[b*4+3];
        float m = fmaxf(fmaxf(l0, l1), fmaxf(l2, l3));
        float e0 = expf(l0 - m), e1 = expf(l1 - m), e2 = expf(l2 - m), e3 = expf(l3 - m);
        float inv = 1.f / (e0 + e1 + e2 + e3);
        g_wt[b*4+0] = e0 * inv; g_wt[b*4+1] = e1 * inv;
        g_wt[b*4+2] = e2 * inv; g_wt[b*4+3] = e3 * inv;
    }
}

// ---------------- output ----------------
__global__ void __launch_bounds__(256) final_kernel(const float* __restrict__ W,
                                                    const float* __restrict__ bbias,
                                                    const float* __restrict__ hx,
                                                    const float* __restrict__ R,
                                                    float* __restrict__ out, int write_hx) {
    __shared__ float sW[64*64];
    __shared__ float sg[4*64];
    int tid = threadIdx.x;
    int r0 = blockIdx.x * 4;
    for (int t = tid; t < 4096; t += 256) sW[t] = W[t];
    {
        float v = g_gc[(size_t)r0*64 + tid];
        sg[tid] = v > 0.f ? v : 0.01f * v;
    }
    __syncthreads();
    int rl = tid >> 6;
    int d = tid & 63;
    int r = r0 + rl;
    int b = r >> 11;
    int n = r & 2047;
    float acc = 0.f;
    #pragma unroll
    for (int e = 0; e < 64; e++) acc += sg[rl*64 + e] * sW[e*64 + d];
    float att = 0.f;
    #pragma unroll
    for (int k = 0; k < 4; k++) {
        float xv = hx[(size_t)((b << 2) + k)*NDD + (size_t)n*64 + d] + R[(size_t)k*NDD + (size_t)n*64 + d];
        att += xv * g_wt[b*4 + k];
    }
    float o = acc + bbias[(size_t)n*64 + d] + att;
    out[(size_t)b*NDD + (size_t)n*64 + d] = o;
    if (write_hx)
        out[(size_t)OUT1 + (size_t)((b << 2) + 3)*NDD + (size_t)n*64 + d] = o;
}

__global__ void hxcopy_kernel(const float* __restrict__ hx, float* __restrict__ out) {
    size_t idx = (size_t)blockIdx.x * 256 + threadIdx.x;
    int b = (int)(idx / (3*(size_t)NDD));
    size_t rem = idx - (size_t)b * (3*(size_t)NDD);
    int kk = (int)(rem / NDD);
    size_t j = rem - (size_t)kk * NDD;
    out[(size_t)OUT1 + (size_t)(b*4 + kk)*NDD + j] = hx[(size_t)(b*4 + kk + 1)*NDD + j];
}

// ---------------- launch ----------------
extern "C" void kernel_launch(void* const* d_in, const int* in_sizes, int n_in,
                              void* d_out, int out_size) {
    const float* inputs = (const float*)d_in[0];
    const float* hx     = (const float*)d_in[1];
    const float* graph  = (const float*)d_in[2];
    const float* nv1    = (const float*)d_in[3];
    const float* nv2    = (const float*)d_in[4];
    const float* W      = (const float*)d_in[5];
    const float* bbias  = (const float*)d_in[6];
    const float* R      = (const float*)d_in[7];
    const float* gw     = (const float*)d_in[8];
    const float* gb     = (const float*)d_in[9];
    const float* aw     = (const float*)d_in[10];
    const float* ab     = (const float*)d_in[11];
    float* out = (float*)d_out;

    int write_hx = ((size_t)out_size >= FULL_OUT) ? 1 : 0;

    cudaFuncSetAttribute(gemm_kernel, cudaFuncAttributeMaxDynamicSharedMemorySize, GEMM_SMEM);

    // supports + adaptive adjacency (bf16 hi/lo written directly)
    rowsum_dinv_kernel<<<NN, 256>>>(graph);
    colsum_part_kernel<<<dim3(NN/256, 8), 256>>>(graph);
    colsum_fin_kernel<<<NN/256, 256>>>();
    build_S1_kernel<<<dim3(64, 64), dim3(32, 8)>>>(graph);
    build_S2_kernel<<<(NN*NN)/256, 256>>>(graph);
    adp_kernel<<<NN, 256>>>(nv1, nv2);

    // x0 + gc init
    build_x0_kernel<<<66560, 256>>>(inputs, hx);
    gc_init_kernel<<<OUT1/256, 256>>>(gb);

    dim3 ggrid(NN/128, XW/128);           // (16 m-tiles, 65 n-tiles)
    dim3 xgrid(XW/32, NN/32);
    dim3 xblk(32, 8);

    // m0 = x0
    proj_kernel<<<NN, 256>>>(0, 0, gw);
    xt_convert_kernel<<<xgrid, xblk>>>(0);                 // B = x0
    // m1 = S1 @ x0 -> X1
    gemm_kernel<<<ggrid, 256, GEMM_SMEM>>>(0, 0, 1, 1.f, 0.f);
    proj_kernel<<<NN, 256>>>(1, 1, gw);
    xt_convert_kernel<<<xgrid, xblk>>>(1);                 // B = m1
    // m2 = 2*S1 @ m1 - x0 -> X2
    gemm_kernel<<<ggrid, 256, GEMM_SMEM>>>(0, 0, 2, 2.f, -1.f);
    proj_kernel<<<NN, 256>>>(2, 2, gw);
    // m3 = S2 @ m1 -> X0   (B still m1)
    gemm_kernel<<<ggrid, 256, GEMM_SMEM>>>(1, 0, 0, 1.f, 0.f);
    proj_kernel<<<NN, 256>>>(0, 3, gw);
    xt_convert_kernel<<<xgrid, xblk>>>(0);                 // B = m3
    // m4 = 2*S2 @ m3 - m1 -> X2
    gemm_kernel<<<ggrid, 256, GEMM_SMEM>>>(1, 1, 2, 2.f, -1.f);
    proj_kernel<<<NN, 256>>>(2, 4, gw);
    // m5 = A @ m3 -> X1
    gemm_kernel<<<ggrid, 256, GEMM_SMEM>>>(2, 0, 1, 1.f, 0.f);
    proj_kernel<<<NN, 256>>>(1, 5, gw);
    xt_convert_kernel<<<xgrid, xblk>>>(1);                 // B = m5
    // m6 = A @ m5 - m3 -> X2
    gemm_kernel<<<ggrid, 256, GEMM_SMEM>>>(2, 0, 2, 1.f, -1.f);
    proj_kernel<<<NN, 256>>>(2, 6, gw);

    // attention
    logits_kernel<<<BB*4, 256>>>(hx, R, aw, ab);
    weight_kernel<<<1, 64>>>();

    // output + new hidden state
    final_kernel<<<(BB*NN)/4, 256>>>(W, bbias, hx, R, out, write_hx);
    if (write_hx)
        hxcopy_kernel<<<(unsigned)((size_t)BB*3*NDD/256), 256>>>(hx, out);
}

// round 5
// speedup vs baseline: 2.7744x; 1.5307x over previous
#include <cuda_runtime.h>
#include <cuda_bf16.h>
#include <math.h>
#include <stdint.h>

#define NN 2048
#define BB 64
#define DD 64
#define ISZ 130
#define XW (ISZ*BB)          // 8320
#define NDD (NN*DD)          // 131072
#define OUT1 (BB*NDD)        // 8388608
#define HXPART ((size_t)BB*4*NDD)
#define FULL_OUT ((size_t)OUT1 + HXPART)
#define PSZ ((size_t)2048*4096)

// ---------------- scratch ----------------
static __device__ __nv_bfloat16 g_S1h[(size_t)NN*NN];
static __device__ __nv_bfloat16 g_S1l[(size_t)NN*NN];
static __device__ __nv_bfloat16 g_S2h[(size_t)NN*NN];
static __device__ __nv_bfloat16 g_S2l[(size_t)NN*NN];
static __device__ __nv_bfloat16 g_Adh[(size_t)NN*NN];
static __device__ __nv_bfloat16 g_Adl[(size_t)NN*NN];
static __device__ float g_dinv1[NN];
static __device__ float g_dinv2[NN];
static __device__ float g_cspart[8*NN];
static __device__ float g_X0[(size_t)NN*XW];
static __device__ float g_X1[(size_t)NN*XW];
static __device__ float g_X2[(size_t)NN*XW];
static __device__ __nv_bfloat16 g_XTh[(size_t)XW*NN];
static __device__ __nv_bfloat16 g_XTl[(size_t)XW*NN];
// P slots: 0=P0 1=P2x0 2=P1 3=P2m1 4=P4m1 5=P3 6=P4m3 7=P5m3 8=P6m3
//          9=Q2 10=Q4 11=Q5 12=Q6a 13=Q6
static __device__ float g_P[14*PSZ];
static __device__ float g_gc[(size_t)BB*NN*DD];
static __device__ float g_logits[BB*4];
static __device__ float g_wt[BB*4];

__device__ __forceinline__ float* bufAny(int s) {
    if (s == 0) return g_X0;
    if (s == 1) return g_X1;
    if (s == 2) return g_X2;
    return g_P + (size_t)(s - 10) * PSZ;
}

// ---------------- PTX helpers ----------------
__device__ __forceinline__ uint32_t smem_u32(const void* p) {
    uint32_t a;
    asm("{ .reg .u64 t; cvta.to.shared.u64 t, %1; cvt.u32.u64 %0, t; }" : "=r"(a) : "l"(p));
    return a;
}
__device__ __forceinline__ void cp16(uint32_t dst, const void* src) {
    asm volatile("cp.async.cg.shared.global [%0], [%1], 16;" :: "r"(dst), "l"(src) : "memory");
}
__device__ __forceinline__ void cp_commit() { asm volatile("cp.async.commit_group;" ::: "memory"); }
__device__ __forceinline__ void cp_wait2() { asm volatile("cp.async.wait_group 2;" ::: "memory"); }

__device__ __forceinline__ void ldm_x4(uint32_t* r, uint32_t addr) {
    asm volatile("ldmatrix.sync.aligned.m8n8.x4.shared.b16 {%0,%1,%2,%3}, [%4];"
                 : "=r"(r[0]), "=r"(r[1]), "=r"(r[2]), "=r"(r[3]) : "r"(addr));
}
__device__ __forceinline__ void mma16816(float* c, const uint32_t* a, uint32_t b0, uint32_t b1) {
    asm volatile(
        "mma.sync.aligned.m16n8k16.row.col.f32.bf16.bf16.f32 "
        "{%0,%1,%2,%3}, {%4,%5,%6,%7}, {%8,%9}, {%0,%1,%2,%3};"
        : "+f"(c[0]), "+f"(c[1]), "+f"(c[2]), "+f"(c[3])
        : "r"(a[0]), "r"(a[1]), "r"(a[2]), "r"(a[3]), "r"(b0), "r"(b1));
}

// ---------------- support construction ----------------
__global__ void rowsum_dinv_kernel(const float* __restrict__ g) {
    int row = blockIdx.x;
    int tid = threadIdx.x;
    float s = 0.f;
    for (int j = tid; j < NN; j += 256) s += g[(size_t)row*NN + j];
    for (int o = 16; o; o >>= 1) s += __shfl_down_sync(0xffffffffu, s, o);
    __shared__ float red[8];
    if ((tid & 31) == 0) red[tid >> 5] = s;
    __syncthreads();
    if (tid == 0) {
        float t = 0.f;
        #pragma unroll
        for (int w = 0; w < 8; w++) t += red[w];
        g_dinv1[row] = 1.f / (1.f + t);
    }
}

__global__ void colsum_part_kernel(const float* __restrict__ g) {
    int col = blockIdx.x * 256 + threadIdx.x;
    int r0 = blockIdx.y * 256;
    float s = 0.f;
    #pragma unroll 8
    for (int r = 0; r < 256; r++) s += g[(size_t)(r0 + r)*NN + col];
    g_cspart[blockIdx.y*NN + col] = s;
}

__global__ void colsum_fin_kernel() {
    int col = blockIdx.x * 256 + threadIdx.x;
    float s = 0.f;
    #pragma unroll
    for (int y = 0; y < 8; y++) s += g_cspart[y*NN + col];
    g_dinv2[col] = 1.f / (1.f + s);
}

__global__ void build_S1_kernel(const float* __restrict__ g) {
    __shared__ float t[32][33];
    int bi = blockIdx.x * 32;
    int bj = blockIdx.y * 32;
    for (int r = threadIdx.y; r < 32; r += 8)
        t[r][threadIdx.x] = g[(size_t)(bj + r)*NN + bi + threadIdx.x];
    __syncthreads();
    for (int r = threadIdx.y; r < 32; r += 8) {
        int i = bi + r, j = bj + threadIdx.x;
        float dv = g_dinv1[j];
        float v = t[threadIdx.x][r] * dv;
        if (i == j) v += dv;
        __nv_bfloat16 hh = __float2bfloat16(v);
        g_S1h[(size_t)i*NN + j] = hh;
        g_S1l[(size_t)i*NN + j] = __float2bfloat16(v - __bfloat162float(hh));
    }
}

__global__ void build_S2_kernel(const float* __restrict__ g) {
    int idx = blockIdx.x * 256 + threadIdx.x;
    int i = idx >> 11, j = idx & 2047;
    float v = (g[idx] + (i == j ? 1.f : 0.f)) * g_dinv2[j];
    __nv_bfloat16 hh = __float2bfloat16(v);
    g_S2h[idx] = hh;
    g_S2l[idx] = __float2bfloat16(v - __bfloat162float(hh));
}

__global__ void adp_kernel(const float* __restrict__ nv1, const float* __restrict__ nv2) {
    int i = blockIdx.x;
    int tid = threadIdx.x;
    __shared__ float v1[10];
    __shared__ float red[40];
    if (tid < 10) v1[tid] = nv1[i*10 + tid];
    __syncthreads();
    float p[8];
    float mx = 0.f;
    #pragma unroll
    for (int c = 0; c < 8; c++) {
        int j = tid + c*256;
        float s = 0.f;
        #pragma unroll
        for (int t = 0; t < 10; t++) s += v1[t] * nv2[t*NN + j];
        s = s > 0.f ? s : 0.f;
        p[c] = s;
        mx = fmaxf(mx, s);
    }
    for (int o = 16; o; o >>= 1) mx = fmaxf(mx, __shfl_xor_sync(0xffffffffu, mx, o));
    if ((tid & 31) == 0) red[tid >> 5] = mx;
    __syncthreads();
    if (tid == 0) {
        float m = red[0];
        #pragma unroll
        for (int w = 1; w < 8; w++) m = fmaxf(m, red[w]);
        red[32] = m;
    }
    __syncthreads();
    mx = red[32];
    float sum = 0.f;
    #pragma unroll
    for (int c = 0; c < 8; c++) { float e = expf(p[c] - mx); p[c] = e; sum += e; }
    for (int o = 16; o; o >>= 1) sum += __shfl_xor_sync(0xffffffffu, sum, o);
    if ((tid & 31) == 0) red[16 + (tid >> 5)] = sum;
    __syncthreads();
    if (tid == 0) {
        float t = 0.f;
        #pragma unroll
        for (int w = 0; w < 8; w++) t += red[16 + w];
        red[33] = 1.f / t;
    }
    __syncthreads();
    float inv = red[33];
    #pragma unroll
    for (int c = 0; c < 8; c++) {
        float v = p[c] * inv;
        __nv_bfloat16 hh = __float2bfloat16(v);
        size_t idx = (size_t)i*NN + tid + c*256;
        g_Adh[idx] = hh;
        g_Adl[idx] = __float2bfloat16(v - __bfloat162float(hh));
    }
}

// transpose + split: X fp32 [2048 x W] -> XT hi/lo bf16 [W x 2048]
__global__ void xt_convert_kernel(int selX, int W) {
    const float* X = bufAny(selX);
    __shared__ float t[32][33];
    int c0 = blockIdx.x * 32;
    int j0 = blockIdx.y * 32;
    int tx = threadIdx.x;
    for (int r = threadIdx.y; r < 32; r += 8)
        t[r][tx] = X[(size_t)(j0 + r)*W + c0 + tx];
    __syncthreads();
    for (int r = threadIdx.y; r < 32; r += 8) {
        int c = c0 + r;
        int j = j0 + tx;
        float v = t[tx][r];
        __nv_bfloat16 hh = __float2bfloat16(v);
        g_XTh[(size_t)c*NN + j] = hh;
        g_XTl[(size_t)c*NN + j] = __float2bfloat16(v - __bfloat162float(hh));
    }
}

// ---------------- x0 build ----------------
__global__ void build_x0_kernel(const float* __restrict__ inputs, const float* __restrict__ hx) {
    size_t total = (size_t)NN * XW;
    for (size_t idx = (size_t)blockIdx.x*256 + threadIdx.x; idx < total; idx += (size_t)gridDim.x*256) {
        int n = (int)(idx / XW);
        int c = (int)(idx - (size_t)n*XW);
        int i = c >> 6, b = c & 63;
        float v;
        if (i < 2) {
            v = inputs[(size_t)b*(NN*2) + n*2 + i];
        } else {
            int q = i - 2;
            int kk = (q < 64) ? 3 : 2;
            int d = q & 63;
            v = hx[(size_t)((b << 2) + kk)*NDD + (size_t)n*64 + d];
        }
        g_X0[idx] = v;
    }
}

// ---------------- projection: P[n, b*64+d] = sum_i X[n, i*64+b] * gw[(i*7+s)*64+d]
#define PROJ_SMEM (2*XW*4)    // sx + sw = 66560 B
__global__ void __launch_bounds__(256) proj_kernel(int selX, int s, int outSel,
                                                   const float* __restrict__ gw) {
    extern __shared__ float ps[];
    float* sx = ps;          // 8320
    float* sw = ps + XW;     // 8320 (130 x 64)
    const float* X = bufAny(selX);
    int n = blockIdx.x;
    int tid = threadIdx.x;
    for (int t = tid; t < XW/4; t += 256)
        ((float4*)sx)[t] = ((const float4*)(X + (size_t)n*XW))[t];
    for (int t = tid; t < ISZ*16; t += 256) {
        int i = t >> 4, dq = t & 15;
        ((float4*)sw)[i*16 + dq] = ((const float4*)gw)[((size_t)i*7 + s)*16 + dq];
    }
    __syncthreads();
    int tb = tid >> 4;        // b tile 0..15 (b0 = tb*4)
    int td = tid & 15;        // d tile 0..15 (d0 = td*4)
    float acc[4][4];
    #pragma unroll
    for (int bb = 0; bb < 4; bb++)
        #pragma unroll
        for (int dd = 0; dd < 4; dd++) acc[bb][dd] = 0.f;
    for (int i = 0; i < ISZ; i++) {
        float4 xa = ((const float4*)sx)[i*16 + tb];
        float4 wv = ((const float4*)sw)[i*16 + td];
        float xs[4] = {xa.x, xa.y, xa.z, xa.w};
        float ws[4] = {wv.x, wv.y, wv.z, wv.w};
        #pragma unroll
        for (int bb = 0; bb < 4; bb++)
            #pragma unroll
            for (int dd = 0; dd < 4; dd++) acc[bb][dd] += xs[bb] * ws[dd];
    }
    float* P = g_P + (size_t)(outSel - 10)*PSZ + (size_t)n*4096;
    #pragma unroll
    for (int bb = 0; bb < 4; bb++)
        *(float4*)&P[(size_t)(tb*4 + bb)*64 + td*4] =
            make_float4(acc[bb][0], acc[bb][1], acc[bb][2], acc[bb][3]);
}

// ---------------- bf16 split GEMM via mma.sync: C = A @ B ----------------
#define KC 32
#define TROW 80
#define TILEB (128*TROW)
#define STAGEB (4*TILEB)
#define GEMM_SMEM (4*STAGEB)    // 163840
#define NSTG 64

__global__ void __launch_bounds__(256, 1)
gemm_kernel(int selA, int selC, int W) {
    extern __shared__ char smem[];
    uint32_t sb = smem_u32(smem);
    int tid = threadIdx.x;
    int wid = tid >> 5;
    int lane = tid & 31;

    const __nv_bfloat16* Ah = selA == 0 ? g_S1h : (selA == 1 ? g_S2h : g_Adh);
    const __nv_bfloat16* Al = selA == 0 ? g_S1l : (selA == 1 ? g_S2l : g_Adl);
    float* C = bufAny(selC);

    int mBase = blockIdx.x * 128;
    int nBase = blockIdx.y * 128;

    const __nv_bfloat16* src[8];
    uint32_t dst[8];
    #pragma unroll
    for (int i = 0; i < 8; i++) {
        int c = tid + i*256;
        int tile = c >> 9;          // 0=Ah 1=Al 2=Bh 3=Bl
        int q = c & 511;
        int row = q >> 2, col = q & 3;
        dst[i] = (uint32_t)(tile*TILEB + row*TROW + col*16);
        const __nv_bfloat16* base;
        if (tile == 0)      base = Ah    + (size_t)(mBase + row) * NN;
        else if (tile == 1) base = Al    + (size_t)(mBase + row) * NN;
        else if (tile == 2) base = g_XTh + (size_t)(nBase + row) * NN;
        else                base = g_XTl + (size_t)(nBase + row) * NN;
        src[i] = base + col*8;
    }

    #pragma unroll
    for (int s = 0; s < 3; s++) {
        uint32_t so = sb + (uint32_t)(s * STAGEB);
        #pragma unroll
        for (int i = 0; i < 8; i++) cp16(so + dst[i], src[i] + s*KC);
        cp_commit();
    }

    float acc[4][4][4];
    #pragma unroll
    for (int mf = 0; mf < 4; mf++)
        #pragma unroll
        for (int nf = 0; nf < 4; nf++)
            #pragma unroll
            for (int e = 0; e < 4; e++) acc[mf][nf][e] = 0.f;

    int mw = wid & 1;
    int nw = wid >> 1;

    int a_row = lane & 15;
    int a_colb = (lane >> 4) * 16;
    int b_row = ((lane >> 4) & 1) * 8 + (lane & 7);
    int b_colb = ((lane >> 3) & 1) * 16;

    uint32_t aOffH = (uint32_t)((mw*64 + a_row) * TROW) + (uint32_t)a_colb;
    uint32_t aOffL = aOffH + (uint32_t)TILEB;
    uint32_t bOffH = (uint32_t)(2*TILEB) + (uint32_t)((nw*32 + b_row) * TROW) + (uint32_t)b_colb;
    uint32_t bOffL = bOffH + (uint32_t)TILEB;

    for (int s = 0; s < NSTG; s++) {
        cp_wait2();
        __syncthreads();
        int sn = s + 3;
        if (sn < NSTG) {
            uint32_t so2 = sb + (uint32_t)((sn & 3) * STAGEB);
            #pragma unroll
            for (int i = 0; i < 8; i++) cp16(so2 + dst[i], src[i] + sn*KC);
        }
        cp_commit();

        uint32_t so = sb + (uint32_t)((s & 3) * STAGEB);
        #pragma unroll
        for (int ks = 0; ks < 2; ks++) {
            uint32_t kb = (uint32_t)(ks*32);
            uint32_t arh[4][4], arl[4][4], brh[2][4], brl[2][4];
            #pragma unroll
            for (int mf = 0; mf < 4; mf++) {
                ldm_x4(arh[mf], so + aOffH + (uint32_t)(mf*16*TROW) + kb);
                ldm_x4(arl[mf], so + aOffL + (uint32_t)(mf*16*TROW) + kb);
            }
            #pragma unroll
            for (int bg = 0; bg < 2; bg++) {
                ldm_x4(brh[bg], so + bOffH + (uint32_t)(bg*16*TROW) + kb);
                ldm_x4(brl[bg], so + bOffL + (uint32_t)(bg*16*TROW) + kb);
            }
            #pragma unroll
            for (int mf = 0; mf < 4; mf++) {
                #pragma unroll
                for (int bg = 0; bg < 2; bg++) {
                    float* a0 = acc[mf][bg*2+0];
                    float* a1 = acc[mf][bg*2+1];
                    mma16816(a0, arh[mf], brh[bg][0], brh[bg][1]);
                    mma16816(a1, arh[mf], brh[bg][2], brh[bg][3]);
                    mma16816(a0, arh[mf], brl[bg][0], brl[bg][1]);
                    mma16816(a1, arh[mf], brl[bg][2], brl[bg][3]);
                    mma16816(a0, arl[mf], brh[bg][0], brh[bg][1]);
                    mma16816(a1, arl[mf], brh[bg][2], brh[bg][3]);
                }
            }
        }
    }

    int gid = lane >> 2, tg = lane & 3;
    #pragma unroll
    for (int mf = 0; mf < 4; mf++) {
        int row0 = mBase + mw*64 + mf*16 + gid;
        #pragma unroll
        for (int nf = 0; nf < 4; nf++) {
            int col = nBase + nw*32 + nf*8 + tg*2;
            size_t i0 = (size_t)row0 * W + col;
            size_t i1 = i0 + (size_t)8 * W;
            *(float2*)&C[i0] = make_float2(acc[mf][nf][0], acc[mf][nf][1]);
            *(float2*)&C[i1] = make_float2(acc[mf][nf][2], acc[mf][nf][3]);
        }
    }
}

// ---------------- combine: gc = gb + P0 + P1 + 2Q2 - P2x0 + P3 + 2Q4 - P4m1 + Q5 + Q6 - P6m3
__global__ void combine_kernel(const float* __restrict__ gb) {
    size_t idx = (size_t)blockIdx.x*256 + threadIdx.x;
    int d = (int)(idx & 63);
    size_t r = idx >> 6;
    int n = (int)(r & 2047);
    int b = (int)(r >> 11);
    size_t p = (size_t)n*4096 + (size_t)(b*64 + d);
    float v = gb[d]
            + g_P[0*PSZ + p]
            + g_P[2*PSZ + p]
            + 2.f*g_P[9*PSZ + p]
            - g_P[1*PSZ + p]
            + g_P[5*PSZ + p]
            + 2.f*g_P[10*PSZ + p]
            - g_P[4*PSZ + p]
            + g_P[11*PSZ + p]
            + g_P[13*PSZ + p]
            - g_P[8*PSZ + p];
    g_gc[idx] = v;
}

// ---------------- attention ----------------
__global__ void logits_kernel(const float* __restrict__ hx, const float* __restrict__ R,
                              const float* __restrict__ aw, const float* __restrict__ ab) {
    int bk = blockIdx.x;
    int k = bk & 3;
    int tid = threadIdx.x;
    const float* hp = hx + (size_t)bk * NDD;
    const float* rp = R + (size_t)k * NDD;
    float s = 0.f;
    for (int t = tid; t < NDD; t += 256) s += (hp[t] + rp[t]) * aw[t];
    for (int o = 16; o; o >>= 1) s += __shfl_down_sync(0xffffffffu, s, o);
    __shared__ float red[8];
    if ((tid & 31) == 0) red[tid >> 5] = s;
    __syncthreads();
    if (tid == 0) {
        float t = 0.f;
        #pragma unroll
        for (int w = 0; w < 8; w++) t += red[w];
        g_logits[bk] = t + ab[0];
    }
}

__global__ void weight_kernel() {
    int b = threadIdx.x;
    if (b < BB) {
        float l0 = g_logits[b*4+0], l1 = g_logits[b*4+1], l2 = g_logits[b*4+2], l3 = g_logits[b*4+3];
        float m = fmaxf(fmaxf(l0, l1), fmaxf(l2, l3));
        float e0 = expf(l0 - m), e1 = expf(l1 - m), e2 = expf(l2 - m), e3 = expf(l3 - m);
        float inv = 1.f / (e0 + e1 + e2 + e3);
        g_wt[b*4+0] = e0 * inv; g_wt[b*4+1] = e1 * inv;
        g_wt[b*4+2] = e2 * inv; g_wt[b*4+3] = e3 * inv;
    }
}

// ---------------- output ----------------
__global__ void __launch_bounds__(256) final_kernel(const float* __restrict__ W,
                                                    const float* __restrict__ bbias,
                                                    const float* __restrict__ hx,
                                                    const float* __restrict__ R,
                                                    float* __restrict__ out, int write_hx) {
    __shared__ float sW[64*64];
    __shared__ float sg[4*64];
    int tid = threadIdx.x;
    int r0 = blockIdx.x * 4;
    for (int t = tid; t < 4096; t += 256) sW[t] = W[t];
    {
        float v = g_gc[(size_t)r0*64 + tid];
        sg[tid] = v > 0.f ? v : 0.01f * v;
    }
    __syncthreads();
    int rl = tid >> 6;
    int d = tid & 63;
    int r = r0 + rl;
    int b = r >> 11;
    int n = r & 2047;
    float acc = 0.f;
    #pragma unroll
    for (int e = 0; e < 64; e++) acc += sg[rl*64 + e] * sW[e*64 + d];
    float att = 0.f;
    #pragma unroll
    for (int k = 0; k < 4; k++) {
        float xv = hx[(size_t)((b << 2) + k)*NDD + (size_t)n*64 + d] + R[(size_t)k*NDD + (size_t)n*64 + d];
        att += xv * g_wt[b*4 + k];
    }
    float o = acc + bbias[(size_t)n*64 + d] + att;
    out[(size_t)b*NDD + (size_t)n*64 + d] = o;
    if (write_hx)
        out[(size_t)OUT1 + (size_t)((b << 2) + 3)*NDD + (size_t)n*64 + d] = o;
}

__global__ void hxcopy_kernel(const float* __restrict__ hx, float* __restrict__ out) {
    size_t idx = (size_t)blockIdx.x * 256 + threadIdx.x;
    int b = (int)(idx / (3*(size_t)NDD));
    size_t rem = idx - (size_t)b * (3*(size_t)NDD);
    int kk = (int)(rem / NDD);
    size_t j = rem - (size_t)kk * NDD;
    out[(size_t)OUT1 + (size_t)(b*4 + kk)*NDD + j] = hx[(size_t)(b*4 + kk + 1)*NDD + j];
}

// ---------------- launch ----------------
extern "C" void kernel_launch(void* const* d_in, const int* in_sizes, int n_in,
                              void* d_out, int out_size) {
    const float* inputs = (const float*)d_in[0];
    const float* hx     = (const float*)d_in[1];
    const float* graph  = (const float*)d_in[2];
    const float* nv1    = (const float*)d_in[3];
    const float* nv2    = (const float*)d_in[4];
    const float* W      = (const float*)d_in[5];
    const float* bbias  = (const float*)d_in[6];
    const float* R      = (const float*)d_in[7];
    const float* gw     = (const float*)d_in[8];
    const float* gb     = (const float*)d_in[9];
    const float* aw     = (const float*)d_in[10];
    const float* ab     = (const float*)d_in[11];
    float* out = (float*)d_out;

    int write_hx = ((size_t)out_size >= FULL_OUT) ? 1 : 0;

    cudaFuncSetAttribute(gemm_kernel, cudaFuncAttributeMaxDynamicSharedMemorySize, GEMM_SMEM);
    cudaFuncSetAttribute(proj_kernel, cudaFuncAttributeMaxDynamicSharedMemorySize, PROJ_SMEM);

    // supports + adaptive adjacency (bf16 hi/lo written directly)
    rowsum_dinv_kernel<<<NN, 256>>>(graph);
    colsum_part_kernel<<<dim3(NN/256, 8), 256>>>(graph);
    colsum_fin_kernel<<<NN/256, 256>>>();
    build_S1_kernel<<<dim3(64, 64), dim3(32, 8)>>>(graph);
    build_S2_kernel<<<(NN*NN)/256, 256>>>(graph);
    adp_kernel<<<NN, 256>>>(nv1, nv2);

    build_x0_kernel<<<66560, 256>>>(inputs, hx);

    dim3 gfull(NN/128, XW/128);           // (16, 65)
    dim3 gproj(NN/128, 4096/128);         // (16, 32)
    dim3 xfull(XW/32, NN/32);
    dim3 xhalf(4096/32, NN/32);
    dim3 xblk(32, 8);

    // projections of x0
    proj_kernel<<<NN, 256, PROJ_SMEM>>>(0, 0, 10, gw);   // P0
    proj_kernel<<<NN, 256, PROJ_SMEM>>>(0, 2, 11, gw);   // P2x0

    // m1 = S1 @ x0 -> X1
    xt_convert_kernel<<<xfull, xblk>>>(0, XW);
    gemm_kernel<<<gfull, 256, GEMM_SMEM>>>(0, 1, XW);

    proj_kernel<<<NN, 256, PROJ_SMEM>>>(1, 1, 12, gw);   // P1
    proj_kernel<<<NN, 256, PROJ_SMEM>>>(1, 2, 13, gw);   // P2m1
    proj_kernel<<<NN, 256, PROJ_SMEM>>>(1, 4, 14, gw);   // P4m1

    // Q2 = S1 @ P2m1
    xt_convert_kernel<<<xhalf, xblk>>>(13, 4096);
    gemm_kernel<<<gproj, 256, GEMM_SMEM>>>(0, 19, 4096);

    // m3 = S2 @ m1 -> X2
    xt_convert_kernel<<<xfull, xblk>>>(1, XW);
    gemm_kernel<<<gfull, 256, GEMM_SMEM>>>(1, 2, XW);

    proj_kernel<<<NN, 256, PROJ_SMEM>>>(2, 3, 15, gw);   // P3
    proj_kernel<<<NN, 256, PROJ_SMEM>>>(2, 4, 16, gw);   // P4m3
    proj_kernel<<<NN, 256, PROJ_SMEM>>>(2, 5, 17, gw);   // P5m3
    proj_kernel<<<NN, 256, PROJ_SMEM>>>(2, 6, 18, gw);   // P6m3

    // Q4 = S2 @ P4m3
    xt_convert_kernel<<<xhalf, xblk>>>(16, 4096);
    gemm_kernel<<<gproj, 256, GEMM_SMEM>>>(1, 20, 4096);
    // Q5 = A @ P5m3
    xt_convert_kernel<<<xhalf, xblk>>>(17, 4096);
    gemm_kernel<<<gproj, 256, GEMM_SMEM>>>(2, 21, 4096);
    // Q6a = A @ P6m3
    xt_convert_kernel<<<xhalf, xblk>>>(18, 4096);
    gemm_kernel<<<gproj, 256, GEMM_SMEM>>>(2, 22, 4096);
    // Q6 = A @ Q6a
    xt_convert_kernel<<<xhalf, xblk>>>(22, 4096);
    gemm_kernel<<<gproj, 256, GEMM_SMEM>>>(2, 23, 4096);

    // assemble gc
    combine_kernel<<<(unsigned)(OUT1/256), 256>>>(gb);

    // attention
    logits_kernel<<<BB*4, 256>>>(hx, R, aw, ab);
    weight_kernel<<<1, 64>>>();

    final_kernel<<<(BB*NN)/4, 256>>>(W, bbias, hx, R, out, write_hx);
    if (write_hx)
        hxcopy_kernel<<<(unsigned)((size_t)BB*3*NDD/256), 256>>>(hx, out);
}

// round 6
// speedup vs baseline: 3.3699x; 1.2147x over previous
#include <cuda_runtime.h>
#include <cuda_bf16.h>
#include <cuda_fp16.h>
#include <math.h>
#include <stdint.h>

#define NN 2048
#define BB 64
#define DD 64
#define ISZ 130
#define XW (ISZ*BB)          // 8320
#define NDD (NN*DD)          // 131072
#define OUT1 (BB*NDD)        // 8388608
#define HXPART ((size_t)BB*4*NDD)
#define FULL_OUT ((size_t)OUT1 + HXPART)
#define PSZ ((size_t)2048*4096)

// ---------------- scratch ----------------
static __device__ __nv_bfloat16 g_S1h[(size_t)NN*NN];
static __device__ __nv_bfloat16 g_S1l[(size_t)NN*NN];
static __device__ __nv_bfloat16 g_S2h[(size_t)NN*NN];
static __device__ __nv_bfloat16 g_S2l[(size_t)NN*NN];
static __device__ __half g_S1f[(size_t)NN*NN];
static __device__ __half g_S2f[(size_t)NN*NN];
static __device__ __half g_Adf[(size_t)NN*NN];
static __device__ __half g_A2f[(size_t)NN*NN];
static __device__ float g_Ad[(size_t)NN*NN];
static __device__ float g_dinv1[NN];
static __device__ float g_dinv2[NN];
static __device__ float g_cspart[8*NN];
static __device__ float g_X0[(size_t)NN*XW];
static __device__ float g_X1[(size_t)NN*XW];
static __device__ float g_X2[(size_t)NN*XW];
static __device__ __nv_bfloat16 g_XTh[(size_t)XW*NN];
static __device__ __nv_bfloat16 g_XTl[(size_t)XW*NN];
static __device__ __half g_YTh[(size_t)4096*NN];
static __device__ __half g_YTl[(size_t)4096*NN];
// P slots 10..23: 10=P0 11=P2x0 12=P1 13=P2m1 14=P4m1 15=P3 16=P4m3 17=P5m3
//                 18=P6m3 19=Q2 20=Q4 21=Q5 22=A2(fp32) 23=Q6
static __device__ float g_P[14*PSZ];
static __device__ float g_gc[(size_t)BB*NN*DD];
static __device__ float g_logits[BB*4];
static __device__ float g_wt[BB*4];

__device__ __forceinline__ float* bufAny(int s) {
    if (s == 0) return g_X0;
    if (s == 1) return g_X1;
    if (s == 2) return g_X2;
    if (s == 3) return g_Ad;
    return g_P + (size_t)(s - 10) * PSZ;
}

// ---------------- PTX helpers ----------------
__device__ __forceinline__ uint32_t smem_u32(const void* p) {
    uint32_t a;
    asm("{ .reg .u64 t; cvta.to.shared.u64 t, %1; cvt.u32.u64 %0, t; }" : "=r"(a) : "l"(p));
    return a;
}
__device__ __forceinline__ void cp16(uint32_t dst, const void* src) {
    asm volatile("cp.async.cg.shared.global [%0], [%1], 16;" :: "r"(dst), "l"(src) : "memory");
}
__device__ __forceinline__ void cp_commit() { asm volatile("cp.async.commit_group;" ::: "memory"); }
__device__ __forceinline__ void cp_wait2() { asm volatile("cp.async.wait_group 2;" ::: "memory"); }

__device__ __forceinline__ void ldm_x4(uint32_t* r, uint32_t addr) {
    asm volatile("ldmatrix.sync.aligned.m8n8.x4.shared.b16 {%0,%1,%2,%3}, [%4];"
                 : "=r"(r[0]), "=r"(r[1]), "=r"(r[2]), "=r"(r[3]) : "r"(addr));
}
__device__ __forceinline__ void mma16816(float* c, const uint32_t* a, uint32_t b0, uint32_t b1) {
    asm volatile(
        "mma.sync.aligned.m16n8k16.row.col.f32.bf16.bf16.f32 "
        "{%0,%1,%2,%3}, {%4,%5,%6,%7}, {%8,%9}, {%0,%1,%2,%3};"
        : "+f"(c[0]), "+f"(c[1]), "+f"(c[2]), "+f"(c[3])
        : "r"(a[0]), "r"(a[1]), "r"(a[2]), "r"(a[3]), "r"(b0), "r"(b1));
}
__device__ __forceinline__ void mma16816h(float* c, const uint32_t* a, uint32_t b0, uint32_t b1) {
    asm volatile(
        "mma.sync.aligned.m16n8k16.row.col.f32.f16.f16.f32 "
        "{%0,%1,%2,%3}, {%4,%5,%6,%7}, {%8,%9}, {%0,%1,%2,%3};"
        : "+f"(c[0]), "+f"(c[1]), "+f"(c[2]), "+f"(c[3])
        : "r"(a[0]), "r"(a[1]), "r"(a[2]), "r"(a[3]), "r"(b0), "r"(b1));
}

// ---------------- support construction ----------------
__global__ void rowsum_dinv_kernel(const float* __restrict__ g) {
    int row = blockIdx.x;
    int tid = threadIdx.x;
    float s = 0.f;
    for (int j = tid; j < NN; j += 256) s += g[(size_t)row*NN + j];
    for (int o = 16; o; o >>= 1) s += __shfl_down_sync(0xffffffffu, s, o);
    __shared__ float red[8];
    if ((tid & 31) == 0) red[tid >> 5] = s;
    __syncthreads();
    if (tid == 0) {
        float t = 0.f;
        #pragma unroll
        for (int w = 0; w < 8; w++) t += red[w];
        g_dinv1[row] = 1.f / (1.f + t);
    }
}

__global__ void colsum_part_kernel(const float* __restrict__ g) {
    int col = blockIdx.x * 256 + threadIdx.x;
    int r0 = blockIdx.y * 256;
    float s = 0.f;
    #pragma unroll 8
    for (int r = 0; r < 256; r++) s += g[(size_t)(r0 + r)*NN + col];
    g_cspart[blockIdx.y*NN + col] = s;
}

__global__ void colsum_fin_kernel() {
    int col = blockIdx.x * 256 + threadIdx.x;
    float s = 0.f;
    #pragma unroll
    for (int y = 0; y < 8; y++) s += g_cspart[y*NN + col];
    g_dinv2[col] = 1.f / (1.f + s);
}

__global__ void build_S1_kernel(const float* __restrict__ g) {
    __shared__ float t[32][33];
    int bi = blockIdx.x * 32;
    int bj = blockIdx.y * 32;
    for (int r = threadIdx.y; r < 32; r += 8)
        t[r][threadIdx.x] = g[(size_t)(bj + r)*NN + bi + threadIdx.x];
    __syncthreads();
    for (int r = threadIdx.y; r < 32; r += 8) {
        int i = bi + r, j = bj + threadIdx.x;
        float dv = g_dinv1[j];
        float v = t[threadIdx.x][r] * dv;
        if (i == j) v += dv;
        size_t idx = (size_t)i*NN + j;
        __nv_bfloat16 hh = __float2bfloat16(v);
        g_S1h[idx] = hh;
        g_S1l[idx] = __float2bfloat16(v - __bfloat162float(hh));
        g_S1f[idx] = __float2half(v);
    }
}

__global__ void build_S2_kernel(const float* __restrict__ g) {
    int idx = blockIdx.x * 256 + threadIdx.x;
    int i = idx >> 11, j = idx & 2047;
    float v = (g[idx] + (i == j ? 1.f : 0.f)) * g_dinv2[j];
    __nv_bfloat16 hh = __float2bfloat16(v);
    g_S2h[idx] = hh;
    g_S2l[idx] = __float2bfloat16(v - __bfloat162float(hh));
    g_S2f[idx] = __float2half(v);
}

__global__ void adp_kernel(const float* __restrict__ nv1, const float* __restrict__ nv2) {
    int i = blockIdx.x;
    int tid = threadIdx.x;
    __shared__ float v1[10];
    __shared__ float red[40];
    if (tid < 10) v1[tid] = nv1[i*10 + tid];
    __syncthreads();
    float p[8];
    float mx = 0.f;
    #pragma unroll
    for (int c = 0; c < 8; c++) {
        int j = tid + c*256;
        float s = 0.f;
        #pragma unroll
        for (int t = 0; t < 10; t++) s += v1[t] * nv2[t*NN + j];
        s = s > 0.f ? s : 0.f;
        p[c] = s;
        mx = fmaxf(mx, s);
    }
    for (int o = 16; o; o >>= 1) mx = fmaxf(mx, __shfl_xor_sync(0xffffffffu, mx, o));
    if ((tid & 31) == 0) red[tid >> 5] = mx;
    __syncthreads();
    if (tid == 0) {
        float m = red[0];
        #pragma unroll
        for (int w = 1; w < 8; w++) m = fmaxf(m, red[w]);
        red[32] = m;
    }
    __syncthreads();
    mx = red[32];
    float sum = 0.f;
    #pragma unroll
    for (int c = 0; c < 8; c++) { float e = expf(p[c] - mx); p[c] = e; sum += e; }
    for (int o = 16; o; o >>= 1) sum += __shfl_xor_sync(0xffffffffu, sum, o);
    if ((tid & 31) == 0) red[16 + (tid >> 5)] = sum;
    __syncthreads();
    if (tid == 0) {
        float t = 0.f;
        #pragma unroll
        for (int w = 0; w < 8; w++) t += red[16 + w];
        red[33] = 1.f / t;
    }
    __syncthreads();
    float inv = red[33];
    #pragma unroll
    for (int c = 0; c < 8; c++) {
        float v = p[c] * inv;
        size_t idx = (size_t)i*NN + tid + c*256;
        g_Ad[idx] = v;
        g_Adf[idx] = __float2half(v);
    }
}

// transpose + split bf16: X fp32 [2048 x W] -> XT hi/lo bf16 [W x 2048]
__global__ void xt_convert_kernel(int selX, int W) {
    const float* X = bufAny(selX);
    __shared__ float t[32][33];
    int c0 = blockIdx.x * 32;
    int j0 = blockIdx.y * 32;
    int tx = threadIdx.x;
    for (int r = threadIdx.y; r < 32; r += 8)
        t[r][tx] = X[(size_t)(j0 + r)*W + c0 + tx];
    __syncthreads();
    for (int r = threadIdx.y; r < 32; r += 8) {
        int c = c0 + r;
        int j = j0 + tx;
        float v = t[tx][r];
        __nv_bfloat16 hh = __float2bfloat16(v);
        g_XTh[(size_t)c*NN + j] = hh;
        g_XTl[(size_t)c*NN + j] = __float2bfloat16(v - __bfloat162float(hh));
    }
}

// transpose + split fp16: X fp32 [2048 x W] -> YT hi/lo half [W x 2048]
__global__ void xt_f16_kernel(int selX, int W) {
    const float* X = bufAny(selX);
    __shared__ float t[32][33];
    int c0 = blockIdx.x * 32;
    int j0 = blockIdx.y * 32;
    int tx = threadIdx.x;
    for (int r = threadIdx.y; r < 32; r += 8)
        t[r][tx] = X[(size_t)(j0 + r)*W + c0 + tx];
    __syncthreads();
    for (int r = threadIdx.y; r < 32; r += 8) {
        int c = c0 + r;
        int j = j0 + tx;
        float v = t[tx][r];
        __half hh = __float2half(v);
        g_YTh[(size_t)c*NN + j] = hh;
        g_YTl[(size_t)c*NN + j] = __float2half(v - __half2float(hh));
    }
}

__global__ void a2f_kernel() {
    size_t idx = (size_t)blockIdx.x*256 + threadIdx.x;
    g_A2f[idx] = __float2half(g_P[12*PSZ + idx]);   // slot 22
}

// ---------------- x0 build ----------------
__global__ void build_x0_kernel(const float* __restrict__ inputs, const float* __restrict__ hx) {
    size_t total = (size_t)NN * XW;
    for (size_t idx = (size_t)blockIdx.x*256 + threadIdx.x; idx < total; idx += (size_t)gridDim.x*256) {
        int n = (int)(idx / XW);
        int c = (int)(idx - (size_t)n*XW);
        int i = c >> 6, b = c & 63;
        float v;
        if (i < 2) {
            v = inputs[(size_t)b*(NN*2) + n*2 + i];
        } else {
            int q = i - 2;
            int kk = (q < 64) ? 3 : 2;
            int d = q & 63;
            v = hx[(size_t)((b << 2) + kk)*NDD + (size_t)n*64 + d];
        }
        g_X0[idx] = v;
    }
}

// ---------------- multi-slice projection ----------------
// For each slice s: P[n, b*64+d] = sum_i X[n, i*64+b] * gw[(i*7+s)*64+d]
#define PROJ_SMEM (2*XW*4)    // 66560
__global__ void __launch_bounds__(256) proj_multi_kernel(int selX, int cnt, int4 sl,
                                                         int outFirst,
                                                         const float* __restrict__ gw) {
    extern __shared__ float ps[];
    float* sx = ps;          // 8320
    float* sw = ps + XW;     // 8320
    const float* X = bufAny(selX);
    int n = blockIdx.x;
    int tid = threadIdx.x;
    for (int t = tid; t < XW/4; t += 256)
        ((float4*)sx)[t] = ((const float4*)(X + (size_t)n*XW))[t];
    int ss[4] = {sl.x, sl.y, sl.z, sl.w};
    int tb = tid >> 4;
    int td = tid & 15;
    for (int q = 0; q < cnt; q++) {
        int s = ss[q];
        __syncthreads();   // previous compute done (and first iter: sx visible after next sync)
        for (int t = tid; t < ISZ*16; t += 256) {
            int i = t >> 4, dq = t & 15;
            ((float4*)sw)[i*16 + dq] = ((const float4*)gw)[((size_t)i*7 + s)*16 + dq];
        }
        __syncthreads();
        float acc[4][4];
        #pragma unroll
        for (int bb = 0; bb < 4; bb++)
            #pragma unroll
            for (int dd = 0; dd < 4; dd++) acc[bb][dd] = 0.f;
        for (int i = 0; i < ISZ; i++) {
            float4 xa = ((const float4*)sx)[i*16 + tb];
            float4 wv = ((const float4*)sw)[i*16 + td];
            float xs[4] = {xa.x, xa.y, xa.z, xa.w};
            float ws[4] = {wv.x, wv.y, wv.z, wv.w};
            #pragma unroll
            for (int bb = 0; bb < 4; bb++)
                #pragma unroll
                for (int dd = 0; dd < 4; dd++) acc[bb][dd] += xs[bb] * ws[dd];
        }
        float* P = g_P + (size_t)(outFirst + q - 10)*PSZ + (size_t)n*4096;
        #pragma unroll
        for (int bb = 0; bb < 4; bb++)
            *(float4*)&P[(size_t)(tb*4 + bb)*64 + td*4] =
                make_float4(acc[bb][0], acc[bb][1], acc[bb][2], acc[bb][3]);
    }
}

// ---------------- bf16 3-product GEMM (m-chain) ----------------
#define KC 32
#define TROW 80
#define TILEB (128*TROW)
#define STAGEB (4*TILEB)
#define GEMM_SMEM (4*STAGEB)    // 163840
#define NSTG 64

__global__ void __launch_bounds__(256, 1)
gemm_kernel(int selA, int selC, int W) {
    extern __shared__ char smem[];
    uint32_t sb = smem_u32(smem);
    int tid = threadIdx.x;
    int wid = tid >> 5;
    int lane = tid & 31;

    const __nv_bfloat16* Ah = selA == 0 ? g_S1h : g_S2h;
    const __nv_bfloat16* Al = selA == 0 ? g_S1l : g_S2l;
    float* C = bufAny(selC);

    int mBase = blockIdx.x * 128;
    int nBase = blockIdx.y * 128;

    const __nv_bfloat16* src[8];
    uint32_t dst[8];
    #pragma unroll
    for (int i = 0; i < 8; i++) {
        int c = tid + i*256;
        int tile = c >> 9;
        int q = c & 511;
        int row = q >> 2, col = q & 3;
        dst[i] = (uint32_t)(tile*TILEB + row*TROW + col*16);
        const __nv_bfloat16* base;
        if (tile == 0)      base = Ah    + (size_t)(mBase + row) * NN;
        else if (tile == 1) base = Al    + (size_t)(mBase + row) * NN;
        else if (tile == 2) base = g_XTh + (size_t)(nBase + row) * NN;
        else                base = g_XTl + (size_t)(nBase + row) * NN;
        src[i] = base + col*8;
    }

    #pragma unroll
    for (int s = 0; s < 3; s++) {
        uint32_t so = sb + (uint32_t)(s * STAGEB);
        #pragma unroll
        for (int i = 0; i < 8; i++) cp16(so + dst[i], src[i] + s*KC);
        cp_commit();
    }

    float acc[4][4][4];
    #pragma unroll
    for (int mf = 0; mf < 4; mf++)
        #pragma unroll
        for (int nf = 0; nf < 4; nf++)
            #pragma unroll
            for (int e = 0; e < 4; e++) acc[mf][nf][e] = 0.f;

    int mw = wid & 1;
    int nw = wid >> 1;
    int a_row = lane & 15;
    int a_colb = (lane >> 4) * 16;
    int b_row = ((lane >> 4) & 1) * 8 + (lane & 7);
    int b_colb = ((lane >> 3) & 1) * 16;

    uint32_t aOffH = (uint32_t)((mw*64 + a_row) * TROW) + (uint32_t)a_colb;
    uint32_t aOffL = aOffH + (uint32_t)TILEB;
    uint32_t bOffH = (uint32_t)(2*TILEB) + (uint32_t)((nw*32 + b_row) * TROW) + (uint32_t)b_colb;
    uint32_t bOffL = bOffH + (uint32_t)TILEB;

    for (int s = 0; s < NSTG; s++) {
        cp_wait2();
        __syncthreads();
        int sn = s + 3;
        if (sn < NSTG) {
            uint32_t so2 = sb + (uint32_t)((sn & 3) * STAGEB);
            #pragma unroll
            for (int i = 0; i < 8; i++) cp16(so2 + dst[i], src[i] + sn*KC);
        }
        cp_commit();

        uint32_t so = sb + (uint32_t)((s & 3) * STAGEB);
        #pragma unroll
        for (int ks = 0; ks < 2; ks++) {
            uint32_t kb = (uint32_t)(ks*32);
            uint32_t arh[4][4], arl[4][4], brh[2][4], brl[2][4];
            #pragma unroll
            for (int mf = 0; mf < 4; mf++) {
                ldm_x4(arh[mf], so + aOffH + (uint32_t)(mf*16*TROW) + kb);
                ldm_x4(arl[mf], so + aOffL + (uint32_t)(mf*16*TROW) + kb);
            }
            #pragma unroll
            for (int bg = 0; bg < 2; bg++) {
                ldm_x4(brh[bg], so + bOffH + (uint32_t)(bg*16*TROW) + kb);
                ldm_x4(brl[bg], so + bOffL + (uint32_t)(bg*16*TROW) + kb);
            }
            #pragma unroll
            for (int mf = 0; mf < 4; mf++) {
                #pragma unroll
                for (int bg = 0; bg < 2; bg++) {
                    float* a0 = acc[mf][bg*2+0];
                    float* a1 = acc[mf][bg*2+1];
                    mma16816(a0, arh[mf], brh[bg][0], brh[bg][1]);
                    mma16816(a1, arh[mf], brh[bg][2], brh[bg][3]);
                    mma16816(a0, arh[mf], brl[bg][0], brl[bg][1]);
                    mma16816(a1, arh[mf], brl[bg][2], brl[bg][3]);
                    mma16816(a0, arl[mf], brh[bg][0], brh[bg][1]);
                    mma16816(a1, arl[mf], brh[bg][2], brh[bg][3]);
                }
            }
        }
    }

    int gid = lane >> 2, tg = lane & 3;
    #pragma unroll
    for (int mf = 0; mf < 4; mf++) {
        int row0 = mBase + mw*64 + mf*16 + gid;
        #pragma unroll
        for (int nf = 0; nf < 4; nf++) {
            int col = nBase + nw*32 + nf*8 + tg*2;
            size_t i0 = (size_t)row0 * W + col;
            size_t i1 = i0 + (size_t)8 * W;
            *(float2*)&C[i0] = make_float2(acc[mf][nf][0], acc[mf][nf][1]);
            *(float2*)&C[i1] = make_float2(acc[mf][nf][2], acc[mf][nf][3]);
        }
    }
}

// ---------------- fp16 2-product GEMM (leaf Q-gemms) ----------------
#define TILEB2 TILEB
#define STAGEB2 (3*TILEB2)      // 30720
#define GEMM2_SMEM (4*STAGEB2)  // 122880

__global__ void __launch_bounds__(256, 1)
gemm2_kernel(int selA, int selC, int W) {
    extern __shared__ char smem[];
    uint32_t sb = smem_u32(smem);
    int tid = threadIdx.x;
    int wid = tid >> 5;
    int lane = tid & 31;

    const __half* Af = selA == 0 ? g_S1f : (selA == 1 ? g_S2f : (selA == 2 ? g_Adf : g_A2f));
    float* C = bufAny(selC);

    int mBase = blockIdx.x * 128;
    int nBase = blockIdx.y * 128;

    const __half* src[6];
    uint32_t dst[6];
    #pragma unroll
    for (int i = 0; i < 6; i++) {
        int c = tid + i*256;
        int tile = c >> 9;          // 0=A 1=Bh 2=Bl
        int q = c & 511;
        int row = q >> 2, col = q & 3;
        dst[i] = (uint32_t)(tile*TILEB2 + row*TROW + col*16);
        const __half* base;
        if (tile == 0)      base = Af    + (size_t)(mBase + row) * NN;
        else if (tile == 1) base = g_YTh + (size_t)(nBase + row) * NN;
        else                base = g_YTl + (size_t)(nBase + row) * NN;
        src[i] = base + col*8;
    }

    #pragma unroll
    for (int s = 0; s < 3; s++) {
        uint32_t so = sb + (uint32_t)(s * STAGEB2);
        #pragma unroll
        for (int i = 0; i < 6; i++) cp16(so + dst[i], src[i] + s*KC);
        cp_commit();
    }

    float acc[4][4][4];
    #pragma unroll
    for (int mf = 0; mf < 4; mf++)
        #pragma unroll
        for (int nf = 0; nf < 4; nf++)
            #pragma unroll
            for (int e = 0; e < 4; e++) acc[mf][nf][e] = 0.f;

    int mw = wid & 1;
    int nw = wid >> 1;
    int a_row = lane & 15;
    int a_colb = (lane >> 4) * 16;
    int b_row = ((lane >> 4) & 1) * 8 + (lane & 7);
    int b_colb = ((lane >> 3) & 1) * 16;

    uint32_t aOff  = (uint32_t)((mw*64 + a_row) * TROW) + (uint32_t)a_colb;
    uint32_t bOffH = (uint32_t)(1*TILEB2) + (uint32_t)((nw*32 + b_row) * TROW) + (uint32_t)b_colb;
    uint32_t bOffL = bOffH + (uint32_t)TILEB2;

    for (int s = 0; s < NSTG; s++) {
        cp_wait2();
        __syncthreads();
        int sn = s + 3;
        if (sn < NSTG) {
            uint32_t so2 = sb + (uint32_t)((sn & 3) * STAGEB2);
            #pragma unroll
            for (int i = 0; i < 6; i++) cp16(so2 + dst[i], src[i] + sn*KC);
        }
        cp_commit();

        uint32_t so = sb + (uint32_t)((s & 3) * STAGEB2);
        #pragma unroll
        for (int ks = 0; ks < 2; ks++) {
            uint32_t kb = (uint32_t)(ks*32);
            uint32_t ar[4][4], brh[2][4], brl[2][4];
            #pragma unroll
            for (int mf = 0; mf < 4; mf++)
                ldm_x4(ar[mf], so + aOff + (uint32_t)(mf*16*TROW) + kb);
            #pragma unroll
            for (int bg = 0; bg < 2; bg++) {
                ldm_x4(brh[bg], so + bOffH + (uint32_t)(bg*16*TROW) + kb);
                ldm_x4(brl[bg], so + bOffL + (uint32_t)(bg*16*TROW) + kb);
            }
            #pragma unroll
            for (int mf = 0; mf < 4; mf++) {
                #pragma unroll
                for (int bg = 0; bg < 2; bg++) {
                    float* a0 = acc[mf][bg*2+0];
                    float* a1 = acc[mf][bg*2+1];
                    mma16816h(a0, ar[mf], brh[bg][0], brh[bg][1]);
                    mma16816h(a1, ar[mf], brh[bg][2], brh[bg][3]);
                    mma16816h(a0, ar[mf], brl[bg][0], brl[bg][1]);
                    mma16816h(a1, ar[mf], brl[bg][2], brl[bg][3]);
                }
            }
        }
    }

    int gid = lane >> 2, tg = lane & 3;
    #pragma unroll
    for (int mf = 0; mf < 4; mf++) {
        int row0 = mBase + mw*64 + mf*16 + gid;
        #pragma unroll
        for (int nf = 0; nf < 4; nf++) {
            int col = nBase + nw*32 + nf*8 + tg*2;
            size_t i0 = (size_t)row0 * W + col;
            size_t i1 = i0 + (size_t)8 * W;
            *(float2*)&C[i0] = make_float2(acc[mf][nf][0], acc[mf][nf][1]);
            *(float2*)&C[i1] = make_float2(acc[mf][nf][2], acc[mf][nf][3]);
        }
    }
}

// ---------------- combine ----------------
__global__ void combine_kernel(const float* __restrict__ gb) {
    size_t idx = (size_t)blockIdx.x*256 + threadIdx.x;
    int d = (int)(idx & 63);
    size_t r = idx >> 6;
    int n = (int)(r & 2047);
    int b = (int)(r >> 11);
    size_t p = (size_t)n*4096 + (size_t)(b*64 + d);
    float v = gb[d]
            + g_P[0*PSZ + p]          // P0
            + g_P[2*PSZ + p]          // P1
            + 2.f*g_P[9*PSZ + p]      // Q2
            - g_P[1*PSZ + p]          // P2x0
            + g_P[5*PSZ + p]          // P3
            + 2.f*g_P[10*PSZ + p]     // Q4
            - g_P[4*PSZ + p]          // P4m1
            + g_P[11*PSZ + p]         // Q5
            + g_P[13*PSZ + p]         // Q6
            - g_P[8*PSZ + p];         // P6m3
    g_gc[idx] = v;
}

// ---------------- attention ----------------
__global__ void logits_kernel(const float* __restrict__ hx, const float* __restrict__ R,
                              const float* __restrict__ aw, const float* __restrict__ ab) {
    int bk = blockIdx.x;
    int k = bk & 3;
    int tid = threadIdx.x;
    const float* hp = hx + (size_t)bk * NDD;
    const float* rp = R + (size_t)k * NDD;
    float s = 0.f;
    for (int t = tid; t < NDD; t += 256) s += (hp[t] + rp[t]) * aw[t];
    for (int o = 16; o; o >>= 1) s += __shfl_down_sync(0xffffffffu, s, o);
    __shared__ float red[8];
    if ((tid & 31) == 0) red[tid >> 5] = s;
    __syncthreads();
    if (tid == 0) {
        float t = 0.f;
        #pragma unroll
        for (int w = 0; w < 8; w++) t += red[w];
        g_logits[bk] = t + ab[0];
    }
}

__global__ void weight_kernel() {
    int b = threadIdx.x;
    if (b < BB) {
        float l0 = g_logits[b*4+0], l1 = g_logits[b*4+1], l2 = g_logits[b*4+2], l3 = g_logits[b*4+3];
        float m = fmaxf(fmaxf(l0, l1), fmaxf(l2, l3));
        float e0 = expf(l0 - m), e1 = expf(l1 - m), e2 = expf(l2 - m), e3 = expf(l3 - m);
        float inv = 1.f / (e0 + e1 + e2 + e3);
        g_wt[b*4+0] = e0 * inv; g_wt[b*4+1] = e1 * inv;
        g_wt[b*4+2] = e2 * inv; g_wt[b*4+3] = e3 * inv;
    }
}

// ---------------- output ----------------
__global__ void __launch_bounds__(256) final_kernel(const float* __restrict__ W,
                                                    const float* __restrict__ bbias,
                                                    const float* __restrict__ hx,
                                                    const float* __restrict__ R,
                                                    float* __restrict__ out, int write_hx) {
    __shared__ float sW[64*64];
    __shared__ float sg[4*64];
    int tid = threadIdx.x;
    int r0 = blockIdx.x * 4;
    for (int t = tid; t < 4096; t += 256) sW[t] = W[t];
    {
        float v = g_gc[(size_t)r0*64 + tid];
        sg[tid] = v > 0.f ? v : 0.01f * v;
    }
    __syncthreads();
    int rl = tid >> 6;
    int d = tid & 63;
    int r = r0 + rl;
    int b = r >> 11;
    int n = r & 2047;
    float acc = 0.f;
    #pragma unroll
    for (int e = 0; e < 64; e++) acc += sg[rl*64 + e] * sW[e*64 + d];
    float att = 0.f;
    #pragma unroll
    for (int k = 0; k < 4; k++) {
        float xv = hx[(size_t)((b << 2) + k)*NDD + (size_t)n*64 + d] + R[(size_t)k*NDD + (size_t)n*64 + d];
        att += xv * g_wt[b*4 + k];
    }
    float o = acc + bbias[(size_t)n*64 + d] + att;
    out[(size_t)b*NDD + (size_t)n*64 + d] = o;
    if (write_hx)
        out[(size_t)OUT1 + (size_t)((b << 2) + 3)*NDD + (size_t)n*64 + d] = o;
}

__global__ void hxcopy_kernel(const float* __restrict__ hx, float* __restrict__ out) {
    size_t idx = (size_t)blockIdx.x * 256 + threadIdx.x;
    int b = (int)(idx / (3*(size_t)NDD));
    size_t rem = idx - (size_t)b * (3*(size_t)NDD);
    int kk = (int)(rem / NDD);
    size_t j = rem - (size_t)kk * NDD;
    out[(size_t)OUT1 + (size_t)(b*4 + kk)*NDD + j] = hx[(size_t)(b*4 + kk + 1)*NDD + j];
}

// ---------------- launch ----------------
extern "C" void kernel_launch(void* const* d_in, const int* in_sizes, int n_in,
                              void* d_out, int out_size) {
    const float* inputs = (const float*)d_in[0];
    const float* hx     = (const float*)d_in[1];
    const float* graph  = (const float*)d_in[2];
    const float* nv1    = (const float*)d_in[3];
    const float* nv2    = (const float*)d_in[4];
    const float* W      = (const float*)d_in[5];
    const float* bbias  = (const float*)d_in[6];
    const float* R      = (const float*)d_in[7];
    const float* gw     = (const float*)d_in[8];
    const float* gb     = (const float*)d_in[9];
    const float* aw     = (const float*)d_in[10];
    const float* ab     = (const float*)d_in[11];
    float* out = (float*)d_out;

    int write_hx = ((size_t)out_size >= FULL_OUT) ? 1 : 0;

    cudaFuncSetAttribute(gemm_kernel, cudaFuncAttributeMaxDynamicSharedMemorySize, GEMM_SMEM);
    cudaFuncSetAttribute(gemm2_kernel, cudaFuncAttributeMaxDynamicSharedMemorySize, GEMM2_SMEM);
    cudaFuncSetAttribute(proj_multi_kernel, cudaFuncAttributeMaxDynamicSharedMemorySize, PROJ_SMEM);

    rowsum_dinv_kernel<<<NN, 256>>>(graph);
    colsum_part_kernel<<<dim3(NN/256, 8), 256>>>(graph);
    colsum_fin_kernel<<<NN/256, 256>>>();
    build_S1_kernel<<<dim3(64, 64), dim3(32, 8)>>>(graph);
    build_S2_kernel<<<(NN*NN)/256, 256>>>(graph);
    adp_kernel<<<NN, 256>>>(nv1, nv2);

    build_x0_kernel<<<66560, 256>>>(inputs, hx);

    dim3 gfull(NN/128, XW/128);           // (16, 65)
    dim3 gproj(NN/128, 4096/128);         // (16, 32)
    dim3 ga2(NN/128, NN/128);             // (16, 16)
    dim3 xfull(XW/32, NN/32);
    dim3 xhalf(4096/32, NN/32);
    dim3 xsq(NN/32, NN/32);
    dim3 xblk(32, 8);

    // P(x0): s0->10, s2->11
    proj_multi_kernel<<<NN, 256, PROJ_SMEM>>>(0, 2, make_int4(0, 2, 0, 0), 10, gw);

    // m1 = S1 @ x0 -> X1
    xt_convert_kernel<<<xfull, xblk>>>(0, XW);
    gemm_kernel<<<gfull, 256, GEMM_SMEM>>>(0, 1, XW);

    // P(m1): s1->12, s2->13, s4->14
    proj_multi_kernel<<<NN, 256, PROJ_SMEM>>>(1, 3, make_int4(1, 2, 4, 0), 12, gw);

    // m3 = S2 @ m1 -> X2
    xt_convert_kernel<<<xfull, xblk>>>(1, XW);
    gemm_kernel<<<gfull, 256, GEMM_SMEM>>>(1, 2, XW);

    // P(m3): s3->15, s4->16, s5->17, s6->18
    proj_multi_kernel<<<NN, 256, PROJ_SMEM>>>(2, 4, make_int4(3, 4, 5, 6), 15, gw);

    // Q2 = S1 @ P2m1
    xt_f16_kernel<<<xhalf, xblk>>>(13, 4096);
    gemm2_kernel<<<gproj, 256, GEMM2_SMEM>>>(0, 19, 4096);
    // Q4 = S2 @ P4m3
    xt_f16_kernel<<<xhalf, xblk>>>(16, 4096);
    gemm2_kernel<<<gproj, 256, GEMM2_SMEM>>>(1, 20, 4096);
    // Q5 = A @ P5m3
    xt_f16_kernel<<<xhalf, xblk>>>(17, 4096);
    gemm2_kernel<<<gproj, 256, GEMM2_SMEM>>>(2, 21, 4096);
    // A2 = A @ A  (fp32 out in slot 22)
    xt_f16_kernel<<<xsq, xblk>>>(3, NN);
    gemm2_kernel<<<ga2, 256, GEMM2_SMEM>>>(2, 22, NN);
    a2f_kernel<<<(NN*NN)/256, 256>>>();
    // Q6 = A2 @ P6m3
    xt_f16_kernel<<<xhalf, xblk>>>(18, 4096);
    gemm2_kernel<<<gproj, 256, GEMM2_SMEM>>>(3, 23, 4096);

    combine_kernel<<<(unsigned)(OUT1/256), 256>>>(gb);

    logits_kernel<<<BB*4, 256>>>(hx, R, aw, ab);
    weight_kernel<<<1, 64>>>();

    final_kernel<<<(BB*NN)/4, 256>>>(W, bbias, hx, R, out, write_hx);
    if (write_hx)
        hxcopy_kernel<<<(unsigned)((size_t)BB*3*NDD/256), 256>>>(hx, out);
}

// round 7
// speedup vs baseline: 3.7345x; 1.1082x over previous
#include <cuda_runtime.h>
#include <cuda_fp16.h>
#include <math.h>
#include <stdint.h>

#define NN 2048
#define BB 64
#define DD 64
#define ISZ 130
#define XW (ISZ*BB)          // 8320
#define NDD (NN*DD)          // 131072
#define OUT1 (BB*NDD)        // 8388608
#define HXPART ((size_t)BB*4*NDD)
#define FULL_OUT ((size_t)OUT1 + HXPART)
#define PSZ ((size_t)2048*4096)

// ---------------- scratch ----------------
static __device__ __half g_S1f[(size_t)NN*NN];
static __device__ __half g_S2f[(size_t)NN*NN];
static __device__ __half g_Adf[(size_t)NN*NN];
static __device__ __half g_A2f[(size_t)NN*NN];
static __device__ float g_Ad[(size_t)NN*NN];
static __device__ float g_dinv1[NN];
static __device__ float g_dinv2[NN];
static __device__ float g_cspart[8*NN];
static __device__ float g_X0[(size_t)NN*XW];
static __device__ float g_X1[(size_t)NN*XW];
static __device__ float g_X2[(size_t)NN*XW];
static __device__ __half g_YTh[(size_t)XW*NN];
static __device__ __half g_YTl[(size_t)XW*NN];
// P slots 10..23: 10=P0 11=P2x0 12=P1 13=P2m1 14=P4m1 15=P3 16=P4m3 17=P5m3
//                 18=P6m3 19=Q2 20=Q4 21=Q5 22=A2(fp32) 23=Q6
static __device__ float g_P[14*PSZ];
static __device__ float g_gc[(size_t)BB*NN*DD];
static __device__ float g_logits[BB*4];
static __device__ float g_wt[BB*4];

__device__ __forceinline__ float* bufAny(int s) {
    if (s == 0) return g_X0;
    if (s == 1) return g_X1;
    if (s == 2) return g_X2;
    if (s == 3) return g_Ad;
    return g_P + (size_t)(s - 10) * PSZ;
}

// ---------------- PTX helpers ----------------
__device__ __forceinline__ uint32_t smem_u32(const void* p) {
    uint32_t a;
    asm("{ .reg .u64 t; cvta.to.shared.u64 t, %1; cvt.u32.u64 %0, t; }" : "=r"(a) : "l"(p));
    return a;
}
__device__ __forceinline__ void cp16(uint32_t dst, const void* src) {
    asm volatile("cp.async.cg.shared.global [%0], [%1], 16;" :: "r"(dst), "l"(src) : "memory");
}
__device__ __forceinline__ void cp_commit() { asm volatile("cp.async.commit_group;" ::: "memory"); }
__device__ __forceinline__ void cp_wait2() { asm volatile("cp.async.wait_group 2;" ::: "memory"); }

__device__ __forceinline__ void ldm_x4(uint32_t* r, uint32_t addr) {
    asm volatile("ldmatrix.sync.aligned.m8n8.x4.shared.b16 {%0,%1,%2,%3}, [%4];"
                 : "=r"(r[0]), "=r"(r[1]), "=r"(r[2]), "=r"(r[3]) : "r"(addr));
}
__device__ __forceinline__ void mma16816h(float* c, const uint32_t* a, uint32_t b0, uint32_t b1) {
    asm volatile(
        "mma.sync.aligned.m16n8k16.row.col.f32.f16.f16.f32 "
        "{%0,%1,%2,%3}, {%4,%5,%6,%7}, {%8,%9}, {%0,%1,%2,%3};"
        : "+f"(c[0]), "+f"(c[1]), "+f"(c[2]), "+f"(c[3])
        : "r"(a[0]), "r"(a[1]), "r"(a[2]), "r"(a[3]), "r"(b0), "r"(b1));
}

// ---------------- support construction ----------------
__global__ void rowsum_dinv_kernel(const float* __restrict__ g) {
    int row = blockIdx.x;
    int tid = threadIdx.x;
    float s = 0.f;
    for (int j = tid; j < NN; j += 256) s += g[(size_t)row*NN + j];
    for (int o = 16; o; o >>= 1) s += __shfl_down_sync(0xffffffffu, s, o);
    __shared__ float red[8];
    if ((tid & 31) == 0) red[tid >> 5] = s;
    __syncthreads();
    if (tid == 0) {
        float t = 0.f;
        #pragma unroll
        for (int w = 0; w < 8; w++) t += red[w];
        g_dinv1[row] = 1.f / (1.f + t);
    }
}

__global__ void colsum_part_kernel(const float* __restrict__ g) {
    int col = blockIdx.x * 256 + threadIdx.x;
    int r0 = blockIdx.y * 256;
    float s = 0.f;
    #pragma unroll 8
    for (int r = 0; r < 256; r++) s += g[(size_t)(r0 + r)*NN + col];
    g_cspart[blockIdx.y*NN + col] = s;
}

__global__ void colsum_fin_kernel() {
    int col = blockIdx.x * 256 + threadIdx.x;
    float s = 0.f;
    #pragma unroll
    for (int y = 0; y < 8; y++) s += g_cspart[y*NN + col];
    g_dinv2[col] = 1.f / (1.f + s);
}

__global__ void build_S1_kernel(const float* __restrict__ g) {
    __shared__ float t[32][33];
    int bi = blockIdx.x * 32;
    int bj = blockIdx.y * 32;
    for (int r = threadIdx.y; r < 32; r += 8)
        t[r][threadIdx.x] = g[(size_t)(bj + r)*NN + bi + threadIdx.x];
    __syncthreads();
    for (int r = threadIdx.y; r < 32; r += 8) {
        int i = bi + r, j = bj + threadIdx.x;
        float dv = g_dinv1[j];
        float v = t[threadIdx.x][r] * dv;
        if (i == j) v += dv;
        g_S1f[(size_t)i*NN + j] = __float2half(v);
    }
}

__global__ void build_S2_kernel(const float* __restrict__ g) {
    int idx = blockIdx.x * 256 + threadIdx.x;
    int i = idx >> 11, j = idx & 2047;
    float v = (g[idx] + (i == j ? 1.f : 0.f)) * g_dinv2[j];
    g_S2f[idx] = __float2half(v);
}

__global__ void adp_kernel(const float* __restrict__ nv1, const float* __restrict__ nv2) {
    int i = blockIdx.x;
    int tid = threadIdx.x;
    __shared__ float v1[10];
    __shared__ float red[40];
    if (tid < 10) v1[tid] = nv1[i*10 + tid];
    __syncthreads();
    float p[8];
    float mx = 0.f;
    #pragma unroll
    for (int c = 0; c < 8; c++) {
        int j = tid + c*256;
        float s = 0.f;
        #pragma unroll
        for (int t = 0; t < 10; t++) s += v1[t] * nv2[t*NN + j];
        s = s > 0.f ? s : 0.f;
        p[c] = s;
        mx = fmaxf(mx, s);
    }
    for (int o = 16; o; o >>= 1) mx = fmaxf(mx, __shfl_xor_sync(0xffffffffu, mx, o));
    if ((tid & 31) == 0) red[tid >> 5] = mx;
    __syncthreads();
    if (tid == 0) {
        float m = red[0];
        #pragma unroll
        for (int w = 1; w < 8; w++) m = fmaxf(m, red[w]);
        red[32] = m;
    }
    __syncthreads();
    mx = red[32];
    float sum = 0.f;
    #pragma unroll
    for (int c = 0; c < 8; c++) { float e = expf(p[c] - mx); p[c] = e; sum += e; }
    for (int o = 16; o; o >>= 1) sum += __shfl_xor_sync(0xffffffffu, sum, o);
    if ((tid & 31) == 0) red[16 + (tid >> 5)] = sum;
    __syncthreads();
    if (tid == 0) {
        float t = 0.f;
        #pragma unroll
        for (int w = 0; w < 8; w++) t += red[16 + w];
        red[33] = 1.f / t;
    }
    __syncthreads();
    float inv = red[33];
    #pragma unroll
    for (int c = 0; c < 8; c++) {
        float v = p[c] * inv;
        size_t idx = (size_t)i*NN + tid + c*256;
        g_Ad[idx] = v;
        g_Adf[idx] = __float2half(v);
    }
}

// transpose + split fp16: X fp32 [2048 x W] -> YT hi/lo half [W x 2048]
__global__ void xt_f16_kernel(int selX, int W) {
    const float* X = bufAny(selX);
    __shared__ float t[32][33];
    int c0 = blockIdx.x * 32;
    int j0 = blockIdx.y * 32;
    int tx = threadIdx.x;
    for (int r = threadIdx.y; r < 32; r += 8)
        t[r][tx] = X[(size_t)(j0 + r)*W + c0 + tx];
    __syncthreads();
    for (int r = threadIdx.y; r < 32; r += 8) {
        int c = c0 + r;
        int j = j0 + tx;
        float v = t[tx][r];
        __half hh = __float2half(v);
        g_YTh[(size_t)c*NN + j] = hh;
        g_YTl[(size_t)c*NN + j] = __float2half(v - __half2float(hh));
    }
}

__global__ void a2f_kernel() {
    size_t idx = (size_t)blockIdx.x*256 + threadIdx.x;
    g_A2f[idx] = __float2half(g_P[12*PSZ + idx]);   // slot 22
}

// ---------------- x0 build ----------------
__global__ void build_x0_kernel(const float* __restrict__ inputs, const float* __restrict__ hx) {
    size_t total = (size_t)NN * XW;
    for (size_t idx = (size_t)blockIdx.x*256 + threadIdx.x; idx < total; idx += (size_t)gridDim.x*256) {
        int n = (int)(idx / XW);
        int c = (int)(idx - (size_t)n*XW);
        int i = c >> 6, b = c & 63;
        float v;
        if (i < 2) {
            v = inputs[(size_t)b*(NN*2) + n*2 + i];
        } else {
            int q = i - 2;
            int kk = (q < 64) ? 3 : 2;
            int d = q & 63;
            v = hx[(size_t)((b << 2) + kk)*NDD + (size_t)n*64 + d];
        }
        g_X0[idx] = v;
    }
}

// ---------------- multi-slice projection ----------------
#define PROJ_SMEM (2*XW*4)    // 66560
__global__ void __launch_bounds__(256) proj_multi_kernel(int selX, int cnt, int4 sl,
                                                         int outFirst,
                                                         const float* __restrict__ gw) {
    extern __shared__ float ps[];
    float* sx = ps;
    float* sw = ps + XW;
    const float* X = bufAny(selX);
    int n = blockIdx.x;
    int tid = threadIdx.x;
    for (int t = tid; t < XW/4; t += 256)
        ((float4*)sx)[t] = ((const float4*)(X + (size_t)n*XW))[t];
    int ss[4] = {sl.x, sl.y, sl.z, sl.w};
    int tb = tid >> 4;
    int td = tid & 15;
    for (int q = 0; q < cnt; q++) {
        int s = ss[q];
        __syncthreads();
        for (int t = tid; t < ISZ*16; t += 256) {
            int i = t >> 4, dq = t & 15;
            ((float4*)sw)[i*16 + dq] = ((const float4*)gw)[((size_t)i*7 + s)*16 + dq];
        }
        __syncthreads();
        float acc[4][4];
        #pragma unroll
        for (int bb = 0; bb < 4; bb++)
            #pragma unroll
            for (int dd = 0; dd < 4; dd++) acc[bb][dd] = 0.f;
        for (int i = 0; i < ISZ; i++) {
            float4 xa = ((const float4*)sx)[i*16 + tb];
            float4 wv = ((const float4*)sw)[i*16 + td];
            float xs[4] = {xa.x, xa.y, xa.z, xa.w};
            float ws[4] = {wv.x, wv.y, wv.z, wv.w};
            #pragma unroll
            for (int bb = 0; bb < 4; bb++)
                #pragma unroll
                for (int dd = 0; dd < 4; dd++) acc[bb][dd] += xs[bb] * ws[dd];
        }
        float* P = g_P + (size_t)(outFirst + q - 10)*PSZ + (size_t)n*4096;
        #pragma unroll
        for (int bb = 0; bb < 4; bb++)
            *(float4*)&P[(size_t)(tb*4 + bb)*64 + td*4] =
                make_float4(acc[bb][0], acc[bb][1], acc[bb][2], acc[bb][3]);
    }
}

// ---------------- fp16 2-product GEMM (all GEMMs) ----------------
#define KC 32
#define TROW 80
#define TILEB (128*TROW)
#define STAGEB2 (3*TILEB)       // 30720
#define GEMM2_SMEM (4*STAGEB2)  // 122880
#define NSTG 64

__global__ void __launch_bounds__(256, 1)
gemm2_kernel(int selA, int selC, int W) {
    extern __shared__ char smem[];
    uint32_t sb = smem_u32(smem);
    int tid = threadIdx.x;
    int wid = tid >> 5;
    int lane = tid & 31;

    const __half* Af = selA == 0 ? g_S1f : (selA == 1 ? g_S2f : (selA == 2 ? g_Adf : g_A2f));
    float* C = bufAny(selC);

    int mBase = blockIdx.x * 128;
    int nBase = blockIdx.y * 128;

    const __half* src[6];
    uint32_t dst[6];
    #pragma unroll
    for (int i = 0; i < 6; i++) {
        int c = tid + i*256;
        int tile = c >> 9;          // 0=A 1=Bh 2=Bl
        int q = c & 511;
        int row = q >> 2, col = q & 3;
        dst[i] = (uint32_t)(tile*TILEB + row*TROW + col*16);
        const __half* base;
        if (tile == 0)      base = Af    + (size_t)(mBase + row) * NN;
        else if (tile == 1) base = g_YTh + (size_t)(nBase + row) * NN;
        else                base = g_YTl + (size_t)(nBase + row) * NN;
        src[i] = base + col*8;
    }

    #pragma unroll
    for (int s = 0; s < 3; s++) {
        uint32_t so = sb + (uint32_t)(s * STAGEB2);
        #pragma unroll
        for (int i = 0; i < 6; i++) cp16(so + dst[i], src[i] + s*KC);
        cp_commit();
    }

    float acc[4][4][4];
    #pragma unroll
    for (int mf = 0; mf < 4; mf++)
        #pragma unroll
        for (int nf = 0; nf < 4; nf++)
            #pragma unroll
            for (int e = 0; e < 4; e++) acc[mf][nf][e] = 0.f;

    int mw = wid & 1;
    int nw = wid >> 1;
    int a_row = lane & 15;
    int a_colb = (lane >> 4) * 16;
    int b_row = ((lane >> 4) & 1) * 8 + (lane & 7);
    int b_colb = ((lane >> 3) & 1) * 16;

    uint32_t aOff  = (uint32_t)((mw*64 + a_row) * TROW) + (uint32_t)a_colb;
    uint32_t bOffH = (uint32_t)(1*TILEB) + (uint32_t)((nw*32 + b_row) * TROW) + (uint32_t)b_colb;
    uint32_t bOffL = bOffH + (uint32_t)TILEB;

    for (int s = 0; s < NSTG; s++) {
        cp_wait2();
        __syncthreads();
        int sn = s + 3;
        if (sn < NSTG) {
            uint32_t so2 = sb + (uint32_t)((sn & 3) * STAGEB2);
            #pragma unroll
            for (int i = 0; i < 6; i++) cp16(so2 + dst[i], src[i] + sn*KC);
        }
        cp_commit();

        uint32_t so = sb + (uint32_t)((s & 3) * STAGEB2);
        #pragma unroll
        for (int ks = 0; ks < 2; ks++) {
            uint32_t kb = (uint32_t)(ks*32);
            uint32_t ar[4][4], brh[2][4], brl[2][4];
            #pragma unroll
            for (int mf = 0; mf < 4; mf++)
                ldm_x4(ar[mf], so + aOff + (uint32_t)(mf*16*TROW) + kb);
            #pragma unroll
            for (int bg = 0; bg < 2; bg++) {
                ldm_x4(brh[bg], so + bOffH + (uint32_t)(bg*16*TROW) + kb);
                ldm_x4(brl[bg], so + bOffL + (uint32_t)(bg*16*TROW) + kb);
            }
            #pragma unroll
            for (int mf = 0; mf < 4; mf++) {
                #pragma unroll
                for (int bg = 0; bg < 2; bg++) {
                    float* a0 = acc[mf][bg*2+0];
                    float* a1 = acc[mf][bg*2+1];
                    mma16816h(a0, ar[mf], brh[bg][0], brh[bg][1]);
                    mma16816h(a1, ar[mf], brh[bg][2], brh[bg][3]);
                    mma16816h(a0, ar[mf], brl[bg][0], brl[bg][1]);
                    mma16816h(a1, ar[mf], brl[bg][2], brl[bg][3]);
                }
            }
        }
    }

    int gid = lane >> 2, tg = lane & 3;
    #pragma unroll
    for (int mf = 0; mf < 4; mf++) {
        int row0 = mBase + mw*64 + mf*16 + gid;
        #pragma unroll
        for (int nf = 0; nf < 4; nf++) {
            int col = nBase + nw*32 + nf*8 + tg*2;
            size_t i0 = (size_t)row0 * W + col;
            size_t i1 = i0 + (size_t)8 * W;
            *(float2*)&C[i0] = make_float2(acc[mf][nf][0], acc[mf][nf][1]);
            *(float2*)&C[i1] = make_float2(acc[mf][nf][2], acc[mf][nf][3]);
        }
    }
}

// ---------------- combine ----------------
__global__ void combine_kernel(const float* __restrict__ gb) {
    size_t idx = (size_t)blockIdx.x*256 + threadIdx.x;
    int d = (int)(idx & 63);
    size_t r = idx >> 6;
    int n = (int)(r & 2047);
    int b = (int)(r >> 11);
    size_t p = (size_t)n*4096 + (size_t)(b*64 + d);
    float v = gb[d]
            + g_P[0*PSZ + p]          // P0
            + g_P[2*PSZ + p]          // P1
            + 2.f*g_P[9*PSZ + p]      // Q2
            - g_P[1*PSZ + p]          // P2x0
            + g_P[5*PSZ + p]          // P3
            + 2.f*g_P[10*PSZ + p]     // Q4
            - g_P[4*PSZ + p]          // P4m1
            + g_P[11*PSZ + p]         // Q5
            + g_P[13*PSZ + p]         // Q6
            - g_P[8*PSZ + p];         // P6m3
    g_gc[idx] = v;
}

// ---------------- attention ----------------
__global__ void logits_kernel(const float* __restrict__ hx, const float* __restrict__ R,
                              const float* __restrict__ aw, const float* __restrict__ ab) {
    int bk = blockIdx.x;
    int k = bk & 3;
    int tid = threadIdx.x;
    const float* hp = hx + (size_t)bk * NDD;
    const float* rp = R + (size_t)k * NDD;
    float s = 0.f;
    for (int t = tid; t < NDD; t += 256) s += (hp[t] + rp[t]) * aw[t];
    for (int o = 16; o; o >>= 1) s += __shfl_down_sync(0xffffffffu, s, o);
    __shared__ float red[8];
    if ((tid & 31) == 0) red[tid >> 5] = s;
    __syncthreads();
    if (tid == 0) {
        float t = 0.f;
        #pragma unroll
        for (int w = 0; w < 8; w++) t += red[w];
        g_logits[bk] = t + ab[0];
    }
}

__global__ void weight_kernel() {
    int b = threadIdx.x;
    if (b < BB) {
        float l0 = g_logits[b*4+0], l1 = g_logits[b*4+1], l2 = g_logits[b*4+2], l3 = g_logits[b*4+3];
        float m = fmaxf(fmaxf(l0, l1), fmaxf(l2, l3));
        float e0 = expf(l0 - m), e1 = expf(l1 - m), e2 = expf(l2 - m), e3 = expf(l3 - m);
        float inv = 1.f / (e0 + e1 + e2 + e3);
        g_wt[b*4+0] = e0 * inv; g_wt[b*4+1] = e1 * inv;
        g_wt[b*4+2] = e2 * inv; g_wt[b*4+3] = e3 * inv;
    }
}

// ---------------- output ----------------
__global__ void __launch_bounds__(256) final_kernel(const float* __restrict__ W,
                                                    const float* __restrict__ bbias,
                                                    const float* __restrict__ hx,
                                                    const float* __restrict__ R,
                                                    float* __restrict__ out, int write_hx) {
    __shared__ float sW[64*64];
    __shared__ float sg[4*64];
    int tid = threadIdx.x;
    int r0 = blockIdx.x * 4;
    for (int t = tid; t < 4096; t += 256) sW[t] = W[t];
    {
        float v = g_gc[(size_t)r0*64 + tid];
        sg[tid] = v > 0.f ? v : 0.01f * v;
    }
    __syncthreads();
    int rl = tid >> 6;
    int d = tid & 63;
    int r = r0 + rl;
    int b = r >> 11;
    int n = r & 2047;
    float acc = 0.f;
    #pragma unroll
    for (int e = 0; e < 64; e++) acc += sg[rl*64 + e] * sW[e*64 + d];
    float att = 0.f;
    #pragma unroll
    for (int k = 0; k < 4; k++) {
        float xv = hx[(size_t)((b << 2) + k)*NDD + (size_t)n*64 + d] + R[(size_t)k*NDD + (size_t)n*64 + d];
        att += xv * g_wt[b*4 + k];
    }
    float o = acc + bbias[(size_t)n*64 + d] + att;
    out[(size_t)b*NDD + (size_t)n*64 + d] = o;
    if (write_hx)
        out[(size_t)OUT1 + (size_t)((b << 2) + 3)*NDD + (size_t)n*64 + d] = o;
}

__global__ void hxcopy_kernel(const float* __restrict__ hx, float* __restrict__ out) {
    size_t idx = (size_t)blockIdx.x * 256 + threadIdx.x;
    int b = (int)(idx / (3*(size_t)NDD));
    size_t rem = idx - (size_t)b * (3*(size_t)NDD);
    int kk = (int)(rem / NDD);
    size_t j = rem - (size_t)kk * NDD;
    out[(size_t)OUT1 + (size_t)(b*4 + kk)*NDD + j] = hx[(size_t)(b*4 + kk + 1)*NDD + j];
}

// ---------------- launch ----------------
extern "C" void kernel_launch(void* const* d_in, const int* in_sizes, int n_in,
                              void* d_out, int out_size) {
    const float* inputs = (const float*)d_in[0];
    const float* hx     = (const float*)d_in[1];
    const float* graph  = (const float*)d_in[2];
    const float* nv1    = (const float*)d_in[3];
    const float* nv2    = (const float*)d_in[4];
    const float* W      = (const float*)d_in[5];
    const float* bbias  = (const float*)d_in[6];
    const float* R      = (const float*)d_in[7];
    const float* gw     = (const float*)d_in[8];
    const float* gb     = (const float*)d_in[9];
    const float* aw     = (const float*)d_in[10];
    const float* ab     = (const float*)d_in[11];
    float* out = (float*)d_out;

    int write_hx = ((size_t)out_size >= FULL_OUT) ? 1 : 0;

    cudaFuncSetAttribute(gemm2_kernel, cudaFuncAttributeMaxDynamicSharedMemorySize, GEMM2_SMEM);
    cudaFuncSetAttribute(proj_multi_kernel, cudaFuncAttributeMaxDynamicSharedMemorySize, PROJ_SMEM);

    rowsum_dinv_kernel<<<NN, 256>>>(graph);
    colsum_part_kernel<<<dim3(NN/256, 8), 256>>>(graph);
    colsum_fin_kernel<<<NN/256, 256>>>();
    build_S1_kernel<<<dim3(64, 64), dim3(32, 8)>>>(graph);
    build_S2_kernel<<<(NN*NN)/256, 256>>>(graph);
    adp_kernel<<<NN, 256>>>(nv1, nv2);

    build_x0_kernel<<<66560, 256>>>(inputs, hx);

    dim3 gfull(NN/128, XW/128);           // (16, 65)
    dim3 gproj(NN/128, 4096/128);         // (16, 32)
    dim3 ga2(NN/128, NN/128);             // (16, 16)
    dim3 xfull(XW/32, NN/32);
    dim3 xhalf(4096/32, NN/32);
    dim3 xsq(NN/32, NN/32);
    dim3 xblk(32, 8);

    // P(x0): s0->10, s2->11
    proj_multi_kernel<<<NN, 256, PROJ_SMEM>>>(0, 2, make_int4(0, 2, 0, 0), 10, gw);

    // m1 = S1 @ x0 -> X1
    xt_f16_kernel<<<xfull, xblk>>>(0, XW);
    gemm2_kernel<<<gfull, 256, GEMM2_SMEM>>>(0, 1, XW);

    // P(m1): s1->12, s2->13, s4->14
    proj_multi_kernel<<<NN, 256, PROJ_SMEM>>>(1, 3, make_int4(1, 2, 4, 0), 12, gw);

    // m3 = S2 @ m1 -> X2
    xt_f16_kernel<<<xfull, xblk>>>(1, XW);
    gemm2_kernel<<<gfull, 256, GEMM2_SMEM>>>(1, 2, XW);

    // P(m3): s3->15, s4->16, s5->17, s6->18
    proj_multi_kernel<<<NN, 256, PROJ_SMEM>>>(2, 4, make_int4(3, 4, 5, 6), 15, gw);

    // Q2 = S1 @ P2m1
    xt_f16_kernel<<<xhalf, xblk>>>(13, 4096);
    gemm2_kernel<<<gproj, 256, GEMM2_SMEM>>>(0, 19, 4096);
    // Q4 = S2 @ P4m3
    xt_f16_kernel<<<xhalf, xblk>>>(16, 4096);
    gemm2_kernel<<<gproj, 256, GEMM2_SMEM>>>(1, 20, 4096);
    // Q5 = A @ P5m3
    xt_f16_kernel<<<xhalf, xblk>>>(17, 4096);
    gemm2_kernel<<<gproj, 256, GEMM2_SMEM>>>(2, 21, 4096);
    // A2 = A @ A
    xt_f16_kernel<<<xsq, xblk>>>(3, NN);
    gemm2_kernel<<<ga2, 256, GEMM2_SMEM>>>(2, 22, NN);
    a2f_kernel<<<(NN*NN)/256, 256>>>();
    // Q6 = A2 @ P6m3
    xt_f16_kernel<<<xhalf, xblk>>>(18, 4096);
    gemm2_kernel<<<gproj, 256, GEMM2_SMEM>>>(3, 23, 4096);

    combine_kernel<<<(unsigned)(OUT1/256), 256>>>(gb);

    logits_kernel<<<BB*4, 256>>>(hx, R, aw, ab);
    weight_kernel<<<1, 64>>>();

    final_kernel<<<(BB*NN)/4, 256>>>(W, bbias, hx, R, out, write_hx);
    if (write_hx)
        hxcopy_kernel<<<(unsigned)((size_t)BB*3*NDD/256), 256>>>(hx, out);
}

// round 8
// speedup vs baseline: 5.1893x; 1.3895x over previous
#include <cuda_runtime.h>
#include <cuda_fp16.h>
#include <math.h>
#include <stdint.h>

#define NN 2048
#define BB 64
#define DD 64
#define ISZ 130
#define XW (ISZ*BB)          // 8320
#define NDD (NN*DD)          // 131072
#define OUT1 (BB*NDD)        // 8388608
#define HXPART ((size_t)BB*4*NDD)
#define FULL_OUT ((size_t)OUT1 + HXPART)
#define PSZ ((size_t)2048*4096)

// ---------------- scratch ----------------
static __device__ __half g_S1f[(size_t)NN*NN];
static __device__ __half g_S2f[(size_t)NN*NN];
static __device__ __half g_Adf[(size_t)NN*NN];
static __device__ __half g_A2f[(size_t)NN*NN];
static __device__ float g_Ad[(size_t)NN*NN];
static __device__ float g_dinv1[NN];
static __device__ float g_dinv2[NN];
static __device__ float g_cspart[8*NN];
static __device__ float g_X0[(size_t)NN*XW];
static __device__ float g_X1[(size_t)NN*XW];
static __device__ float g_X2[(size_t)NN*XW];
static __device__ __half g_YTh[(size_t)XW*NN];
// P slots 10..23: 10=P0 11=P2x0 12=P1 13=P2m1 14=P4m1 15=P3 16=P4m3 17=P5m3
//                 18=P6m3 19=Q2 20=Q4 21=Q5 22=A2(fp32) 23=Q6
static __device__ float g_P[14*PSZ];
static __device__ float g_gc[(size_t)BB*NN*DD];
static __device__ float g_logits[BB*4];
static __device__ float g_wt[BB*4];

__device__ __forceinline__ float* bufAny(int s) {
    if (s == 0) return g_X0;
    if (s == 1) return g_X1;
    if (s == 2) return g_X2;
    if (s == 3) return g_Ad;
    return g_P + (size_t)(s - 10) * PSZ;
}

// ---------------- PTX helpers ----------------
__device__ __forceinline__ uint32_t smem_u32(const void* p) {
    uint32_t a;
    asm("{ .reg .u64 t; cvta.to.shared.u64 t, %1; cvt.u32.u64 %0, t; }" : "=r"(a) : "l"(p));
    return a;
}
__device__ __forceinline__ void cp16(uint32_t dst, const void* src) {
    asm volatile("cp.async.cg.shared.global [%0], [%1], 16;" :: "r"(dst), "l"(src) : "memory");
}
__device__ __forceinline__ void cp_commit() { asm volatile("cp.async.commit_group;" ::: "memory"); }
__device__ __forceinline__ void cp_wait2() { asm volatile("cp.async.wait_group 2;" ::: "memory"); }

__device__ __forceinline__ void ldm_x4(uint32_t* r, uint32_t addr) {
    asm volatile("ldmatrix.sync.aligned.m8n8.x4.shared.b16 {%0,%1,%2,%3}, [%4];"
                 : "=r"(r[0]), "=r"(r[1]), "=r"(r[2]), "=r"(r[3]) : "r"(addr));
}
__device__ __forceinline__ void mma16816h(float* c, const uint32_t* a, uint32_t b0, uint32_t b1) {
    asm volatile(
        "mma.sync.aligned.m16n8k16.row.col.f32.f16.f16.f32 "
        "{%0,%1,%2,%3}, {%4,%5,%6,%7}, {%8,%9}, {%0,%1,%2,%3};"
        : "+f"(c[0]), "+f"(c[1]), "+f"(c[2]), "+f"(c[3])
        : "r"(a[0]), "r"(a[1]), "r"(a[2]), "r"(a[3]), "r"(b0), "r"(b1));
}

// ---------------- support construction ----------------
__global__ void rowsum_dinv_kernel(const float* __restrict__ g) {
    int row = blockIdx.x;
    int tid = threadIdx.x;
    float s = 0.f;
    for (int j = tid; j < NN; j += 256) s += g[(size_t)row*NN + j];
    for (int o = 16; o; o >>= 1) s += __shfl_down_sync(0xffffffffu, s, o);
    __shared__ float red[8];
    if ((tid & 31) == 0) red[tid >> 5] = s;
    __syncthreads();
    if (tid == 0) {
        float t = 0.f;
        #pragma unroll
        for (int w = 0; w < 8; w++) t += red[w];
        g_dinv1[row] = 1.f / (1.f + t);
    }
}

__global__ void colsum_part_kernel(const float* __restrict__ g) {
    int col = blockIdx.x * 256 + threadIdx.x;
    int r0 = blockIdx.y * 256;
    float s = 0.f;
    #pragma unroll 8
    for (int r = 0; r < 256; r++) s += g[(size_t)(r0 + r)*NN + col];
    g_cspart[blockIdx.y*NN + col] = s;
}

__global__ void colsum_fin_kernel() {
    int col = blockIdx.x * 256 + threadIdx.x;
    float s = 0.f;
    #pragma unroll
    for (int y = 0; y < 8; y++) s += g_cspart[y*NN + col];
    g_dinv2[col] = 1.f / (1.f + s);
}

__global__ void build_S1_kernel(const float* __restrict__ g) {
    __shared__ float t[32][33];
    int bi = blockIdx.x * 32;
    int bj = blockIdx.y * 32;
    for (int r = threadIdx.y; r < 32; r += 8)
        t[r][threadIdx.x] = g[(size_t)(bj + r)*NN + bi + threadIdx.x];
    __syncthreads();
    for (int r = threadIdx.y; r < 32; r += 8) {
        int i = bi + r, j = bj + threadIdx.x;
        float dv = g_dinv1[j];
        float v = t[threadIdx.x][r] * dv;
        if (i == j) v += dv;
        g_S1f[(size_t)i*NN + j] = __float2half(v);
    }
}

__global__ void build_S2_kernel(const float* __restrict__ g) {
    int idx = blockIdx.x * 256 + threadIdx.x;
    int i = idx >> 11, j = idx & 2047;
    float v = (g[idx] + (i == j ? 1.f : 0.f)) * g_dinv2[j];
    g_S2f[idx] = __float2half(v);
}

__global__ void adp_kernel(const float* __restrict__ nv1, const float* __restrict__ nv2) {
    int i = blockIdx.x;
    int tid = threadIdx.x;
    __shared__ float v1[10];
    __shared__ float red[40];
    if (tid < 10) v1[tid] = nv1[i*10 + tid];
    __syncthreads();
    float p[8];
    float mx = 0.f;
    #pragma unroll
    for (int c = 0; c < 8; c++) {
        int j = tid + c*256;
        float s = 0.f;
        #pragma unroll
        for (int t = 0; t < 10; t++) s += v1[t] * nv2[t*NN + j];
        s = s > 0.f ? s : 0.f;
        p[c] = s;
        mx = fmaxf(mx, s);
    }
    for (int o = 16; o; o >>= 1) mx = fmaxf(mx, __shfl_xor_sync(0xffffffffu, mx, o));
    if ((tid & 31) == 0) red[tid >> 5] = mx;
    __syncthreads();
    if (tid == 0) {
        float m = red[0];
        #pragma unroll
        for (int w = 1; w < 8; w++) m = fmaxf(m, red[w]);
        red[32] = m;
    }
    __syncthreads();
    mx = red[32];
    float sum = 0.f;
    #pragma unroll
    for (int c = 0; c < 8; c++) { float e = expf(p[c] - mx); p[c] = e; sum += e; }
    for (int o = 16; o; o >>= 1) sum += __shfl_xor_sync(0xffffffffu, sum, o);
    if ((tid & 31) == 0) red[16 + (tid >> 5)] = sum;
    __syncthreads();
    if (tid == 0) {
        float t = 0.f;
        #pragma unroll
        for (int w = 0; w < 8; w++) t += red[16 + w];
        red[33] = 1.f / t;
    }
    __syncthreads();
    float inv = red[33];
    #pragma unroll
    for (int c = 0; c < 8; c++) {
        float v = p[c] * inv;
        size_t idx = (size_t)i*NN + tid + c*256;
        g_Ad[idx] = v;
        g_Adf[idx] = __float2half(v);
    }
}

// transpose fp16: X fp32 [2048 x W] -> YT half [W x 2048]
__global__ void xt_f16_kernel(int selX, int W) {
    const float* X = bufAny(selX);
    __shared__ float t[32][33];
    int c0 = blockIdx.x * 32;
    int j0 = blockIdx.y * 32;
    int tx = threadIdx.x;
    for (int r = threadIdx.y; r < 32; r += 8)
        t[r][tx] = X[(size_t)(j0 + r)*W + c0 + tx];
    __syncthreads();
    for (int r = threadIdx.y; r < 32; r += 8) {
        int c = c0 + r;
        int j = j0 + tx;
        g_YTh[(size_t)c*NN + j] = __float2half(t[tx][r]);
    }
}

__global__ void a2f_kernel() {
    size_t idx = (size_t)blockIdx.x*256 + threadIdx.x;
    g_A2f[idx] = __float2half(g_P[12*PSZ + idx]);   // slot 22
}

// ---------------- x0 build ----------------
__global__ void build_x0_kernel(const float* __restrict__ inputs, const float* __restrict__ hx) {
    size_t total = (size_t)NN * XW;
    for (size_t idx = (size_t)blockIdx.x*256 + threadIdx.x; idx < total; idx += (size_t)gridDim.x*256) {
        int n = (int)(idx / XW);
        int c = (int)(idx - (size_t)n*XW);
        int i = c >> 6, b = c & 63;
        float v;
        if (i < 2) {
            v = inputs[(size_t)b*(NN*2) + n*2 + i];
        } else {
            int q = i - 2;
            int kk = (q < 64) ? 3 : 2;
            int d = q & 63;
            v = hx[(size_t)((b << 2) + kk)*NDD + (size_t)n*64 + d];
        }
        g_X0[idx] = v;
    }
}

// ---------------- multi-slice projection ----------------
#define PROJ_SMEM (2*XW*4)    // 66560
__global__ void __launch_bounds__(256) proj_multi_kernel(int selX, int cnt, int4 sl,
                                                         int outFirst,
                                                         const float* __restrict__ gw) {
    extern __shared__ float ps[];
    float* sx = ps;
    float* sw = ps + XW;
    const float* X = bufAny(selX);
    int n = blockIdx.x;
    int tid = threadIdx.x;
    for (int t = tid; t < XW/4; t += 256)
        ((float4*)sx)[t] = ((const float4*)(X + (size_t)n*XW))[t];
    int ss[4] = {sl.x, sl.y, sl.z, sl.w};
    int tb = tid >> 4;
    int td = tid & 15;
    for (int q = 0; q < cnt; q++) {
        int s = ss[q];
        __syncthreads();
        for (int t = tid; t < ISZ*16; t += 256) {
            int i = t >> 4, dq = t & 15;
            ((float4*)sw)[i*16 + dq] = ((const float4*)gw)[((size_t)i*7 + s)*16 + dq];
        }
        __syncthreads();
        float acc[4][4];
        #pragma unroll
        for (int bb = 0; bb < 4; bb++)
            #pragma unroll
            for (int dd = 0; dd < 4; dd++) acc[bb][dd] = 0.f;
        for (int i = 0; i < ISZ; i++) {
            float4 xa = ((const float4*)sx)[i*16 + tb];
            float4 wv = ((const float4*)sw)[i*16 + td];
            float xs[4] = {xa.x, xa.y, xa.z, xa.w};
            float ws[4] = {wv.x, wv.y, wv.z, wv.w};
            #pragma unroll
            for (int bb = 0; bb < 4; bb++)
                #pragma unroll
                for (int dd = 0; dd < 4; dd++) acc[bb][dd] += xs[bb] * ws[dd];
        }
        float* P = g_P + (size_t)(outFirst + q - 10)*PSZ + (size_t)n*4096;
        #pragma unroll
        for (int bb = 0; bb < 4; bb++)
            *(float4*)&P[(size_t)(tb*4 + bb)*64 + td*4] =
                make_float4(acc[bb][0], acc[bb][1], acc[bb][2], acc[bb][3]);
    }
}

// ---------------- single-product fp16 GEMM ----------------
#define KC 32
#define TROW 80
#define TILEB (128*TROW)
#define STAGEB1 (2*TILEB)       // 20480
#define GEMM1_SMEM (4*STAGEB1)  // 81920
#define NSTG 64

__global__ void __launch_bounds__(256, 1)
gemm1_kernel(int selA, int selC, int W) {
    extern __shared__ char smem[];
    uint32_t sb = smem_u32(smem);
    int tid = threadIdx.x;
    int wid = tid >> 5;
    int lane = tid & 31;

    const __half* Af = selA == 0 ? g_S1f : (selA == 1 ? g_S2f : (selA == 2 ? g_Adf : g_A2f));
    float* C = bufAny(selC);

    int mBase = blockIdx.x * 128;
    int nBase = blockIdx.y * 128;

    const __half* src[4];
    uint32_t dst[4];
    #pragma unroll
    for (int i = 0; i < 4; i++) {
        int c = tid + i*256;
        int tile = c >> 9;          // 0=A 1=B
        int q = c & 511;
        int row = q >> 2, col = q & 3;
        dst[i] = (uint32_t)(tile*TILEB + row*TROW + col*16);
        const __half* base;
        if (tile == 0) base = Af    + (size_t)(mBase + row) * NN;
        else           base = g_YTh + (size_t)(nBase + row) * NN;
        src[i] = base + col*8;
    }

    #pragma unroll
    for (int s = 0; s < 3; s++) {
        uint32_t so = sb + (uint32_t)(s * STAGEB1);
        #pragma unroll
        for (int i = 0; i < 4; i++) cp16(so + dst[i], src[i] + s*KC);
        cp_commit();
    }

    float acc[4][4][4];
    #pragma unroll
    for (int mf = 0; mf < 4; mf++)
        #pragma unroll
        for (int nf = 0; nf < 4; nf++)
            #pragma unroll
            for (int e = 0; e < 4; e++) acc[mf][nf][e] = 0.f;

    int mw = wid & 1;
    int nw = wid >> 1;
    int a_row = lane & 15;
    int a_colb = (lane >> 4) * 16;
    int b_row = ((lane >> 4) & 1) * 8 + (lane & 7);
    int b_colb = ((lane >> 3) & 1) * 16;

    uint32_t aOff = (uint32_t)((mw*64 + a_row) * TROW) + (uint32_t)a_colb;
    uint32_t bOff = (uint32_t)TILEB + (uint32_t)((nw*32 + b_row) * TROW) + (uint32_t)b_colb;

    for (int s = 0; s < NSTG; s++) {
        cp_wait2();
        __syncthreads();
        int sn = s + 3;
        if (sn < NSTG) {
            uint32_t so2 = sb + (uint32_t)((sn & 3) * STAGEB1);
            #pragma unroll
            for (int i = 0; i < 4; i++) cp16(so2 + dst[i], src[i] + sn*KC);
        }
        cp_commit();

        uint32_t so = sb + (uint32_t)((s & 3) * STAGEB1);
        #pragma unroll
        for (int ks = 0; ks < 2; ks++) {
            uint32_t kb = (uint32_t)(ks*32);
            uint32_t ar[4][4], br[2][4];
            #pragma unroll
            for (int mf = 0; mf < 4; mf++)
                ldm_x4(ar[mf], so + aOff + (uint32_t)(mf*16*TROW) + kb);
            #pragma unroll
            for (int bg = 0; bg < 2; bg++)
                ldm_x4(br[bg], so + bOff + (uint32_t)(bg*16*TROW) + kb);
            #pragma unroll
            for (int mf = 0; mf < 4; mf++) {
                #pragma unroll
                for (int bg = 0; bg < 2; bg++) {
                    mma16816h(acc[mf][bg*2+0], ar[mf], br[bg][0], br[bg][1]);
                    mma16816h(acc[mf][bg*2+1], ar[mf], br[bg][2], br[bg][3]);
                }
            }
        }
    }

    int gid = lane >> 2, tg = lane & 3;
    #pragma unroll
    for (int mf = 0; mf < 4; mf++) {
        int row0 = mBase + mw*64 + mf*16 + gid;
        #pragma unroll
        for (int nf = 0; nf < 4; nf++) {
            int col = nBase + nw*32 + nf*8 + tg*2;
            size_t i0 = (size_t)row0 * W + col;
            size_t i1 = i0 + (size_t)8 * W;
            *(float2*)&C[i0] = make_float2(acc[mf][nf][0], acc[mf][nf][1]);
            *(float2*)&C[i1] = make_float2(acc[mf][nf][2], acc[mf][nf][3]);
        }
    }
}

// ---------------- combine ----------------
__global__ void combine_kernel(const float* __restrict__ gb) {
    size_t idx = (size_t)blockIdx.x*256 + threadIdx.x;
    int d = (int)(idx & 63);
    size_t r = idx >> 6;
    int n = (int)(r & 2047);
    int b = (int)(r >> 11);
    size_t p = (size_t)n*4096 + (size_t)(b*64 + d);
    float v = gb[d]
            + g_P[0*PSZ + p]          // P0
            + g_P[2*PSZ + p]          // P1
            + 2.f*g_P[9*PSZ + p]      // Q2
            - g_P[1*PSZ + p]          // P2x0
            + g_P[5*PSZ + p]          // P3
            + 2.f*g_P[10*PSZ + p]     // Q4
            - g_P[4*PSZ + p]          // P4m1
            + g_P[11*PSZ + p]         // Q5
            + g_P[13*PSZ + p]         // Q6
            - g_P[8*PSZ + p];         // P6m3
    g_gc[idx] = v;
}

// ---------------- attention ----------------
__global__ void logits_kernel(const float* __restrict__ hx, const float* __restrict__ R,
                              const float* __restrict__ aw, const float* __restrict__ ab) {
    int bk = blockIdx.x;
    int k = bk & 3;
    int tid = threadIdx.x;
    const float* hp = hx + (size_t)bk * NDD;
    const float* rp = R + (size_t)k * NDD;
    float s = 0.f;
    for (int t = tid; t < NDD; t += 256) s += (hp[t] + rp[t]) * aw[t];
    for (int o = 16; o; o >>= 1) s += __shfl_down_sync(0xffffffffu, s, o);
    __shared__ float red[8];
    if ((tid & 31) == 0) red[tid >> 5] = s;
    __syncthreads();
    if (tid == 0) {
        float t = 0.f;
        #pragma unroll
        for (int w = 0; w < 8; w++) t += red[w];
        g_logits[bk] = t + ab[0];
    }
}

__global__ void weight_kernel() {
    int b = threadIdx.x;
    if (b < BB) {
        float l0 = g_logits[b*4+0], l1 = g_logits[b*4+1], l2 = g_logits[b*4+2], l3 = g_logits[b*4+3];
        float m = fmaxf(fmaxf(l0, l1), fmaxf(l2, l3));
        float e0 = expf(l0 - m), e1 = expf(l1 - m), e2 = expf(l2 - m), e3 = expf(l3 - m);
        float inv = 1.f / (e0 + e1 + e2 + e3);
        g_wt[b*4+0] = e0 * inv; g_wt[b*4+1] = e1 * inv;
        g_wt[b*4+2] = e2 * inv; g_wt[b*4+3] = e3 * inv;
    }
}

// ---------------- output ----------------
__global__ void __launch_bounds__(256) final_kernel(const float* __restrict__ W,
                                                    const float* __restrict__ bbias,
                                                    const float* __restrict__ hx,
                                                    const float* __restrict__ R,
                                                    float* __restrict__ out, int write_hx) {
    __shared__ float sW[64*64];
    __shared__ float sg[4*64];
    int tid = threadIdx.x;
    int r0 = blockIdx.x * 4;
    for (int t = tid; t < 4096; t += 256) sW[t] = W[t];
    {
        float v = g_gc[(size_t)r0*64 + tid];
        sg[tid] = v > 0.f ? v : 0.01f * v;
    }
    __syncthreads();
    int rl = tid >> 6;
    int d = tid & 63;
    int r = r0 + rl;
    int b = r >> 11;
    int n = r & 2047;
    float acc = 0.f;
    #pragma unroll
    for (int e = 0; e < 64; e++) acc += sg[rl*64 + e] * sW[e*64 + d];
    float att = 0.f;
    #pragma unroll
    for (int k = 0; k < 4; k++) {
        float xv = hx[(size_t)((b << 2) + k)*NDD + (size_t)n*64 + d] + R[(size_t)k*NDD + (size_t)n*64 + d];
        att += xv * g_wt[b*4 + k];
    }
    float o = acc + bbias[(size_t)n*64 + d] + att;
    out[(size_t)b*NDD + (size_t)n*64 + d] = o;
    if (write_hx)
        out[(size_t)OUT1 + (size_t)((b << 2) + 3)*NDD + (size_t)n*64 + d] = o;
}

__global__ void hxcopy_kernel(const float* __restrict__ hx, float* __restrict__ out) {
    size_t idx = (size_t)blockIdx.x * 256 + threadIdx.x;
    int b = (int)(idx / (3*(size_t)NDD));
    size_t rem = idx - (size_t)b * (3*(size_t)NDD);
    int kk = (int)(rem / NDD);
    size_t j = rem - (size_t)kk * NDD;
    out[(size_t)OUT1 + (size_t)(b*4 + kk)*NDD + j] = hx[(size_t)(b*4 + kk + 1)*NDD + j];
}

// ---------------- launch ----------------
extern "C" void kernel_launch(void* const* d_in, const int* in_sizes, int n_in,
                              void* d_out, int out_size) {
    const float* inputs = (const float*)d_in[0];
    const float* hx     = (const float*)d_in[1];
    const float* graph  = (const float*)d_in[2];
    const float* nv1    = (const float*)d_in[3];
    const float* nv2    = (const float*)d_in[4];
    const float* W      = (const float*)d_in[5];
    const float* bbias  = (const float*)d_in[6];
    const float* R      = (const float*)d_in[7];
    const float* gw     = (const float*)d_in[8];
    const float* gb     = (const float*)d_in[9];
    const float* aw     = (const float*)d_in[10];
    const float* ab     = (const float*)d_in[11];
    float* out = (float*)d_out;

    int write_hx = ((size_t)out_size >= FULL_OUT) ? 1 : 0;

    cudaFuncSetAttribute(gemm1_kernel, cudaFuncAttributeMaxDynamicSharedMemorySize, GEMM1_SMEM);
    cudaFuncSetAttribute(proj_multi_kernel, cudaFuncAttributeMaxDynamicSharedMemorySize, PROJ_SMEM);

    rowsum_dinv_kernel<<<NN, 256>>>(graph);
    colsum_part_kernel<<<dim3(NN/256, 8), 256>>>(graph);
    colsum_fin_kernel<<<NN/256, 256>>>();
    build_S1_kernel<<<dim3(64, 64), dim3(32, 8)>>>(graph);
    build_S2_kernel<<<(NN*NN)/256, 256>>>(graph);
    adp_kernel<<<NN, 256>>>(nv1, nv2);

    build_x0_kernel<<<66560, 256>>>(inputs, hx);

    dim3 gfull(NN/128, XW/128);           // (16, 65)
    dim3 gproj(NN/128, 4096/128);         // (16, 32)
    dim3 ga2(NN/128, NN/128);             // (16, 16)
    dim3 xfull(XW/32, NN/32);
    dim3 xhalf(4096/32, NN/32);
    dim3 xsq(NN/32, NN/32);
    dim3 xblk(32, 8);

    // P(x0): s0->10, s2->11
    proj_multi_kernel<<<NN, 256, PROJ_SMEM>>>(0, 2, make_int4(0, 2, 0, 0), 10, gw);

    // m1 = S1 @ x0 -> X1
    xt_f16_kernel<<<xfull, xblk>>>(0, XW);
    gemm1_kernel<<<gfull, 256, GEMM1_SMEM>>>(0, 1, XW);

    // P(m1): s1->12, s2->13, s4->14
    proj_multi_kernel<<<NN, 256, PROJ_SMEM>>>(1, 3, make_int4(1, 2, 4, 0), 12, gw);

    // m3 = S2 @ m1 -> X2
    xt_f16_kernel<<<xfull, xblk>>>(1, XW);
    gemm1_kernel<<<gfull, 256, GEMM1_SMEM>>>(1, 2, XW);

    // P(m3): s3->15, s4->16, s5->17, s6->18
    proj_multi_kernel<<<NN, 256, PROJ_SMEM>>>(2, 4, make_int4(3, 4, 5, 6), 15, gw);

    // Q2 = S1 @ P2m1
    xt_f16_kernel<<<xhalf, xblk>>>(13, 4096);
    gemm1_kernel<<<gproj, 256, GEMM1_SMEM>>>(0, 19, 4096);
    // Q4 = S2 @ P4m3
    xt_f16_kernel<<<xhalf, xblk>>>(16, 4096);
    gemm1_kernel<<<gproj, 256, GEMM1_SMEM>>>(1, 20, 4096);
    // Q5 = A @ P5m3
    xt_f16_kernel<<<xhalf, xblk>>>(17, 4096);
    gemm1_kernel<<<gproj, 256, GEMM1_SMEM>>>(2, 21, 4096);
    // A2 = A @ A
    xt_f16_kernel<<<xsq, xblk>>>(3, NN);
    gemm1_kernel<<<ga2, 256, GEMM1_SMEM>>>(2, 22, NN);
    a2f_kernel<<<(NN*NN)/256, 256>>>();
    // Q6 = A2 @ P6m3
    xt_f16_kernel<<<xhalf, xblk>>>(18, 4096);
    gemm1_kernel<<<gproj, 256, GEMM1_SMEM>>>(3, 23, 4096);

    combine_kernel<<<(unsigned)(OUT1/256), 256>>>(gb);

    logits_kernel<<<BB*4, 256>>>(hx, R, aw, ab);
    weight_kernel<<<1, 64>>>();

    final_kernel<<<(BB*NN)/4, 256>>>(W, bbias, hx, R, out, write_hx);
    if (write_hx)
        hxcopy_kernel<<<(unsigned)((size_t)BB*3*NDD/256), 256>>>(hx, out);
}

// round 10
// speedup vs baseline: 5.9813x; 1.1526x over previous
#include <cuda_runtime.h>
#include <cuda_fp16.h>
#include <math.h>
#include <stdint.h>

#define NN 2048
#define BB 64
#define DD 64
#define ISZ 130
#define XW (ISZ*BB)          // 8320
#define NDD (NN*DD)          // 131072
#define OUT1 (BB*NDD)        // 8388608
#define HXPART ((size_t)BB*4*NDD)
#define FULL_OUT ((size_t)OUT1 + HXPART)
#define PSZ ((size_t)2048*4096)
#define QSZ ((size_t)4096*NN)

// ---------------- scratch ----------------
static __device__ __half g_S1f[(size_t)NN*NN];
static __device__ __half g_S2f[(size_t)NN*NN];
static __device__ __half g_Adf[(size_t)NN*NN];
static __device__ __half g_A2f[(size_t)NN*NN];
static __device__ float g_Ad[(size_t)NN*NN];
static __device__ float g_dinv1[NN];
static __device__ float g_dinv2[NN];
static __device__ float g_cspart[8*NN];
static __device__ float g_X0[(size_t)NN*XW];
static __device__ float g_X1[(size_t)NN*XW];
static __device__ float g_X2[(size_t)NN*XW];
static __device__ __half g_YTh[(size_t)XW*NN];   // YT of x0 / Ad
static __device__ __half g_YTb[(size_t)XW*NN];   // YT of m1 (gemm epilogue)
static __device__ __half g_YTq[4*QSZ];           // YT of the 4 leaf P slices
// P slots 10..23 (only 13,16,17,18 inputs; 19,20,21,23 Q outputs used)
static __device__ float g_P[14*PSZ];
static __device__ float g_gc[(size_t)BB*NN*DD];
static __device__ float g_logits[BB*4];
static __device__ float g_wt[BB*4];

__device__ __forceinline__ float* bufAny(int s) {
    if (s == 0) return g_X0;
    if (s == 1) return g_X1;
    if (s == 2) return g_X2;
    if (s == 3) return g_Ad;
    return g_P + (size_t)(s - 10) * PSZ;
}

// ---------------- PTX helpers ----------------
__device__ __forceinline__ uint32_t smem_u32(const void* p) {
    uint32_t a;
    asm("{ .reg .u64 t; cvta.to.shared.u64 t, %1; cvt.u32.u64 %0, t; }" : "=r"(a) : "l"(p));
    return a;
}
__device__ __forceinline__ void cp16(uint32_t dst, const void* src) {
    asm volatile("cp.async.cg.shared.global [%0], [%1], 16;" :: "r"(dst), "l"(src) : "memory");
}
__device__ __forceinline__ void cp_commit() { asm volatile("cp.async.commit_group;" ::: "memory"); }
__device__ __forceinline__ void cp_wait2() { asm volatile("cp.async.wait_group 2;" ::: "memory"); }
__device__ __forceinline__ void cp_wait0() { asm volatile("cp.async.wait_group 0;" ::: "memory"); }

__device__ __forceinline__ void ldm_x4(uint32_t* r, uint32_t addr) {
    asm volatile("ldmatrix.sync.aligned.m8n8.x4.shared.b16 {%0,%1,%2,%3}, [%4];"
                 : "=r"(r[0]), "=r"(r[1]), "=r"(r[2]), "=r"(r[3]) : "r"(addr));
}
__device__ __forceinline__ void mma16816h(float* c, const uint32_t* a, uint32_t b0, uint32_t b1) {
    asm volatile(
        "mma.sync.aligned.m16n8k16.row.col.f32.f16.f16.f32 "
        "{%0,%1,%2,%3}, {%4,%5,%6,%7}, {%8,%9}, {%0,%1,%2,%3};"
        : "+f"(c[0]), "+f"(c[1]), "+f"(c[2]), "+f"(c[3])
        : "r"(a[0]), "r"(a[1]), "r"(a[2]), "r"(a[3]), "r"(b0), "r"(b1));
}

// ---------------- support construction ----------------
__global__ void rowsum_dinv_kernel(const float* __restrict__ g) {
    int row = blockIdx.x;
    int tid = threadIdx.x;
    float s = 0.f;
    for (int j = tid; j < NN; j += 256) s += g[(size_t)row*NN + j];
    for (int o = 16; o; o >>= 1) s += __shfl_down_sync(0xffffffffu, s, o);
    __shared__ float red[8];
    if ((tid & 31) == 0) red[tid >> 5] = s;
    __syncthreads();
    if (tid == 0) {
        float t = 0.f;
        #pragma unroll
        for (int w = 0; w < 8; w++) t += red[w];
        g_dinv1[row] = 1.f / (1.f + t);
    }
}

__global__ void colsum_part_kernel(const float* __restrict__ g) {
    int col = blockIdx.x * 256 + threadIdx.x;
    int r0 = blockIdx.y * 256;
    float s = 0.f;
    #pragma unroll 8
    for (int r = 0; r < 256; r++) s += g[(size_t)(r0 + r)*NN + col];
    g_cspart[blockIdx.y*NN + col] = s;
}

__global__ void colsum_fin_kernel() {
    int col = blockIdx.x * 256 + threadIdx.x;
    float s = 0.f;
    #pragma unroll
    for (int y = 0; y < 8; y++) s += g_cspart[y*NN + col];
    g_dinv2[col] = 1.f / (1.f + s);
}

__global__ void build_S1_kernel(const float* __restrict__ g) {
    __shared__ float t[32][33];
    int bi = blockIdx.x * 32;
    int bj = blockIdx.y * 32;
    for (int r = threadIdx.y; r < 32; r += 8)
        t[r][threadIdx.x] = g[(size_t)(bj + r)*NN + bi + threadIdx.x];
    __syncthreads();
    for (int r = threadIdx.y; r < 32; r += 8) {
        int i = bi + r, j = bj + threadIdx.x;
        float dv = g_dinv1[j];
        float v = t[threadIdx.x][r] * dv;
        if (i == j) v += dv;
        g_S1f[(size_t)i*NN + j] = __float2half(v);
    }
}

__global__ void build_S2_kernel(const float* __restrict__ g) {
    int idx = blockIdx.x * 256 + threadIdx.x;
    int i = idx >> 11, j = idx & 2047;
    float v = (g[idx] + (i == j ? 1.f : 0.f)) * g_dinv2[j];
    g_S2f[idx] = __float2half(v);
}

__global__ void adp_kernel(const float* __restrict__ nv1, const float* __restrict__ nv2) {
    int i = blockIdx.x;
    int tid = threadIdx.x;
    __shared__ float v1[10];
    __shared__ float red[40];
    if (tid < 10) v1[tid] = nv1[i*10 + tid];
    __syncthreads();
    float p[8];
    float mx = 0.f;
    #pragma unroll
    for (int c = 0; c < 8; c++) {
        int j = tid + c*256;
        float s = 0.f;
        #pragma unroll
        for (int t = 0; t < 10; t++) s += v1[t] * nv2[t*NN + j];
        s = s > 0.f ? s : 0.f;
        p[c] = s;
        mx = fmaxf(mx, s);
    }
    for (int o = 16; o; o >>= 1) mx = fmaxf(mx, __shfl_xor_sync(0xffffffffu, mx, o));
    if ((tid & 31) == 0) red[tid >> 5] = mx;
    __syncthreads();
    if (tid == 0) {
        float m = red[0];
        #pragma unroll
        for (int w = 1; w < 8; w++) m = fmaxf(m, red[w]);
        red[32] = m;
    }
    __syncthreads();
    mx = red[32];
    float sum = 0.f;
    #pragma unroll
    for (int c = 0; c < 8; c++) { float e = expf(p[c] - mx); p[c] = e; sum += e; }
    for (int o = 16; o; o >>= 1) sum += __shfl_xor_sync(0xffffffffu, sum, o);
    if ((tid & 31) == 0) red[16 + (tid >> 5)] = sum;
    __syncthreads();
    if (tid == 0) {
        float t = 0.f;
        #pragma unroll
        for (int w = 0; w < 8; w++) t += red[16 + w];
        red[33] = 1.f / t;
    }
    __syncthreads();
    float inv = red[33];
    #pragma unroll
    for (int c = 0; c < 8; c++) {
        float v = p[c] * inv;
        size_t idx = (size_t)i*NN + tid + c*256;
        g_Ad[idx] = v;
        g_Adf[idx] = __float2half(v);
    }
}

// transpose fp16: X fp32 [2048 x W] -> g_YTh [W x 2048]
__global__ void xt_f16_kernel(int selX, int W) {
    const float* X = bufAny(selX);
    __shared__ float t[32][33];
    int c0 = blockIdx.x * 32;
    int j0 = blockIdx.y * 32;
    int tx = threadIdx.x;
    for (int r = threadIdx.y; r < 32; r += 8)
        t[r][tx] = X[(size_t)(j0 + r)*W + c0 + tx];
    __syncthreads();
    for (int r = threadIdx.y; r < 32; r += 8)
        g_YTh[(size_t)(c0 + r)*NN + j0 + tx] = __float2half(t[tx][r]);
}

// batched transpose of 4 leaf P slices -> g_YTq quadrants
__global__ void xt_f16_batch_kernel() {
    int q = blockIdx.z;
    int slot = (q == 0) ? 13 : (q == 1) ? 16 : (q == 2) ? 17 : 18;
    const float* X = g_P + (size_t)(slot - 10)*PSZ;
    __half* Y = g_YTq + (size_t)q*QSZ;
    __shared__ float t[32][33];
    int c0 = blockIdx.x * 32;
    int j0 = blockIdx.y * 32;
    int tx = threadIdx.x;
    for (int r = threadIdx.y; r < 32; r += 8)
        t[r][tx] = X[(size_t)(j0 + r)*4096 + c0 + tx];
    __syncthreads();
    for (int r = threadIdx.y; r < 32; r += 8)
        Y[(size_t)(c0 + r)*NN + j0 + tx] = __float2half(t[tx][r]);
}

// ---------------- x0 build ----------------
__global__ void build_x0_kernel(const float* __restrict__ inputs, const float* __restrict__ hx) {
    size_t total = (size_t)NN * XW;
    for (size_t idx = (size_t)blockIdx.x*256 + threadIdx.x; idx < total; idx += (size_t)gridDim.x*256) {
        int n = (int)(idx / XW);
        int c = (int)(idx - (size_t)n*XW);
        int i = c >> 6, b = c & 63;
        float v;
        if (i < 2) {
            v = inputs[(size_t)b*(NN*2) + n*2 + i];
        } else {
            int q = i - 2;
            int kk = (q < 64) ? 3 : 2;
            int d = q & 63;
            v = hx[(size_t)((b << 2) + kk)*NDD + (size_t)n*64 + d];
        }
        g_X0[idx] = v;
    }
}

// ---------------- multi-slice projection + static gc accumulation ----------------
#define PROJ_SMEM (2*XW*4)    // 66560
__global__ void __launch_bounds__(256) proj_multi_kernel(int selX, int cnt, int4 sl,
                                                         int4 outSlot, float4 coef, int initMode,
                                                         const float* __restrict__ gw,
                                                         const float* __restrict__ gb) {
    extern __shared__ float ps[];
    float* sx = ps;
    float* sw = ps + XW;
    const float* X = bufAny(selX);
    int n = blockIdx.x;
    int tid = threadIdx.x;
    for (int t = tid; t < XW/4; t += 256)
        ((float4*)sx)[t] = ((const float4*)(X + (size_t)n*XW))[t];
    int ss[4] = {sl.x, sl.y, sl.z, sl.w};
    int os[4] = {outSlot.x, outSlot.y, outSlot.z, outSlot.w};
    float cf[4] = {coef.x, coef.y, coef.z, coef.w};
    int tb = tid >> 4;
    int td = tid & 15;
    float sacc[4][4];
    #pragma unroll
    for (int bb = 0; bb < 4; bb++)
        #pragma unroll
        for (int dd = 0; dd < 4; dd++) sacc[bb][dd] = 0.f;
    for (int q = 0; q < cnt; q++) {
        int s = ss[q];
        __syncthreads();
        for (int t = tid; t < ISZ*16; t += 256) {
            int i = t >> 4, dq = t & 15;
            ((float4*)sw)[i*16 + dq] = ((const float4*)gw)[((size_t)i*7 + s)*16 + dq];
        }
        __syncthreads();
        float acc[4][4];
        #pragma unroll
        for (int bb = 0; bb < 4; bb++)
            #pragma unroll
            for (int dd = 0; dd < 4; dd++) acc[bb][dd] = 0.f;
        for (int i = 0; i < ISZ; i++) {
            float4 xa = ((const float4*)sx)[i*16 + tb];
            float4 wv = ((const float4*)sw)[i*16 + td];
            float xs[4] = {xa.x, xa.y, xa.z, xa.w};
            float ws[4] = {wv.x, wv.y, wv.z, wv.w};
            #pragma unroll
            for (int bb = 0; bb < 4; bb++)
                #pragma unroll
                for (int dd = 0; dd < 4; dd++) acc[bb][dd] += xs[bb] * ws[dd];
        }
        if (os[q] >= 0) {
            float* P = g_P + (size_t)(os[q] - 10)*PSZ + (size_t)n*4096;
            #pragma unroll
            for (int bb = 0; bb < 4; bb++)
                *(float4*)&P[(size_t)(tb*4 + bb)*64 + td*4] =
                    make_float4(acc[bb][0], acc[bb][1], acc[bb][2], acc[bb][3]);
        }
        float c = cf[q];
        if (c != 0.f) {
            #pragma unroll
            for (int bb = 0; bb < 4; bb++)
                #pragma unroll
                for (int dd = 0; dd < 4; dd++) sacc[bb][dd] += c * acc[bb][dd];
        }
    }
    #pragma unroll
    for (int bb = 0; bb < 4; bb++) {
        int b = tb*4 + bb;
        size_t gidx = ((size_t)b*NN + n)*64 + td*4;
        float4 v = make_float4(sacc[bb][0], sacc[bb][1], sacc[bb][2], sacc[bb][3]);
        if (initMode) {
            v.x += gb[td*4+0]; v.y += gb[td*4+1]; v.z += gb[td*4+2]; v.w += gb[td*4+3];
        } else {
            float4 o = *(const float4*)&g_gc[gidx];
            v.x += o.x; v.y += o.y; v.z += o.z; v.w += o.w;
        }
        *(float4*)&g_gc[gidx] = v;
    }
}

// ---------------- single-product fp16 GEMM ----------------
// mode: 0 = fp32 C only; 1 = fp32 C + transposed fp16 -> g_YTb; 2 = fp16 row-major -> g_A2f only
#define KC 32
#define TROW 80
#define TILEB (128*TROW)
#define STAGEB1 (2*TILEB)       // 20480
#define GEMM1_SMEM (4*STAGEB1)  // 81920
#define NSTG 64

__global__ void __launch_bounds__(256, 2)
gemm1_kernel(int selA, int selB, int selC, int W, int mode, int batch) {
    extern __shared__ char smem[];
    uint32_t sb = smem_u32(smem);
    int tid = threadIdx.x;
    int wid = tid >> 5;
    int lane = tid & 31;

    if (batch) {
        int bz = blockIdx.z;
        selA = bz;                      // 0=S1 1=S2 2=Ad 3=A2
        selB = 2 + bz;
        selC = (bz == 0) ? 19 : (bz == 1) ? 20 : (bz == 2) ? 21 : 23;
    }
    const __half* Af = selA == 0 ? g_S1f : (selA == 1 ? g_S2f : (selA == 2 ? g_Adf : g_A2f));
    const __half* Bf = selB == 0 ? g_YTh : (selB == 1 ? g_YTb : g_YTq + (size_t)(selB - 2)*QSZ);
    float* C = bufAny(selC);

    int mBase = blockIdx.x * 128;
    int nBase = blockIdx.y * 128;

    const __half* src[4];
    uint32_t dst[4];
    #pragma unroll
    for (int i = 0; i < 4; i++) {
        int c = tid + i*256;
        int tile = c >> 9;
        int q = c & 511;
        int row = q >> 2, col = q & 3;
        dst[i] = (uint32_t)(tile*TILEB + row*TROW + col*16);
        const __half* base = (tile == 0) ? Af + (size_t)(mBase + row) * NN
                                         : Bf + (size_t)(nBase + row) * NN;
        src[i] = base + col*8;
    }

    #pragma unroll
    for (int s = 0; s < 3; s++) {
        uint32_t so = sb + (uint32_t)(s * STAGEB1);
        #pragma unroll
        for (int i = 0; i < 4; i++) cp16(so + dst[i], src[i] + s*KC);
        cp_commit();
    }

    float acc[4][4][4];
    #pragma unroll
    for (int mf = 0; mf < 4; mf++)
        #pragma unroll
        for (int nf = 0; nf < 4; nf++)
            #pragma unroll
            for (int e = 0; e < 4; e++) acc[mf][nf][e] = 0.f;

    int mw = wid & 1;
    int nw = wid >> 1;
    int a_row = lane & 15;
    int a_colb = (lane >> 4) * 16;
    int b_row = ((lane >> 4) & 1) * 8 + (lane & 7);
    int b_colb = ((lane >> 3) & 1) * 16;

    uint32_t aOff = (uint32_t)((mw*64 + a_row) * TROW) + (uint32_t)a_colb;
    uint32_t bOff = (uint32_t)TILEB + (uint32_t)((nw*32 + b_row) * TROW) + (uint32_t)b_colb;

    for (int s = 0; s < NSTG; s++) {
        cp_wait2();
        __syncthreads();
        int sn = s + 3;
        if (sn < NSTG) {
            uint32_t so2 = sb + (uint32_t)((sn & 3) * STAGEB1);
            #pragma unroll
            for (int i = 0; i < 4; i++) cp16(so2 + dst[i], src[i] + sn*KC);
        }
        cp_commit();

        uint32_t so = sb + (uint32_t)((s & 3) * STAGEB1);
        #pragma unroll
        for (int ks = 0; ks < 2; ks++) {
            uint32_t kb = (uint32_t)(ks*32);
            uint32_t ar[4][4], br[2][4];
            #pragma unroll
            for (int mf = 0; mf < 4; mf++)
                ldm_x4(ar[mf], so + aOff + (uint32_t)(mf*16*TROW) + kb);
            #pragma unroll
            for (int bg = 0; bg < 2; bg++)
                ldm_x4(br[bg], so + bOff + (uint32_t)(bg*16*TROW) + kb);
            #pragma unroll
            for (int mf = 0; mf < 4; mf++) {
                #pragma unroll
                for (int bg = 0; bg < 2; bg++) {
                    mma16816h(acc[mf][bg*2+0], ar[mf], br[bg][0], br[bg][1]);
                    mma16816h(acc[mf][bg*2+1], ar[mf], br[bg][2], br[bg][3]);
                }
            }
        }
    }

    int gid = lane >> 2, tg = lane & 3;

    if (mode != 2) {
        #pragma unroll
        for (int mf = 0; mf < 4; mf++) {
            int row0 = mBase + mw*64 + mf*16 + gid;
            #pragma unroll
            for (int nf = 0; nf < 4; nf++) {
                int col = nBase + nw*32 + nf*8 + tg*2;
                size_t i0 = (size_t)row0 * W + col;
                size_t i1 = i0 + (size_t)8 * W;
                *(float2*)&C[i0] = make_float2(acc[mf][nf][0], acc[mf][nf][1]);
                *(float2*)&C[i1] = make_float2(acc[mf][nf][2], acc[mf][nf][3]);
            }
        }
    } else {
        // fp16 row-major into g_A2f
        #pragma unroll
        for (int mf = 0; mf < 4; mf++) {
            int row0 = mBase + mw*64 + mf*16 + gid;
            #pragma unroll
            for (int nf = 0; nf < 4; nf++) {
                int col = nBase + nw*32 + nf*8 + tg*2;
                __half2 v0 = __floats2half2_rn(acc[mf][nf][0], acc[mf][nf][1]);
                __half2 v1 = __floats2half2_rn(acc[mf][nf][2], acc[mf][nf][3]);
                *(__half2*)&g_A2f[(size_t)row0 * NN + col] = v0;
                *(__half2*)&g_A2f[(size_t)(row0 + 8) * NN + col] = v1;
            }
        }
    }

    if (mode == 1) {
        // transposed fp16 tile -> g_YTb via smem staging
        cp_wait0();
        __syncthreads();
        __half* st = (__half*)smem;     // pitch 136 halves
        #pragma unroll
        for (int mf = 0; mf < 4; mf++) {
            #pragma unroll
            for (int nf = 0; nf < 4; nf++) {
                int r = mw*64 + mf*16 + gid;
                int c = nw*32 + nf*8 + tg*2;
                st[(c+0)*136 + r]     = __float2half(acc[mf][nf][0]);
                st[(c+1)*136 + r]     = __float2half(acc[mf][nf][1]);
                st[(c+0)*136 + r + 8] = __float2half(acc[mf][nf][2]);
                st[(c+1)*136 + r + 8] = __float2half(acc[mf][nf][3]);
            }
        }
        __syncthreads();
        // FIX: 16 segments of 8 halves each cover all 128 rows per column
        for (int t = tid; t < 128*16; t += 256) {
            int c = t >> 4, seg = t & 15;
            uint4 v = *(const uint4*)&st[c*136 + seg*8];
            *(uint4*)&g_YTb[(size_t)(nBase + c)*NN + mBase + seg*8] = v;
        }
    }
}

// ---------------- attention ----------------
__global__ void logits_kernel(const float* __restrict__ hx, const float* __restrict__ R,
                              const float* __restrict__ aw, const float* __restrict__ ab) {
    int bk = blockIdx.x;
    int k = bk & 3;
    int tid = threadIdx.x;
    const float* hp = hx + (size_t)bk * NDD;
    const float* rp = R + (size_t)k * NDD;
    float s = 0.f;
    for (int t = tid; t < NDD; t += 256) s += (hp[t] + rp[t]) * aw[t];
    for (int o = 16; o; o >>= 1) s += __shfl_down_sync(0xffffffffu, s, o);
    __shared__ float red[8];
    if ((tid & 31) == 0) red[tid >> 5] = s;
    __syncthreads();
    if (tid == 0) {
        float t = 0.f;
        #pragma unroll
        for (int w = 0; w < 8; w++) t += red[w];
        g_logits[bk] = t + ab[0];
    }
}

__global__ void weight_kernel() {
    int b = threadIdx.x;
    if (b < BB) {
        float l0 = g_logits[b*4+0], l1 = g_logits[b*4+1], l2 = g_logits[b*4+2], l3 = g_logits[b*4+3];
        float m = fmaxf(fmaxf(l0, l1), fmaxf(l2, l3));
        float e0 = expf(l0 - m), e1 = expf(l1 - m), e2 = expf(l2 - m), e3 = expf(l3 - m);
        float inv = 1.f / (e0 + e1 + e2 + e3);
        g_wt[b*4+0] = e0 * inv; g_wt[b*4+1] = e1 * inv;
        g_wt[b*4+2] = e2 * inv; g_wt[b*4+3] = e3 * inv;
    }
}

// ---------------- output (fused combine) ----------------
__global__ void __launch_bounds__(256) final_kernel(const float* __restrict__ W,
                                                    const float* __restrict__ bbias,
                                                    const float* __restrict__ hx,
                                                    const float* __restrict__ R,
                                                    float* __restrict__ out, int write_hx) {
    __shared__ float sW[64*64];
    __shared__ float sg[4*64];
    int tid = threadIdx.x;
    int r0 = blockIdx.x * 4;
    for (int t = tid; t < 4096; t += 256) sW[t] = W[t];
    {
        int row = r0 + (tid >> 6);
        int d = tid & 63;
        int n = row & 2047;
        int b = row >> 11;
        size_t p = (size_t)n*4096 + (size_t)(b*64 + d);
        float v = g_gc[(size_t)r0*64 + tid]
                + 2.f*g_P[9*PSZ + p]      // Q2
                + 2.f*g_P[10*PSZ + p]     // Q4
                + g_P[11*PSZ + p]         // Q5
                + g_P[13*PSZ + p];        // Q6
        sg[tid] = v > 0.f ? v : 0.01f * v;
    }
    __syncthreads();
    int rl = tid >> 6;
    int d = tid & 63;
    int r = r0 + rl;
    int b = r >> 11;
    int n = r & 2047;
    float acc = 0.f;
    #pragma unroll
    for (int e = 0; e < 64; e++) acc += sg[rl*64 + e] * sW[e*64 + d];
    float att = 0.f;
    #pragma unroll
    for (int k = 0; k < 4; k++) {
        float xv = hx[(size_t)((b << 2) + k)*NDD + (size_t)n*64 + d] + R[(size_t)k*NDD + (size_t)n*64 + d];
        att += xv * g_wt[b*4 + k];
    }
    float o = acc + bbias[(size_t)n*64 + d] + att;
    out[(size_t)b*NDD + (size_t)n*64 + d] = o;
    if (write_hx)
        out[(size_t)OUT1 + (size_t)((b << 2) + 3)*NDD + (size_t)n*64 + d] = o;
}

__global__ void hxcopy_kernel(const float* __restrict__ hx, float* __restrict__ out) {
    size_t idx = (size_t)blockIdx.x * 256 + threadIdx.x;
    int b = (int)(idx / (3*(size_t)NDD));
    size_t rem = idx - (size_t)b * (3*(size_t)NDD);
    int kk = (int)(rem / NDD);
    size_t j = rem - (size_t)kk * NDD;
    out[(size_t)OUT1 + (size_t)(b*4 + kk)*NDD + j] = hx[(size_t)(b*4 + kk + 1)*NDD + j];
}

// ---------------- launch ----------------
extern "C" void kernel_launch(void* const* d_in, const int* in_sizes, int n_in,
                              void* d_out, int out_size) {
    const float* inputs = (const float*)d_in[0];
    const float* hx     = (const float*)d_in[1];
    const float* graph  = (const float*)d_in[2];
    const float* nv1    = (const float*)d_in[3];
    const float* nv2    = (const float*)d_in[4];
    const float* W      = (const float*)d_in[5];
    const float* bbias  = (const float*)d_in[6];
    const float* R      = (const float*)d_in[7];
    const float* gw     = (const float*)d_in[8];
    const float* gb     = (const float*)d_in[9];
    const float* aw     = (const float*)d_in[10];
    const float* ab     = (const float*)d_in[11];
    float* out = (float*)d_out;

    int write_hx = ((size_t)out_size >= FULL_OUT) ? 1 : 0;

    cudaFuncSetAttribute(gemm1_kernel, cudaFuncAttributeMaxDynamicSharedMemorySize, GEMM1_SMEM);
    cudaFuncSetAttribute(proj_multi_kernel, cudaFuncAttributeMaxDynamicSharedMemorySize, PROJ_SMEM);

    rowsum_dinv_kernel<<<NN, 256>>>(graph);
    colsum_part_kernel<<<dim3(NN/256, 8), 256>>>(graph);
    colsum_fin_kernel<<<NN/256, 256>>>();
    build_S1_kernel<<<dim3(64, 64), dim3(32, 8)>>>(graph);
    build_S2_kernel<<<(NN*NN)/256, 256>>>(graph);
    adp_kernel<<<NN, 256>>>(nv1, nv2);

    dim3 gfull(NN/128, XW/128);
    dim3 ga2(NN/128, NN/128);
    dim3 gleaf(NN/128, 4096/128, 4);
    dim3 xfull(XW/32, NN/32);
    dim3 xsq(NN/32, NN/32);
    dim3 xqb(4096/32, NN/32, 4);
    dim3 xblk(32, 8);

    // A2 = A @ A (depends only on adp) -> g_A2f (fp16 epilogue)
    xt_f16_kernel<<<xsq, xblk>>>(3, NN);
    gemm1_kernel<<<ga2, 256, GEMM1_SMEM>>>(2, 0, 2, NN, 2, 0);

    build_x0_kernel<<<66560, 256>>>(inputs, hx);

    // P(x0): static gc init = gb + P0 - P2x0
    proj_multi_kernel<<<NN, 256, PROJ_SMEM>>>(0, 2, make_int4(0, 2, 0, 0),
        make_int4(-1, -1, -1, -1), make_float4(1.f, -1.f, 0.f, 0.f), 1, gw, gb);

    // m1 = S1 @ x0 -> X1 (+ YTb fp16 transposed epilogue)
    xt_f16_kernel<<<xfull, xblk>>>(0, XW);
    gemm1_kernel<<<gfull, 256, GEMM1_SMEM>>>(0, 0, 1, XW, 1, 0);

    // P(m1): gc += P1 - P4m1 ; write P2m1 -> slot 13
    proj_multi_kernel<<<NN, 256, PROJ_SMEM>>>(1, 3, make_int4(1, 2, 4, 0),
        make_int4(-1, 13, -1, -1), make_float4(1.f, 0.f, -1.f, 0.f), 0, gw, gb);

    // m3 = S2 @ m1 -> X2 (B = YTb)
    gemm1_kernel<<<gfull, 256, GEMM1_SMEM>>>(1, 1, 2, XW, 0, 0);

    // P(m3): gc += P3 - P6m3 ; write P4m3->16, P5m3->17, P6m3->18
    proj_multi_kernel<<<NN, 256, PROJ_SMEM>>>(2, 4, make_int4(3, 4, 5, 6),
        make_int4(-1, 16, 17, 18), make_float4(1.f, 0.f, 0.f, -1.f), 0, gw, gb);

    // batched transposes of the 4 leaf slices
    xt_f16_batch_kernel<<<xqb, xblk>>>();
    // batched leaf GEMMs: Q2, Q4, Q5, Q6
    gemm1_kernel<<<gleaf, 256, GEMM1_SMEM>>>(0, 0, 0, 4096, 0, 1);

    logits_kernel<<<BB*4, 256>>>(hx, R, aw, ab);
    weight_kernel<<<1, 64>>>();

    final_kernel<<<(BB*NN)/4, 256>>>(W, bbias, hx, R, out, write_hx);
    if (write_hx)
        hxcopy_kernel<<<(unsigned)((size_t)BB*3*NDD/256), 256>>>(hx, out);
}

// round 12
// speedup vs baseline: 6.9619x; 1.1639x over previous
#include <cuda_runtime.h>
#include <cuda_fp16.h>
#include <math.h>
#include <stdint.h>

#define NN 2048
#define BB 64
#define DD 64
#define ISZ 130
#define XW (ISZ*BB)          // 8320
#define NDD (NN*DD)          // 131072
#define OUT1 (BB*NDD)        // 8388608
#define HXPART ((size_t)BB*4*NDD)
#define FULL_OUT ((size_t)OUT1 + HXPART)
#define PSZ ((size_t)2048*4096)
#define QSZ ((size_t)4096*NN)
#define KP 144               // padded proj K
#define MP ((size_t)NN*64)   // 131072 proj rows

// ---------------- scratch ----------------
static __device__ __half g_S1f[(size_t)NN*NN];
static __device__ __half g_S2f[(size_t)NN*NN];
static __device__ __half g_Adf[(size_t)NN*NN];
static __device__ __half g_A2f[(size_t)NN*NN];
static __device__ float g_Ad[(size_t)NN*NN];
static __device__ float g_dinv1[NN];
static __device__ float g_dinv2[NN];
static __device__ float g_cspart[8*NN];
static __device__ float g_X0[(size_t)NN*XW];
static __device__ float g_X1[(size_t)NN*XW];
static __device__ float g_X2[(size_t)NN*XW];
static __device__ __half g_YTh[(size_t)XW*NN];   // YT of x0 / Ad
static __device__ __half g_YTb[(size_t)XW*NN];   // YT of m1 (gemm epilogue)
static __device__ __half g_YTq[4*QSZ];           // YT of the 4 leaf P slices
static __device__ __half g_Xp[MP*KP];            // proj A operand (reused per source)
static __device__ __half g_GWT[7*64*KP];         // 7 groups of transposed gw slices
// P slots 10..23 (13,16,17,18 leaf inputs; 19,20,21,23 Q outputs)
static __device__ float g_P[14*PSZ];
static __device__ float g_gc[(size_t)NN*4096];   // layout [n][b*64+d]
static __device__ float g_logits[BB*4];
static __device__ float g_wt[BB*4];

__device__ __forceinline__ float* bufAny(int s) {
    if (s == 0) return g_X0;
    if (s == 1) return g_X1;
    if (s == 2) return g_X2;
    if (s == 3) return g_Ad;
    return g_P + (size_t)(s - 10) * PSZ;
}

// ---------------- PTX helpers ----------------
__device__ __forceinline__ uint32_t smem_u32(const void* p) {
    uint32_t a;
    asm("{ .reg .u64 t; cvta.to.shared.u64 t, %1; cvt.u32.u64 %0, t; }" : "=r"(a) : "l"(p));
    return a;
}
__device__ __forceinline__ void cp16(uint32_t dst, const void* src) {
    asm volatile("cp.async.cg.shared.global [%0], [%1], 16;" :: "r"(dst), "l"(src) : "memory");
}
__device__ __forceinline__ void cp_commit() { asm volatile("cp.async.commit_group;" ::: "memory"); }
__device__ __forceinline__ void cp_wait2() { asm volatile("cp.async.wait_group 2;" ::: "memory"); }
__device__ __forceinline__ void cp_wait0() { asm volatile("cp.async.wait_group 0;" ::: "memory"); }

__device__ __forceinline__ void ldm_x4(uint32_t* r, uint32_t addr) {
    asm volatile("ldmatrix.sync.aligned.m8n8.x4.shared.b16 {%0,%1,%2,%3}, [%4];"
                 : "=r"(r[0]), "=r"(r[1]), "=r"(r[2]), "=r"(r[3]) : "r"(addr));
}
__device__ __forceinline__ void mma16816h(float* c, const uint32_t* a, uint32_t b0, uint32_t b1) {
    asm volatile(
        "mma.sync.aligned.m16n8k16.row.col.f32.f16.f16.f32 "
        "{%0,%1,%2,%3}, {%4,%5,%6,%7}, {%8,%9}, {%0,%1,%2,%3};"
        : "+f"(c[0]), "+f"(c[1]), "+f"(c[2]), "+f"(c[3])
        : "r"(a[0]), "r"(a[1]), "r"(a[2]), "r"(a[3]), "r"(b0), "r"(b1));
}

// ---------------- support construction ----------------
__global__ void rowsum_dinv_kernel(const float* __restrict__ g) {
    int row = blockIdx.x;
    int tid = threadIdx.x;
    float s = 0.f;
    for (int j = tid; j < NN; j += 256) s += g[(size_t)row*NN + j];
    for (int o = 16; o; o >>= 1) s += __shfl_down_sync(0xffffffffu, s, o);
    __shared__ float red[8];
    if ((tid & 31) == 0) red[tid >> 5] = s;
    __syncthreads();
    if (tid == 0) {
        float t = 0.f;
        #pragma unroll
        for (int w = 0; w < 8; w++) t += red[w];
        g_dinv1[row] = 1.f / (1.f + t);
    }
}

__global__ void colsum_part_kernel(const float* __restrict__ g) {
    int col = blockIdx.x * 256 + threadIdx.x;
    int r0 = blockIdx.y * 256;
    float s = 0.f;
    #pragma unroll 8
    for (int r = 0; r < 256; r++) s += g[(size_t)(r0 + r)*NN + col];
    g_cspart[blockIdx.y*NN + col] = s;
}

__global__ void colsum_fin_kernel() {
    int col = blockIdx.x * 256 + threadIdx.x;
    float s = 0.f;
    #pragma unroll
    for (int y = 0; y < 8; y++) s += g_cspart[y*NN + col];
    g_dinv2[col] = 1.f / (1.f + s);
}

__global__ void build_S1_kernel(const float* __restrict__ g) {
    __shared__ float t[32][33];
    int bi = blockIdx.x * 32;
    int bj = blockIdx.y * 32;
    for (int r = threadIdx.y; r < 32; r += 8)
        t[r][threadIdx.x] = g[(size_t)(bj + r)*NN + bi + threadIdx.x];
    __syncthreads();
    for (int r = threadIdx.y; r < 32; r += 8) {
        int i = bi + r, j = bj + threadIdx.x;
        float dv = g_dinv1[j];
        float v = t[threadIdx.x][r] * dv;
        if (i == j) v += dv;
        g_S1f[(size_t)i*NN + j] = __float2half(v);
    }
}

__global__ void build_S2_kernel(const float* __restrict__ g) {
    int idx = blockIdx.x * 256 + threadIdx.x;
    int i = idx >> 11, j = idx & 2047;
    float v = (g[idx] + (i == j ? 1.f : 0.f)) * g_dinv2[j];
    g_S2f[idx] = __float2half(v);
}

__global__ void adp_kernel(const float* __restrict__ nv1, const float* __restrict__ nv2) {
    int i = blockIdx.x;
    int tid = threadIdx.x;
    __shared__ float v1[10];
    __shared__ float red[40];
    if (tid < 10) v1[tid] = nv1[i*10 + tid];
    __syncthreads();
    float p[8];
    float mx = 0.f;
    #pragma unroll
    for (int c = 0; c < 8; c++) {
        int j = tid + c*256;
        float s = 0.f;
        #pragma unroll
        for (int t = 0; t < 10; t++) s += v1[t] * nv2[t*NN + j];
        s = s > 0.f ? s : 0.f;
        p[c] = s;
        mx = fmaxf(mx, s);
    }
    for (int o = 16; o; o >>= 1) mx = fmaxf(mx, __shfl_xor_sync(0xffffffffu, mx, o));
    if ((tid & 31) == 0) red[tid >> 5] = mx;
    __syncthreads();
    if (tid == 0) {
        float m = red[0];
        #pragma unroll
        for (int w = 1; w < 8; w++) m = fmaxf(m, red[w]);
        red[32] = m;
    }
    __syncthreads();
    mx = red[32];
    float sum = 0.f;
    #pragma unroll
    for (int c = 0; c < 8; c++) { float e = expf(p[c] - mx); p[c] = e; sum += e; }
    for (int o = 16; o; o >>= 1) sum += __shfl_xor_sync(0xffffffffu, sum, o);
    if ((tid & 31) == 0) red[16 + (tid >> 5)] = sum;
    __syncthreads();
    if (tid == 0) {
        float t = 0.f;
        #pragma unroll
        for (int w = 0; w < 8; w++) t += red[16 + w];
        red[33] = 1.f / t;
    }
    __syncthreads();
    float inv = red[33];
    #pragma unroll
    for (int c = 0; c < 8; c++) {
        float v = p[c] * inv;
        size_t idx = (size_t)i*NN + tid + c*256;
        g_Ad[idx] = v;
        g_Adf[idx] = __float2half(v);
    }
}

// transpose fp16: X fp32 [2048 x W] -> g_YTh [W x 2048]
__global__ void xt_f16_kernel(int selX, int W) {
    const float* X = bufAny(selX);
    __shared__ float t[32][33];
    int c0 = blockIdx.x * 32;
    int j0 = blockIdx.y * 32;
    int tx = threadIdx.x;
    for (int r = threadIdx.y; r < 32; r += 8)
        t[r][tx] = X[(size_t)(j0 + r)*W + c0 + tx];
    __syncthreads();
    for (int r = threadIdx.y; r < 32; r += 8)
        g_YTh[(size_t)(c0 + r)*NN + j0 + tx] = __float2half(t[tx][r]);
}

// batched transpose of 4 leaf P slices -> g_YTq quadrants
__global__ void xt_f16_batch_kernel() {
    int q = blockIdx.z;
    int slot = (q == 0) ? 13 : (q == 1) ? 16 : (q == 2) ? 17 : 18;
    const float* X = g_P + (size_t)(slot - 10)*PSZ;
    __half* Y = g_YTq + (size_t)q*QSZ;
    __shared__ float t[32][33];
    int c0 = blockIdx.x * 32;
    int j0 = blockIdx.y * 32;
    int tx = threadIdx.x;
    for (int r = threadIdx.y; r < 32; r += 8)
        t[r][tx] = X[(size_t)(j0 + r)*4096 + c0 + tx];
    __syncthreads();
    for (int r = threadIdx.y; r < 32; r += 8)
        Y[(size_t)(c0 + r)*NN + j0 + tx] = __float2half(t[tx][r]);
}

// ---------------- x0 build ----------------
__global__ void build_x0_kernel(const float* __restrict__ inputs, const float* __restrict__ hx) {
    size_t total = (size_t)NN * XW;
    for (size_t idx = (size_t)blockIdx.x*256 + threadIdx.x; idx < total; idx += (size_t)gridDim.x*256) {
        int n = (int)(idx / XW);
        int c = (int)(idx - (size_t)n*XW);
        int i = c >> 6, b = c & 63;
        float v;
        if (i < 2) {
            v = inputs[(size_t)b*(NN*2) + n*2 + i];
        } else {
            int q = i - 2;
            int kk = (q < 64) ? 3 : 2;
            int d = q & 63;
            v = hx[(size_t)((b << 2) + kk)*NDD + (size_t)n*64 + d];
        }
        g_X0[idx] = v;
    }
}

// ---------------- gw prep: 7 transposed (possibly combined) slices, fp16, padded K ----------------
// groups: 0:(0-2) 1:(1-4) 2:(2) 3:(3-6) 4:(4) 5:(5) 6:(6)
__global__ void gw_prep_kernel(const float* __restrict__ gw) {
    int idx = blockIdx.x * 256 + threadIdx.x;      // over 7*64*KP = 64512
    if (idx >= 7*64*KP) return;
    int i = idx % KP;
    int rd = idx / KP;
    int d = rd & 63;
    int g = rd >> 6;
    const int sA[7] = {0, 1, 2, 3, 4, 5, 6};
    const int sB[7] = {2, 4, -1, 6, -1, -1, -1};
    float v = 0.f;
    if (i < ISZ) {
        v = gw[((size_t)i*7 + sA[g])*64 + d];
        if (sB[g] >= 0) v -= gw[((size_t)i*7 + sB[g])*64 + d];
    }
    g_GWT[idx] = __float2half(v);
}

// ---------------- Xp build: X[n, i*64+b] fp32 -> Xp[(n*64+b), i] fp16 (pad K to 144) ----------------
__global__ void __launch_bounds__(256) xp_kernel(int selX) {
    __shared__ float sx[ISZ*66];
    const float* X = bufAny(selX);
    int n = blockIdx.x;
    int tid = threadIdx.x;
    for (int t = tid; t < XW; t += 256)
        sx[(t >> 6)*66 + (t & 63)] = X[(size_t)n*XW + t];
    __syncthreads();
    for (int t = tid; t < 64*36; t += 256) {
        int b = t / 36, c4 = t % 36;
        int i0 = c4 * 4;
        __half h[4];
        #pragma unroll
        for (int j = 0; j < 4; j++) {
            int i = i0 + j;
            h[j] = (i < ISZ) ? __float2half(sx[i*66 + b]) : __half(__ushort_as_half(0));
        }
        *(uint2*)&g_Xp[(size_t)(n*64 + b)*KP + i0] = *(uint2*)h;
    }
}

// ---------------- tensor-core projection GEMM ----------------
// C[(n*64+b), d] = Xp @ GWT[group]^T ; M=131072, K=144, N=64 per group.
// outSel per group: -2 = gc init (+gb), -1 = gc accumulate, >=10 = P slot.
#define TPROW 152
#define TP_A_BYTES (128*TPROW*2)   // 38912
#define TP_B_BYTES (64*TPROW*2)    // 19456
#define TPROJ_SMEM (TP_A_BYTES + TP_B_BYTES)

__global__ void __launch_bounds__(256, 2)
tcproj_kernel(int grpBase, int4 outSel, const float* __restrict__ gb) {
    extern __shared__ char smem[];
    uint32_t sb = smem_u32(smem);
    int tid = threadIdx.x;
    int wid = tid >> 5;
    int lane = tid & 31;
    int mb = blockIdx.x;
    int grp = blockIdx.y;
    int sels[4] = {outSel.x, outSel.y, outSel.z, outSel.w};
    int sel = sels[grp];

    // load A tile: Xp rows [mb*128, +128), 144 halves -> smem pitch 152
    {
        const __half* Asrc = g_Xp + (size_t)mb*128*KP;
        for (int t = tid; t < 128*18; t += 256) {
            int r = t / 18, ch = t % 18;
            cp16(sb + (uint32_t)(r*TPROW*2 + ch*16), Asrc + (size_t)r*KP + ch*8);
        }
        const __half* Bsrc = g_GWT + (size_t)(grpBase + grp)*64*KP;
        for (int t = tid; t < 64*18; t += 256) {
            int r = t / 18, ch = t % 18;
            cp16(sb + (uint32_t)(TP_A_BYTES + r*TPROW*2 + ch*16), Bsrc + (size_t)r*KP + ch*8);
        }
    }
    cp_commit();
    cp_wait0();
    __syncthreads();

    int mw = wid & 3;      // 4 m-chunks of 32 rows
    int nw = wid >> 2;     // 2 n-chunks of 32 cols
    int a_row = lane & 15;
    int a_colb = (lane >> 4) * 16;
    int b_row = ((lane >> 4) & 1) * 8 + (lane & 7);
    int b_colb = ((lane >> 3) & 1) * 16;

    uint32_t aOff = (uint32_t)((mw*32 + a_row) * TPROW * 2) + (uint32_t)a_colb;
    uint32_t bOff = (uint32_t)TP_A_BYTES + (uint32_t)((nw*32 + b_row) * TPROW * 2) + (uint32_t)b_colb;

    float acc[2][4][4];
    #pragma unroll
    for (int mf = 0; mf < 2; mf++)
        #pragma unroll
        for (int nf = 0; nf < 4; nf++)
            #pragma unroll
            for (int e = 0; e < 4; e++) acc[mf][nf][e] = 0.f;

    #pragma unroll
    for (int ks = 0; ks < 9; ks++) {
        uint32_t kb = (uint32_t)(ks*32);
        uint32_t ar[2][4], br[2][4];
        #pragma unroll
        for (int mf = 0; mf < 2; mf++)
            ldm_x4(ar[mf], sb + aOff + (uint32_t)(mf*16*TPROW*2) + kb);
        #pragma unroll
        for (int bg = 0; bg < 2; bg++)
            ldm_x4(br[bg], sb + bOff + (uint32_t)(bg*16*TPROW*2) + kb);
        #pragma unroll
        for (int mf = 0; mf < 2; mf++) {
            #pragma unroll
            for (int bg = 0; bg < 2; bg++) {
                mma16816h(acc[mf][bg*2+0], ar[mf], br[bg][0], br[bg][1]);
                mma16816h(acc[mf][bg*2+1], ar[mf], br[bg][2], br[bg][3]);
            }
        }
    }

    int gid = lane >> 2, tg = lane & 3;
    float* Pout = (sel >= 10) ? (g_P + (size_t)(sel - 10)*PSZ) : g_gc;
    #pragma unroll
    for (int mf = 0; mf < 2; mf++) {
        int r0g = mb*128 + mw*32 + mf*16 + gid;
        #pragma unroll
        for (int nf = 0; nf < 4; nf++) {
            int col = nw*32 + nf*8 + tg*2;
            size_t i0 = (size_t)r0g*64 + col;
            size_t i1 = i0 + (size_t)8*64;
            float2 v0 = make_float2(acc[mf][nf][0], acc[mf][nf][1]);
            float2 v1 = make_float2(acc[mf][nf][2], acc[mf][nf][3]);
            if (sel == -2) {
                float2 gbv = *(const float2*)&gb[col];
                v0.x += gbv.x; v0.y += gbv.y;
                v1.x += gbv.x; v1.y += gbv.y;
            } else if (sel == -1) {
                float2 o0 = *(const float2*)&g_gc[i0];
                float2 o1 = *(const float2*)&g_gc[i1];
                v0.x += o0.x; v0.y += o0.y;
                v1.x += o1.x; v1.y += o1.y;
            }
            *(float2*)&Pout[i0] = v0;
            *(float2*)&Pout[i1] = v1;
        }
    }
}

// ---------------- single-product fp16 GEMM ----------------
// mode: 0 = fp32 C only; 1 = fp32 C + transposed fp16 -> g_YTb; 2 = fp16 row-major -> g_A2f only
#define KC 32
#define TROW 80
#define TILEB (128*TROW)
#define STAGEB1 (2*TILEB)       // 20480
#define GEMM1_SMEM (4*STAGEB1)  // 81920
#define NSTG 64

__global__ void __launch_bounds__(256, 2)
gemm1_kernel(int selA, int selB, int selC, int W, int mode, int batch) {
    extern __shared__ char smem[];
    uint32_t sb = smem_u32(smem);
    int tid = threadIdx.x;
    int wid = tid >> 5;
    int lane = tid & 31;

    if (batch) {
        int bz = blockIdx.z;
        selA = bz;                      // 0=S1 1=S2 2=Ad 3=A2
        selB = 2 + bz;
        selC = (bz == 0) ? 19 : (bz == 1) ? 20 : (bz == 2) ? 21 : 23;
    }
    const __half* Af = selA == 0 ? g_S1f : (selA == 1 ? g_S2f : (selA == 2 ? g_Adf : g_A2f));
    const __half* Bf = selB == 0 ? g_YTh : (selB == 1 ? g_YTb : g_YTq + (size_t)(selB - 2)*QSZ);
    float* C = bufAny(selC);

    int mBase = blockIdx.x * 128;
    int nBase = blockIdx.y * 128;

    const __half* src[4];
    uint32_t dst[4];
    #pragma unroll
    for (int i = 0; i < 4; i++) {
        int c = tid + i*256;
        int tile = c >> 9;
        int q = c & 511;
        int row = q >> 2, col = q & 3;
        dst[i] = (uint32_t)(tile*TILEB + row*TROW + col*16);
        const __half* base = (tile == 0) ? Af + (size_t)(mBase + row) * NN
                                         : Bf + (size_t)(nBase + row) * NN;
        src[i] = base + col*8;
    }

    #pragma unroll
    for (int s = 0; s < 3; s++) {
        uint32_t so = sb + (uint32_t)(s * STAGEB1);
        #pragma unroll
        for (int i = 0; i < 4; i++) cp16(so + dst[i], src[i] + s*KC);
        cp_commit();
    }

    float acc[4][4][4];
    #pragma unroll
    for (int mf = 0; mf < 4; mf++)
        #pragma unroll
        for (int nf = 0; nf < 4; nf++)
            #pragma unroll
            for (int e = 0; e < 4; e++) acc[mf][nf][e] = 0.f;

    int mw = wid & 1;
    int nw = wid >> 1;
    int a_row = lane & 15;
    int a_colb = (lane >> 4) * 16;
    int b_row = ((lane >> 4) & 1) * 8 + (lane & 7);
    int b_colb = ((lane >> 3) & 1) * 16;

    uint32_t aOff = (uint32_t)((mw*64 + a_row) * TROW) + (uint32_t)a_colb;
    uint32_t bOff = (uint32_t)TILEB + (uint32_t)((nw*32 + b_row) * TROW) + (uint32_t)b_colb;

    for (int s = 0; s < NSTG; s++) {
        cp_wait2();
        __syncthreads();
        int sn = s + 3;
        if (sn < NSTG) {
            uint32_t so2 = sb + (uint32_t)((sn & 3) * STAGEB1);
            #pragma unroll
            for (int i = 0; i < 4; i++) cp16(so2 + dst[i], src[i] + sn*KC);
        }
        cp_commit();

        uint32_t so = sb + (uint32_t)((s & 3) * STAGEB1);
        #pragma unroll
        for (int ks = 0; ks < 2; ks++) {
            uint32_t kb = (uint32_t)(ks*32);
            uint32_t ar[4][4], br[2][4];
            #pragma unroll
            for (int mf = 0; mf < 4; mf++)
                ldm_x4(ar[mf], so + aOff + (uint32_t)(mf*16*TROW) + kb);
            #pragma unroll
            for (int bg = 0; bg < 2; bg++)
                ldm_x4(br[bg], so + bOff + (uint32_t)(bg*16*TROW) + kb);
            #pragma unroll
            for (int mf = 0; mf < 4; mf++) {
                #pragma unroll
                for (int bg = 0; bg < 2; bg++) {
                    mma16816h(acc[mf][bg*2+0], ar[mf], br[bg][0], br[bg][1]);
                    mma16816h(acc[mf][bg*2+1], ar[mf], br[bg][2], br[bg][3]);
                }
            }
        }
    }

    int gid = lane >> 2, tg = lane & 3;

    if (mode != 2) {
        #pragma unroll
        for (int mf = 0; mf < 4; mf++) {
            int row0 = mBase + mw*64 + mf*16 + gid;
            #pragma unroll
            for (int nf = 0; nf < 4; nf++) {
                int col = nBase + nw*32 + nf*8 + tg*2;
                size_t i0 = (size_t)row0 * W + col;
                size_t i1 = i0 + (size_t)8 * W;
                *(float2*)&C[i0] = make_float2(acc[mf][nf][0], acc[mf][nf][1]);
                *(float2*)&C[i1] = make_float2(acc[mf][nf][2], acc[mf][nf][3]);
            }
        }
    } else {
        #pragma unroll
        for (int mf = 0; mf < 4; mf++) {
            int row0 = mBase + mw*64 + mf*16 + gid;
            #pragma unroll
            for (int nf = 0; nf < 4; nf++) {
                int col = nBase + nw*32 + nf*8 + tg*2;
                __half2 v0 = __floats2half2_rn(acc[mf][nf][0], acc[mf][nf][1]);
                __half2 v1 = __floats2half2_rn(acc[mf][nf][2], acc[mf][nf][3]);
                *(__half2*)&g_A2f[(size_t)row0 * NN + col] = v0;
                *(__half2*)&g_A2f[(size_t)(row0 + 8) * NN + col] = v1;
            }
        }
    }

    if (mode == 1) {
        cp_wait0();
        __syncthreads();
        __half* st = (__half*)smem;     // pitch 136 halves
        #pragma unroll
        for (int mf = 0; mf < 4; mf++) {
            #pragma unroll
            for (int nf = 0; nf < 4; nf++) {
                int r = mw*64 + mf*16 + gid;
                int c = nw*32 + nf*8 + tg*2;
                st[(c+0)*136 + r]     = __float2half(acc[mf][nf][0]);
                st[(c+1)*136 + r]     = __float2half(acc[mf][nf][1]);
                st[(c+0)*136 + r + 8] = __float2half(acc[mf][nf][2]);
                st[(c+1)*136 + r + 8] = __float2half(acc[mf][nf][3]);
            }
        }
        __syncthreads();
        for (int t = tid; t < 128*16; t += 256) {
            int c = t >> 4, seg = t & 15;
            uint4 v = *(const uint4*)&st[c*136 + seg*8];
            *(uint4*)&g_YTb[(size_t)(nBase + c)*NN + mBase + seg*8] = v;
        }
    }
}

// ---------------- attention ----------------
__global__ void logits_kernel(const float* __restrict__ hx, const float* __restrict__ R,
                              const float* __restrict__ aw, const float* __restrict__ ab) {
    int bk = blockIdx.x;
    int k = bk & 3;
    int tid = threadIdx.x;
    const float* hp = hx + (size_t)bk * NDD;
    const float* rp = R + (size_t)k * NDD;
    float s = 0.f;
    for (int t = tid; t < NDD; t += 256) s += (hp[t] + rp[t]) * aw[t];
    for (int o = 16; o; o >>= 1) s += __shfl_down_sync(0xffffffffu, s, o);
    __shared__ float red[8];
    if ((tid & 31) == 0) red[tid >> 5] = s;
    __syncthreads();
    if (tid == 0) {
        float t = 0.f;
        #pragma unroll
        for (int w = 0; w < 8; w++) t += red[w];
        g_logits[bk] = t + ab[0];
    }
}

__global__ void weight_kernel() {
    int b = threadIdx.x;
    if (b < BB) {
        float l0 = g_logits[b*4+0], l1 = g_logits[b*4+1], l2 = g_logits[b*4+2], l3 = g_logits[b*4+3];
        float m = fmaxf(fmaxf(l0, l1), fmaxf(l2, l3));
        float e0 = expf(l0 - m), e1 = expf(l1 - m), e2 = expf(l2 - m), e3 = expf(l3 - m);
        float inv = 1.f / (e0 + e1 + e2 + e3);
        g_wt[b*4+0] = e0 * inv; g_wt[b*4+1] = e1 * inv;
        g_wt[b*4+2] = e2 * inv; g_wt[b*4+3] = e3 * inv;
    }
}

// ---------------- output (fused combine; gc in [n][4096] layout) ----------------
__global__ void __launch_bounds__(256) final_kernel(const float* __restrict__ W,
                                                    const float* __restrict__ bbias,
                                                    const float* __restrict__ hx,
                                                    const float* __restrict__ R,
                                                    float* __restrict__ out, int write_hx) {
    __shared__ float sW[64*64];
    __shared__ float sg[4*64];
    int tid = threadIdx.x;
    int r0 = blockIdx.x * 4;
    for (int t = tid; t < 4096; t += 256) sW[t] = W[t];
    {
        int row = r0 + (tid >> 6);
        int d = tid & 63;
        int n = row & 2047;
        int b = row >> 11;
        size_t p = (size_t)n*4096 + (size_t)(b*64 + d);
        float v = g_gc[p]
                + 2.f*g_P[9*PSZ + p]      // Q2
                + 2.f*g_P[10*PSZ + p]     // Q4
                + g_P[11*PSZ + p]         // Q5
                + g_P[13*PSZ + p];        // Q6
        sg[tid] = v > 0.f ? v : 0.01f * v;
    }
    __syncthreads();
    int rl = tid >> 6;
    int d = tid & 63;
    int r = r0 + rl;
    int b = r >> 11;
    int n = r & 2047;
    float acc = 0.f;
    #pragma unroll
    for (int e = 0; e < 64; e++) acc += sg[rl*64 + e] * sW[e*64 + d];
    float att = 0.f;
    #pragma unroll
    for (int k = 0; k < 4; k++) {
        float xv = hx[(size_t)((b << 2) + k)*NDD + (size_t)n*64 + d] + R[(size_t)k*NDD + (size_t)n*64 + d];
        att += xv * g_wt[b*4 + k];
    }
    float o = acc + bbias[(size_t)n*64 + d] + att;
    out[(size_t)b*NDD + (size_t)n*64 + d] = o;
    if (write_hx)
        out[(size_t)OUT1 + (size_t)((b << 2) + 3)*NDD + (size_t)n*64 + d] = o;
}

__global__ void hxcopy_kernel(const float* __restrict__ hx, float* __restrict__ out) {
    size_t idx = (size_t)blockIdx.x * 256 + threadIdx.x;
    int b = (int)(idx / (3*(size_t)NDD));
    size_t rem = idx - (size_t)b * (3*(size_t)NDD);
    int kk = (int)(rem / NDD);
    size_t j = rem - (size_t)kk * NDD;
    out[(size_t)OUT1 + (size_t)(b*4 + kk)*NDD + j] = hx[(size_t)(b*4 + kk + 1)*NDD + j];
}

// ---------------- launch ----------------
extern "C" void kernel_launch(void* const* d_in, const int* in_sizes, int n_in,
                              void* d_out, int out_size) {
    const float* inputs = (const float*)d_in[0];
    const float* hx     = (const float*)d_in[1];
    const float* graph  = (const float*)d_in[2];
    const float* nv1    = (const float*)d_in[3];
    const float* nv2    = (const float*)d_in[4];
    const float* W      = (const float*)d_in[5];
    const float* bbias  = (const float*)d_in[6];
    const float* R      = (const float*)d_in[7];
    const float* gw     = (const float*)d_in[8];
    const float* gb     = (const float*)d_in[9];
    const float* aw     = (const float*)d_in[10];
    const float* ab     = (const float*)d_in[11];
    float* out = (float*)d_out;

    int write_hx = ((size_t)out_size >= FULL_OUT) ? 1 : 0;

    cudaFuncSetAttribute(gemm1_kernel, cudaFuncAttributeMaxDynamicSharedMemorySize, GEMM1_SMEM);
    cudaFuncSetAttribute(tcproj_kernel, cudaFuncAttributeMaxDynamicSharedMemorySize, TPROJ_SMEM);

    rowsum_dinv_kernel<<<NN, 256>>>(graph);
    colsum_part_kernel<<<dim3(NN/256, 8), 256>>>(graph);
    colsum_fin_kernel<<<NN/256, 256>>>();
    build_S1_kernel<<<dim3(64, 64), dim3(32, 8)>>>(graph);
    build_S2_kernel<<<(NN*NN)/256, 256>>>(graph);
    adp_kernel<<<NN, 256>>>(nv1, nv2);
    gw_prep_kernel<<<(7*64*KP + 255)/256, 256>>>(gw);

    dim3 gfull(NN/128, XW/128);
    dim3 ga2(NN/128, NN/128);
    dim3 gleaf(NN/128, 4096/128, 4);
    dim3 xfull(XW/32, NN/32);
    dim3 xsq(NN/32, NN/32);
    dim3 xqb(4096/32, NN/32, 4);
    dim3 xblk(32, 8);

    // A2 = A @ A (depends only on adp) -> g_A2f
    xt_f16_kernel<<<xsq, xblk>>>(3, NN);
    gemm1_kernel<<<ga2, 256, GEMM1_SMEM>>>(2, 0, 2, NN, 2, 0);

    build_x0_kernel<<<66560, 256>>>(inputs, hx);

    // proj(x0): gc init = gb + proj(x0, w0-w2)
    xp_kernel<<<NN, 256>>>(0);
    tcproj_kernel<<<dim3(1024, 1), 256, TPROJ_SMEM>>>(0, make_int4(-2, 0, 0, 0), gb);

    // m1 = S1 @ x0 -> X1 (+ YTb fp16 transposed epilogue)
    xt_f16_kernel<<<xfull, xblk>>>(0, XW);
    gemm1_kernel<<<gfull, 256, GEMM1_SMEM>>>(0, 0, 1, XW, 1, 0);

    // m3 = S2 @ m1 -> X2 (B = YTb)
    gemm1_kernel<<<gfull, 256, GEMM1_SMEM>>>(1, 1, 2, XW, 0, 0);

    // proj(m1): gc += proj(m1, w1-w4); P2m1 -> slot 13
    xp_kernel<<<NN, 256>>>(1);
    tcproj_kernel<<<dim3(1024, 2), 256, TPROJ_SMEM>>>(1, make_int4(-1, 13, 0, 0), gb);

    // proj(m3): gc += proj(m3, w3-w6); P4m3->16, P5m3->17, P6m3->18
    xp_kernel<<<NN, 256>>>(2);
    tcproj_kernel<<<dim3(1024, 4), 256, TPROJ_SMEM>>>(3, make_int4(-1, 16, 17, 18), gb);

    // batched transposes of the 4 leaf slices
    xt_f16_batch_kernel<<<xqb, xblk>>>();
    // batched leaf GEMMs: Q2, Q4, Q5, Q6
    gemm1_kernel<<<gleaf, 256, GEMM1_SMEM>>>(0, 0, 0, 4096, 0, 1);

    logits_kernel<<<BB*4, 256>>>(hx, R, aw, ab);
    weight_kernel<<<1, 64>>>();

    final_kernel<<<(BB*NN)/4, 256>>>(W, bbias, hx, R, out, write_hx);
    if (write_hx)
        hxcopy_kernel<<<(unsigned)((size_t)BB*3*NDD/256), 256>>>(hx, out);
}